// round 5
// baseline (speedup 1.0000x reference)
#include <cuda_runtime.h>
#include <math.h>
#include <cstdint>

#define Bsz   2
#define Sq    2048
#define Dm    1024
#define Hh    16
#define Mtot  4096
#define DIMq  256
#define EPSf  1e-5f

// ---------------- scratch (device globals; no allocs allowed) ----------------
__device__ float g_q[Mtot * Dm];
__device__ float g_k[Mtot * Dm];
__device__ float g_v[Mtot * Dm];
__device__ float g_o[Mtot * Dm];
__device__ float g_proj[Mtot * Dm];

// ======================= helpers =======================
__device__ __forceinline__ uint32_t smem_to_u32(const void* p) {
    uint32_t a;
    asm("{ .reg .u64 t; cvta.to.shared.u64 t, %1; cvt.u32.u64 %0, t; }" : "=r"(a) : "l"(p));
    return a;
}
__device__ __forceinline__ void cp16(uint32_t sm, const void* g) {
    asm volatile("cp.async.cg.shared.global [%0], [%1], 16;" :: "r"(sm), "l"(g));
}
__device__ __forceinline__ void cp_commit() {
    asm volatile("cp.async.commit_group;");
}
template <int N>
__device__ __forceinline__ void cp_wait() {
    asm volatile("cp.async.wait_group %0;" :: "n"(N));
}
__device__ __forceinline__ uint32_t f2tf32(float x) {
    uint32_t r;
    asm("cvt.rna.tf32.f32 %0, %1;" : "=r"(r) : "f"(x));
    return r;
}
__device__ __forceinline__ float f2tf32f(float x) {
    return __uint_as_float(f2tf32(x));
}
__device__ __forceinline__ void mma_tf32(float c[4], const uint32_t a[4], const uint32_t b[2]) {
    asm volatile(
        "mma.sync.aligned.m16n8k8.row.col.f32.tf32.tf32.f32 "
        "{%0,%1,%2,%3}, {%4,%5,%6,%7}, {%8,%9}, {%0,%1,%2,%3};"
        : "+f"(c[0]), "+f"(c[1]), "+f"(c[2]), "+f"(c[3])
        : "r"(a[0]), "r"(a[1]), "r"(a[2]), "r"(a[3]), "r"(b[0]), "r"(b[1]));
}

// ============ tf32 mma.sync GEMM core: C[M,1024] = A[M,1024] * W[1024,1024]^T =
#define BM 128
#define BN 256
#define BK 32
#define LDP 36
#define A_STAGE_B (BM * LDP * 4)
#define B_STAGE_B (BN * LDP * 4)
#define GSMEM (3 * (A_STAGE_B + B_STAGE_B))
#define NKT (Dm / BK)

__device__ __forceinline__ void gemm_body(const float* __restrict__ A,
                                          const float* __restrict__ W,
                                          float* __restrict__ C,
                                          char* gsm)
{
    const uint32_t usm = smem_to_u32(gsm);
    const uint32_t usmA = usm;
    const uint32_t usmB = usm + 3 * A_STAGE_B;

    const int tid  = threadIdx.x;
    const int wid  = tid >> 5;
    const int lane = tid & 31;
    const int grp  = lane >> 2;
    const int tig  = lane & 3;
    const int wm   = wid >> 2;
    const int wn   = wid & 3;

    const int aRow0 = blockIdx.y * BM;
    const int bRow0 = blockIdx.x * BN;

    int aSm[4], bSm[8];
    int aGm[4], bGm[8];
#pragma unroll
    for (int i = 0; i < 4; i++) {
        int e = tid + (i << 8);
        int r = e >> 3, c4 = (e & 7) << 2;
        aSm[i] = (r * LDP + c4) * 4;
        aGm[i] = r * Dm + c4;
    }
#pragma unroll
    for (int i = 0; i < 8; i++) {
        int e = tid + (i << 8);
        int r = e >> 3, c4 = (e & 7) << 2;
        bSm[i] = (r * LDP + c4) * 4;
        bGm[i] = r * Dm + c4;
    }
    const float* gA = A + (size_t)aRow0 * Dm;
    const float* gB = W + (size_t)bRow0 * Dm;

    float acc[4][8][4];
#pragma unroll
    for (int im = 0; im < 4; im++)
#pragma unroll
        for (int jn = 0; jn < 8; jn++)
#pragma unroll
            for (int t = 0; t < 4; t++) acc[im][jn][t] = 0.f;

#pragma unroll
    for (int p = 0; p < 2; p++) {
        uint32_t sa = usmA + p * A_STAGE_B;
        uint32_t sb = usmB + p * B_STAGE_B;
        const float* ka = gA + p * BK;
        const float* kb = gB + p * BK;
#pragma unroll
        for (int i = 0; i < 4; i++) cp16(sa + aSm[i], ka + aGm[i]);
#pragma unroll
        for (int i = 0; i < 8; i++) cp16(sb + bSm[i], kb + bGm[i]);
        cp_commit();
    }

    for (int kt = 0; kt < NKT; kt++) {
        cp_wait<1>();
        __syncthreads();

        if (kt + 2 < NKT) {
            int s = (kt + 2) % 3;
            uint32_t sa = usmA + s * A_STAGE_B;
            uint32_t sb = usmB + s * B_STAGE_B;
            const float* ka = gA + (kt + 2) * BK;
            const float* kb = gB + (kt + 2) * BK;
#pragma unroll
            for (int i = 0; i < 4; i++) cp16(sa + aSm[i], ka + aGm[i]);
#pragma unroll
            for (int i = 0; i < 8; i++) cp16(sb + bSm[i], kb + bGm[i]);
        }
        cp_commit();

        const float* As = (const float*)(gsm + (kt % 3) * A_STAGE_B);
        const float* Bs = (const float*)(gsm + 3 * A_STAGE_B + (kt % 3) * B_STAGE_B);

#pragma unroll
        for (int k8 = 0; k8 < 4; k8++) {
            const int kb = k8 * 8 + tig;
            uint32_t afr[4][4], bfr[8][2];
#pragma unroll
            for (int im = 0; im < 4; im++) {
                int row = wm * 64 + im * 16 + grp;
                afr[im][0] = f2tf32(As[row * LDP + kb]);
                afr[im][1] = f2tf32(As[(row + 8) * LDP + kb]);
                afr[im][2] = f2tf32(As[row * LDP + kb + 4]);
                afr[im][3] = f2tf32(As[(row + 8) * LDP + kb + 4]);
            }
#pragma unroll
            for (int jn = 0; jn < 8; jn++) {
                int brow = wn * 64 + jn * 8 + grp;
                bfr[jn][0] = f2tf32(Bs[brow * LDP + kb]);
                bfr[jn][1] = f2tf32(Bs[brow * LDP + kb + 4]);
            }
#pragma unroll
            for (int im = 0; im < 4; im++)
#pragma unroll
                for (int jn = 0; jn < 8; jn++)
                    mma_tf32(acc[im][jn], afr[im], bfr[jn]);
        }
        __syncthreads();
    }

    const int rowBase = aRow0 + wm * 64;
    const int colBase = bRow0 + wn * 64;
#pragma unroll
    for (int im = 0; im < 4; im++) {
        int r0 = rowBase + im * 16 + grp;
#pragma unroll
        for (int jn = 0; jn < 8; jn++) {
            int col = colBase + jn * 8 + 2 * tig;
            float2 v01 = make_float2(acc[im][jn][0], acc[im][jn][1]);
            float2 v23 = make_float2(acc[im][jn][2], acc[im][jn][3]);
            *reinterpret_cast<float2*>(C + (size_t)r0 * Dm + col) = v01;
            *reinterpret_cast<float2*>(C + (size_t)(r0 + 8) * Dm + col) = v23;
        }
    }
}

__global__ __launch_bounds__(256, 1) void gemm_mma(const float* __restrict__ A,
                                                   const float* __restrict__ W,
                                                   float* __restrict__ C)
{
    extern __shared__ __align__(16) char gsm[];
    gemm_body(A, W, C, gsm);
}

// fused QKV: blockIdx.z selects weight/output
__global__ __launch_bounds__(256, 1) void gemm_qkv(const float* __restrict__ A,
                                                   const float* __restrict__ W0,
                                                   const float* __restrict__ W1,
                                                   const float* __restrict__ W2,
                                                   float* __restrict__ C0,
                                                   float* __restrict__ C1,
                                                   float* __restrict__ C2)
{
    extern __shared__ __align__(16) char gsm[];
    const int z = blockIdx.z;
    const float* W = (z == 0) ? W0 : (z == 1) ? W1 : W2;
    float*       C = (z == 0) ? C0 : (z == 1) ? C1 : C2;
    gemm_body(A, W, C, gsm);
}

// ============ Flash attention, tf32 mma.sync, pre-rounded permuted smem ======
// CTA: 128 Q rows, 8 warps. KV tiles of 64.
// smem (floats):
//   Ps  : 128 x 68  (Q staging, then P)          @ 0
//   rawK: 2 x 64 x 68 (cp.async staging)          @ 8704
//   rawV: 2 x 64 x 68                             @ 17408
//   Kp  : 64 x 72  (rounded, column-pair-permuted)@ 26112
//   Vt  : 64 x 72  (rounded, transposed+permuted) @ 30720
#define FA_PP 68
#define FA_PR 68
#define FA_PC 72
#define PS_OFF 0
#define RK_OFF (128 * FA_PP)
#define RK_STRIDE (64 * FA_PR)
#define RV_OFF (RK_OFF + 2 * RK_STRIDE)
#define KP_OFF (RV_OFF + 2 * RK_STRIDE)
#define VT_OFF (KP_OFF + 64 * FA_PC)
#define FA_SMEM ((VT_OFF + 64 * FA_PC) * 4)      // 141312 B
#define NKV (Sq / 64)
#define LOG2E 1.44269504088896f

// Round raw K/V tile (buffer rbuf) into permuted Kp / transposed Vt.
__device__ __forceinline__ void round_convert(float* fsm, int tid, int rbuf) {
    const float* rk = fsm + RK_OFF + rbuf * RK_STRIDE;
    const float* rv = fsm + RV_OFF + rbuf * RK_STRIDE;
    float* kp = fsm + KP_OFF;
    float* vt = fsm + VT_OFF;
#pragma unroll
    for (int i = 0; i < 4; i++) {
        int e = tid + (i << 8);
        int r = e >> 4, c4 = (e & 15) << 2;
        float4 kv = *reinterpret_cast<const float4*>(rk + r * FA_PR + c4);
        float4 vv = *reinterpret_cast<const float4*>(rv + r * FA_PR + c4);
        // K: cols c4..c4+3 -> permuted slots: pair (c, c+4) adjacent
        int kb = (c4 >> 3) * 8 + ((c4 & 4) ? 1 : 0);
        float* kd = kp + r * FA_PC + kb;
        kd[0] = f2tf32f(kv.x); kd[2] = f2tf32f(kv.y);
        kd[4] = f2tf32f(kv.z); kd[6] = f2tf32f(kv.w);
        // V: transpose; row r -> permuted slot (pair (r, r+4) adjacent)
        int tr = r & 7;
        int pr = (r & ~7) + ((tr < 4) ? 2 * tr : 2 * (tr - 4) + 1);
        vt[(c4 + 0) * FA_PC + pr] = f2tf32f(vv.x);
        vt[(c4 + 1) * FA_PC + pr] = f2tf32f(vv.y);
        vt[(c4 + 2) * FA_PC + pr] = f2tf32f(vv.z);
        vt[(c4 + 3) * FA_PC + pr] = f2tf32f(vv.w);
    }
}

__global__ __launch_bounds__(256, 1) void flash_mma(const float* __restrict__ q,
                                                    const float* __restrict__ k,
                                                    const float* __restrict__ v,
                                                    float* __restrict__ o)
{
    extern __shared__ __align__(16) float fsm[];
    const uint32_t usm = smem_to_u32(fsm);

    const int tid  = threadIdx.x;
    const int wid  = tid >> 5;
    const int lane = tid & 31;
    const int grp  = lane >> 2;
    const int tig  = lane & 3;

    const int b  = blockIdx.z;
    const int h  = blockIdx.y;
    const int q0 = blockIdx.x << 7;

    const float* qg = q + (((size_t)(b * Sq + q0) * Hh + h) << 6);
    const float* kg = k + (((size_t)(b * Sq) * Hh + h) << 6);
    const float* vg = v + (((size_t)(b * Sq) * Hh + h) << 6);

    // ---- prologue ----
    {
#pragma unroll
        for (int i = 0; i < 8; i++) {
            int e = tid + (i << 8);
            int r = e >> 4, c4 = (e & 15) << 2;
            cp16(usm + (PS_OFF + r * FA_PP + c4) * 4, qg + (size_t)r * 1024 + c4);
        }
#pragma unroll
        for (int i = 0; i < 4; i++) {
            int e = tid + (i << 8);
            int r = e >> 4, c4 = (e & 15) << 2;
            cp16(usm + (RK_OFF + r * FA_PR + c4) * 4, kg + (size_t)r * 1024 + c4);
            cp16(usm + (RV_OFF + r * FA_PR + c4) * 4, vg + (size_t)r * 1024 + c4);
        }
        cp_commit();   // g0: Q + K0 + V0
#pragma unroll
        for (int i = 0; i < 4; i++) {
            int e = tid + (i << 8);
            int r = e >> 4, c4 = (e & 15) << 2;
            cp16(usm + (RK_OFF + RK_STRIDE + r * FA_PR + c4) * 4, kg + (size_t)(64 + r) * 1024 + c4);
            cp16(usm + (RV_OFF + RK_STRIDE + r * FA_PR + c4) * 4, vg + (size_t)(64 + r) * 1024 + c4);
        }
        cp_commit();   // g1: K1 + V1
    }
    cp_wait<1>();
    __syncthreads();

    // ---- Q fragments: scale 0.125*log2e folded in; rounded once ----
    const int lr0 = wid * 16 + grp;
    const float qs = 0.125f * LOG2E;
    uint32_t qf[8][4];
#pragma unroll
    for (int k8 = 0; k8 < 8; k8++) {
        int kc = k8 * 8 + tig;
        qf[k8][0] = f2tf32(fsm[PS_OFF + lr0 * FA_PP + kc] * qs);
        qf[k8][1] = f2tf32(fsm[PS_OFF + (lr0 + 8) * FA_PP + kc] * qs);
        qf[k8][2] = f2tf32(fsm[PS_OFF + lr0 * FA_PP + kc + 4] * qs);
        qf[k8][3] = f2tf32(fsm[PS_OFF + (lr0 + 8) * FA_PP + kc + 4] * qs);
    }
    round_convert(fsm, tid, 0);
    __syncthreads();   // Q reads done; Kp/Vt ready

    float m0 = -1e30f, m1 = -1e30f, l0 = 0.f, l1 = 0.f;
    float oac[8][4];
#pragma unroll
    for (int jd = 0; jd < 8; jd++)
#pragma unroll
        for (int t = 0; t < 4; t++) oac[jd][t] = 0.f;

    const float* kp = fsm + KP_OFF;
    const float* vt = fsm + VT_OFF;

    for (int it = 0; it < NKV; it++) {
        // prefetch it+2 into raw(it&1) (already consumed by round_convert)
        if (it + 2 < NKV) {
            int kv0 = (it + 2) << 6;
            uint32_t rb = (it & 1) * RK_STRIDE;
#pragma unroll
            for (int i = 0; i < 4; i++) {
                int e = tid + (i << 8);
                int r = e >> 4, c4 = (e & 15) << 2;
                cp16(usm + (RK_OFF + rb + r * FA_PR + c4) * 4, kg + (size_t)(kv0 + r) * 1024 + c4);
                cp16(usm + (RV_OFF + rb + r * FA_PR + c4) * 4, vg + (size_t)(kv0 + r) * 1024 + c4);
            }
        }
        cp_commit();

        // ---- S = Q K^T  (log2 domain) ----
        float sac[8][4];
#pragma unroll
        for (int jn = 0; jn < 8; jn++)
#pragma unroll
            for (int t = 0; t < 4; t++) sac[jn][t] = 0.f;
#pragma unroll
        for (int k8 = 0; k8 < 8; k8++) {
            const int co = k8 * 8 + 2 * tig;
            uint32_t bfr[8][2];
#pragma unroll
            for (int jn = 0; jn < 8; jn++) {
                float2 kk = *reinterpret_cast<const float2*>(kp + (jn * 8 + grp) * FA_PC + co);
                bfr[jn][0] = __float_as_uint(kk.x);
                bfr[jn][1] = __float_as_uint(kk.y);
            }
#pragma unroll
            for (int jn = 0; jn < 8; jn++)
                mma_tf32(sac[jn], qf[k8], bfr[jn]);
        }

        // ---- online softmax (base-2) ----
        float mx0 = -1e30f, mx1 = -1e30f;
#pragma unroll
        for (int jn = 0; jn < 8; jn++) {
            mx0 = fmaxf(mx0, fmaxf(sac[jn][0], sac[jn][1]));
            mx1 = fmaxf(mx1, fmaxf(sac[jn][2], sac[jn][3]));
        }
        mx0 = fmaxf(mx0, __shfl_xor_sync(0xffffffffu, mx0, 1));
        mx0 = fmaxf(mx0, __shfl_xor_sync(0xffffffffu, mx0, 2));
        mx1 = fmaxf(mx1, __shfl_xor_sync(0xffffffffu, mx1, 1));
        mx1 = fmaxf(mx1, __shfl_xor_sync(0xffffffffu, mx1, 2));
        float mn0 = fmaxf(m0, mx0), mn1 = fmaxf(m1, mx1);
        float al0 = exp2f(m0 - mn0), al1 = exp2f(m1 - mn1);

        float sum0 = 0.f, sum1 = 0.f;
#pragma unroll
        for (int jn = 0; jn < 8; jn++) {
            float p00 = f2tf32f(exp2f(sac[jn][0] - mn0));
            float p01 = f2tf32f(exp2f(sac[jn][1] - mn0));
            float p10 = f2tf32f(exp2f(sac[jn][2] - mn1));
            float p11 = f2tf32f(exp2f(sac[jn][3] - mn1));
            int c = jn * 8 + 2 * tig;
            *reinterpret_cast<float2*>(&fsm[PS_OFF + lr0 * FA_PP + c])       = make_float2(p00, p01);
            *reinterpret_cast<float2*>(&fsm[PS_OFF + (lr0 + 8) * FA_PP + c]) = make_float2(p10, p11);
            sum0 += p00 + p01;
            sum1 += p10 + p11;
        }
        sum0 += __shfl_xor_sync(0xffffffffu, sum0, 1);
        sum0 += __shfl_xor_sync(0xffffffffu, sum0, 2);
        sum1 += __shfl_xor_sync(0xffffffffu, sum1, 1);
        sum1 += __shfl_xor_sync(0xffffffffu, sum1, 2);
        l0 = l0 * al0 + sum0;  m0 = mn0;
        l1 = l1 * al1 + sum1;  m1 = mn1;
#pragma unroll
        for (int jd = 0; jd < 8; jd++) {
            oac[jd][0] *= al0; oac[jd][1] *= al0;
            oac[jd][2] *= al1; oac[jd][3] *= al1;
        }
        __syncwarp();

        // ---- O += P V ----
#pragma unroll
        for (int k8 = 0; k8 < 8; k8++) {
            const int kc = k8 * 8 + tig;
            const int co = k8 * 8 + 2 * tig;
            uint32_t afr[4];
            afr[0] = __float_as_uint(fsm[PS_OFF + lr0 * FA_PP + kc]);
            afr[1] = __float_as_uint(fsm[PS_OFF + (lr0 + 8) * FA_PP + kc]);
            afr[2] = __float_as_uint(fsm[PS_OFF + lr0 * FA_PP + kc + 4]);
            afr[3] = __float_as_uint(fsm[PS_OFF + (lr0 + 8) * FA_PP + kc + 4]);
            uint32_t bfr[8][2];
#pragma unroll
            for (int jd = 0; jd < 8; jd++) {
                float2 vv2 = *reinterpret_cast<const float2*>(vt + (jd * 8 + grp) * FA_PC + co);
                bfr[jd][0] = __float_as_uint(vv2.x);
                bfr[jd][1] = __float_as_uint(vv2.y);
            }
#pragma unroll
            for (int jd = 0; jd < 8; jd++)
                mma_tf32(oac[jd], afr, bfr[jd]);
        }

        // ---- tail: round next raw tile into Kp/Vt ----
        if (it + 1 < NKV) {
            cp_wait<1>();
            __syncthreads();
            round_convert(fsm, tid, (it + 1) & 1);
            __syncthreads();
        }
    }

    // ---- epilogue ----
    const float inv0 = 1.f / l0, inv1 = 1.f / l1;
    float* og  = o + (((size_t)(b * Sq + q0 + lr0) * Hh + h) << 6);
    float* og8 = og + (size_t)8 * 1024;
#pragma unroll
    for (int jd = 0; jd < 8; jd++) {
        int c = jd * 8 + 2 * tig;
        *reinterpret_cast<float2*>(og + c)  = make_float2(oac[jd][0] * inv0, oac[jd][1] * inv0);
        *reinterpret_cast<float2*>(og8 + c) = make_float2(oac[jd][2] * inv1, oac[jd][3] * inv1);
    }
}

// ========= fused: x1 = LN(x + proj); quantum FFN; out = LN(x1 + ffn) =========
__global__ __launch_bounds__(256) void ln_quantum(const float* __restrict__ x,
                                                  const float* __restrict__ proj,
                                                  const float* __restrict__ g1,
                                                  const float* __restrict__ b1,
                                                  const float* __restrict__ Win,
                                                  const float* __restrict__ b_in,
                                                  const float* __restrict__ Wout,
                                                  const float* __restrict__ b_out,
                                                  const float* __restrict__ ry,
                                                  const float* __restrict__ g2,
                                                  const float* __restrict__ b2,
                                                  float* __restrict__ out)
{
    const int row = blockIdx.x;
    const int tid = threadIdx.x;
    const int lane = tid & 31, wid = tid >> 5;
    const float* px = x + (size_t)row * Dm;
    const float* pp = proj + (size_t)row * Dm;

    __shared__ float redw[64];
    __shared__ float angs[8];
    __shared__ float ezs[8];
    __shared__ float2 st[2][DIMq];

    // ---- first residual + LN -> xv (x1 values in regs) ----
    float xv[4];
    {
        float yv[4], sum = 0.f, sq = 0.f;
#pragma unroll
        for (int j = 0; j < 4; j++) {
            int d = tid + (j << 8);
            float t = px[d] + pp[d];
            yv[j] = t; sum += t; sq = fmaf(t, t, sq);
        }
#pragma unroll
        for (int off = 16; off; off >>= 1) {
            sum += __shfl_xor_sync(0xffffffffu, sum, off);
            sq  += __shfl_xor_sync(0xffffffffu, sq, off);
        }
        if (lane == 0) { redw[wid] = sum; redw[8 + wid] = sq; }
        __syncthreads();
        float tsum = 0.f, tsq = 0.f;
#pragma unroll
        for (int w = 0; w < 8; w++) { tsum += redw[w]; tsq += redw[8 + w]; }
        float mean = tsum * (1.f / 1024.f);
        float var  = tsq * (1.f / 1024.f) - mean * mean;
        float rstd = rsqrtf(var + EPSf);
#pragma unroll
        for (int j = 0; j < 4; j++) {
            int d = tid + (j << 8);
            xv[j] = (yv[j] - mean) * rstd * g1[d] + b1[d];
        }
        __syncthreads();   // redw reuse guard
    }

    // ---- angles ----
    float accq[8] = {0, 0, 0, 0, 0, 0, 0, 0};
#pragma unroll
    for (int j = 0; j < 4; j++) {
        int d = tid + (j << 8);
#pragma unroll
        for (int qq = 0; qq < 8; qq++)
            accq[qq] = fmaf(xv[j], Win[qq * Dm + d], accq[qq]);
    }
#pragma unroll
    for (int qq = 0; qq < 8; qq++) {
        float vsum = accq[qq];
#pragma unroll
        for (int off = 16; off; off >>= 1)
            vsum += __shfl_xor_sync(0xffffffffu, vsum, off);
        if (lane == 0) redw[wid * 8 + qq] = vsum;
    }
    __syncthreads();
    if (tid < 8) {
        float s = b_in[tid];
#pragma unroll
        for (int w = 0; w < 8; w++) s += redw[w * 8 + tid];
        angs[tid] = s * 0.5f;
    }
    st[0][tid] = make_float2(tid == 0 ? 1.f : 0.f, 0.f);
    __syncthreads();

    int curb = 0;
#pragma unroll
    for (int w = 0; w < 8; w++) {
        int mask = 1 << (7 - w);
        float sn, cs;
        __sincosf(angs[w], &sn, &cs);
        float2 a  = st[curb][tid];
        float2 bb = st[curb][tid ^ mask];
        st[curb ^ 1][tid] = make_float2(fmaf(cs, a.x,  sn * bb.y),
                                        fmaf(cs, a.y, -sn * bb.x));
        curb ^= 1;
        __syncthreads();
    }
#pragma unroll
    for (int w = 0; w < 8; w++) {
        int mask = 1 << (7 - w);
        float sn, cs;
        __sincosf(ry[w] * 0.5f, &sn, &cs);
        float2 a  = st[curb][tid];
        float2 bb = st[curb][tid ^ mask];
        float sg = (tid & mask) ? sn : -sn;
        st[curb ^ 1][tid] = make_float2(fmaf(cs, a.x, sg * bb.x),
                                        fmaf(cs, a.y, sg * bb.y));
        curb ^= 1;
        __syncthreads();
    }
    int src = tid;
#pragma unroll
    for (int c = 6; c >= 0; c--) {
        int cmask = 1 << (7 - c);
        int tmask = cmask >> 1;
        if (src & cmask) src ^= tmask;
    }
    float2 fa = st[curb][src];
    float p = fa.x * fa.x + fa.y * fa.y;

#pragma unroll
    for (int w = 0; w < 8; w++) {
        float vsum = ((tid >> (7 - w)) & 1) ? -p : p;
#pragma unroll
        for (int off = 16; off; off >>= 1)
            vsum += __shfl_xor_sync(0xffffffffu, vsum, off);
        if (lane == 0) redw[wid * 8 + w] = vsum;
    }
    __syncthreads();
    if (tid < 8) {
        float s = 0.f;
#pragma unroll
        for (int w = 0; w < 8; w++) s += redw[w * 8 + tid];
        ezs[tid] = s;
    }
    __syncthreads();
    float e[8];
#pragma unroll
    for (int qq = 0; qq < 8; qq++) e[qq] = ezs[qq];

    // ---- ffn + residual + LN2 ----
    float y[4], sum = 0.f, sq = 0.f;
#pragma unroll
    for (int j = 0; j < 4; j++) {
        int d = tid + (j << 8);
        const float4* wrow = reinterpret_cast<const float4*>(Wout + (size_t)d * 8);
        float4 w0 = wrow[0], w1 = wrow[1];
        float acc = b_out[d];
        acc = fmaf(e[0], w0.x, acc); acc = fmaf(e[1], w0.y, acc);
        acc = fmaf(e[2], w0.z, acc); acc = fmaf(e[3], w0.w, acc);
        acc = fmaf(e[4], w1.x, acc); acc = fmaf(e[5], w1.y, acc);
        acc = fmaf(e[6], w1.z, acc); acc = fmaf(e[7], w1.w, acc);
        acc = fmaxf(acc, 0.f);
        float yv = xv[j] + acc;
        y[j] = yv; sum += yv; sq = fmaf(yv, yv, sq);
    }
    __syncthreads();
#pragma unroll
    for (int off = 16; off; off >>= 1) {
        sum += __shfl_xor_sync(0xffffffffu, sum, off);
        sq  += __shfl_xor_sync(0xffffffffu, sq, off);
    }
    if (lane == 0) { redw[wid] = sum; redw[8 + wid] = sq; }
    __syncthreads();
    float tsum = 0.f, tsq = 0.f;
#pragma unroll
    for (int w = 0; w < 8; w++) { tsum += redw[w]; tsq += redw[8 + w]; }
    float mean = tsum * (1.f / 1024.f);
    float var  = tsq * (1.f / 1024.f) - mean * mean;
    float rstd = rsqrtf(var + EPSf);
#pragma unroll
    for (int j = 0; j < 4; j++) {
        int d = tid + (j << 8);
        out[(size_t)row * Dm + d] = (y[j] - mean) * rstd * g2[d] + b2[d];
    }
}

// ---------------- launch ----------------
extern "C" void kernel_launch(void* const* d_in, const int* in_sizes, int n_in,
                              void* d_out, int out_size)
{
    const float* x     = (const float*)d_in[0];
    const float* Wq    = (const float*)d_in[1];
    const float* Wk    = (const float*)d_in[2];
    const float* Wv    = (const float*)d_in[3];
    const float* Wo    = (const float*)d_in[4];
    const float* g1    = (const float*)d_in[5];
    const float* b1    = (const float*)d_in[6];
    const float* g2    = (const float*)d_in[7];
    const float* b2    = (const float*)d_in[8];
    const float* Win   = (const float*)d_in[9];
    const float* b_in  = (const float*)d_in[10];
    const float* Wout  = (const float*)d_in[11];
    const float* b_out = (const float*)d_in[12];
    const float* ry    = (const float*)d_in[13];
    float* out = (float*)d_out;

    float *q, *k, *v, *o, *proj;
    cudaGetSymbolAddress((void**)&q,    g_q);
    cudaGetSymbolAddress((void**)&k,    g_k);
    cudaGetSymbolAddress((void**)&v,    g_v);
    cudaGetSymbolAddress((void**)&o,    g_o);
    cudaGetSymbolAddress((void**)&proj, g_proj);

    cudaFuncSetAttribute(gemm_mma,  cudaFuncAttributeMaxDynamicSharedMemorySize, GSMEM);
    cudaFuncSetAttribute(gemm_qkv,  cudaFuncAttributeMaxDynamicSharedMemorySize, GSMEM);
    cudaFuncSetAttribute(flash_mma, cudaFuncAttributeMaxDynamicSharedMemorySize, FA_SMEM);

    gemm_qkv<<<dim3(Dm / BN, Mtot / BM, 3), 256, GSMEM>>>(x, Wq, Wk, Wv, q, k, v);
    flash_mma<<<dim3(Sq / 128, Hh, Bsz), 256, FA_SMEM>>>(q, k, v, o);
    gemm_mma<<<dim3(Dm / BN, Mtot / BM), 256, GSMEM>>>(o, Wo, proj);
    ln_quantum<<<Mtot, 256>>>(x, proj, g1, b1, Win, b_in, Wout, b_out, ry, g2, b2, out);
}

// round 6
// speedup vs baseline: 1.2821x; 1.2821x over previous
#include <cuda_runtime.h>
#include <math.h>
#include <cstdint>

#define Bsz   2
#define Sq    2048
#define Dm    1024
#define Hh    16
#define Mtot  4096
#define DIMq  256
#define EPSf  1e-5f
#define LOG2E 1.44269504088896f

// ---------------- scratch (device globals; no allocs allowed) ----------------
__device__ float g_q[Mtot * Dm];
__device__ float g_k[Mtot * Dm];
__device__ float g_v[Mtot * Dm];
__device__ float g_o[Mtot * Dm];
__device__ float g_proj[Mtot * Dm];

// ======================= helpers =======================
__device__ __forceinline__ uint32_t smem_to_u32(const void* p) {
    uint32_t a;
    asm("{ .reg .u64 t; cvta.to.shared.u64 t, %1; cvt.u32.u64 %0, t; }" : "=r"(a) : "l"(p));
    return a;
}
__device__ __forceinline__ void cp16(uint32_t sm, const void* g) {
    asm volatile("cp.async.cg.shared.global [%0], [%1], 16;" :: "r"(sm), "l"(g));
}
__device__ __forceinline__ void cp_commit() {
    asm volatile("cp.async.commit_group;");
}
template <int N>
__device__ __forceinline__ void cp_wait() {
    asm volatile("cp.async.wait_group %0;" :: "n"(N));
}
__device__ __forceinline__ uint32_t f2tf32(float x) {
    uint32_t r;
    asm("cvt.rna.tf32.f32 %0, %1;" : "=r"(r) : "f"(x));
    return r;
}
__device__ __forceinline__ void mma_tf32(float c[4], const uint32_t a[4], const uint32_t b[2]) {
    asm volatile(
        "mma.sync.aligned.m16n8k8.row.col.f32.tf32.tf32.f32 "
        "{%0,%1,%2,%3}, {%4,%5,%6,%7}, {%8,%9}, {%0,%1,%2,%3};"
        : "+f"(c[0]), "+f"(c[1]), "+f"(c[2]), "+f"(c[3])
        : "r"(a[0]), "r"(a[1]), "r"(a[2]), "r"(a[3]), "r"(b[0]), "r"(b[1]));
}

// ============ tf32 mma.sync GEMM core: C[M,1024] = A[M,1024] * W[1024,1024]^T =
#define BM 128
#define BN 256
#define BK 32
#define LDP 36
#define A_STAGE_B (BM * LDP * 4)
#define B_STAGE_B (BN * LDP * 4)
#define GSMEM (3 * (A_STAGE_B + B_STAGE_B))
#define NKT (Dm / BK)

__device__ __forceinline__ void gemm_body(const float* __restrict__ A,
                                          const float* __restrict__ W,
                                          float* __restrict__ C,
                                          char* gsm)
{
    const uint32_t usm = smem_to_u32(gsm);
    const uint32_t usmA = usm;
    const uint32_t usmB = usm + 3 * A_STAGE_B;

    const int tid  = threadIdx.x;
    const int wid  = tid >> 5;
    const int lane = tid & 31;
    const int grp  = lane >> 2;
    const int tig  = lane & 3;
    const int wm   = wid >> 2;
    const int wn   = wid & 3;

    const int aRow0 = blockIdx.y * BM;
    const int bRow0 = blockIdx.x * BN;

    int aSm[4], bSm[8];
    int aGm[4], bGm[8];
#pragma unroll
    for (int i = 0; i < 4; i++) {
        int e = tid + (i << 8);
        int r = e >> 3, c4 = (e & 7) << 2;
        aSm[i] = (r * LDP + c4) * 4;
        aGm[i] = r * Dm + c4;
    }
#pragma unroll
    for (int i = 0; i < 8; i++) {
        int e = tid + (i << 8);
        int r = e >> 3, c4 = (e & 7) << 2;
        bSm[i] = (r * LDP + c4) * 4;
        bGm[i] = r * Dm + c4;
    }
    const float* gA = A + (size_t)aRow0 * Dm;
    const float* gB = W + (size_t)bRow0 * Dm;

    float acc[4][8][4];
#pragma unroll
    for (int im = 0; im < 4; im++)
#pragma unroll
        for (int jn = 0; jn < 8; jn++)
#pragma unroll
            for (int t = 0; t < 4; t++) acc[im][jn][t] = 0.f;

#pragma unroll
    for (int p = 0; p < 2; p++) {
        uint32_t sa = usmA + p * A_STAGE_B;
        uint32_t sb = usmB + p * B_STAGE_B;
        const float* ka = gA + p * BK;
        const float* kb = gB + p * BK;
#pragma unroll
        for (int i = 0; i < 4; i++) cp16(sa + aSm[i], ka + aGm[i]);
#pragma unroll
        for (int i = 0; i < 8; i++) cp16(sb + bSm[i], kb + bGm[i]);
        cp_commit();
    }

    for (int kt = 0; kt < NKT; kt++) {
        cp_wait<1>();
        __syncthreads();

        if (kt + 2 < NKT) {
            int s = (kt + 2) % 3;
            uint32_t sa = usmA + s * A_STAGE_B;
            uint32_t sb = usmB + s * B_STAGE_B;
            const float* ka = gA + (kt + 2) * BK;
            const float* kb = gB + (kt + 2) * BK;
#pragma unroll
            for (int i = 0; i < 4; i++) cp16(sa + aSm[i], ka + aGm[i]);
#pragma unroll
            for (int i = 0; i < 8; i++) cp16(sb + bSm[i], kb + bGm[i]);
        }
        cp_commit();

        const float* As = (const float*)(gsm + (kt % 3) * A_STAGE_B);
        const float* Bs = (const float*)(gsm + 3 * A_STAGE_B + (kt % 3) * B_STAGE_B);

#pragma unroll
        for (int k8 = 0; k8 < 4; k8++) {
            const int kb = k8 * 8 + tig;
            uint32_t afr[4][4], bfr[8][2];
#pragma unroll
            for (int im = 0; im < 4; im++) {
                int row = wm * 64 + im * 16 + grp;
                afr[im][0] = f2tf32(As[row * LDP + kb]);
                afr[im][1] = f2tf32(As[(row + 8) * LDP + kb]);
                afr[im][2] = f2tf32(As[row * LDP + kb + 4]);
                afr[im][3] = f2tf32(As[(row + 8) * LDP + kb + 4]);
            }
#pragma unroll
            for (int jn = 0; jn < 8; jn++) {
                int brow = wn * 64 + jn * 8 + grp;
                bfr[jn][0] = f2tf32(Bs[brow * LDP + kb]);
                bfr[jn][1] = f2tf32(Bs[brow * LDP + kb + 4]);
            }
#pragma unroll
            for (int im = 0; im < 4; im++)
#pragma unroll
                for (int jn = 0; jn < 8; jn++)
                    mma_tf32(acc[im][jn], afr[im], bfr[jn]);
        }
        __syncthreads();
    }

    const int rowBase = aRow0 + wm * 64;
    const int colBase = bRow0 + wn * 64;
#pragma unroll
    for (int im = 0; im < 4; im++) {
        int r0 = rowBase + im * 16 + grp;
#pragma unroll
        for (int jn = 0; jn < 8; jn++) {
            int col = colBase + jn * 8 + 2 * tig;
            float2 v01 = make_float2(acc[im][jn][0], acc[im][jn][1]);
            float2 v23 = make_float2(acc[im][jn][2], acc[im][jn][3]);
            *reinterpret_cast<float2*>(C + (size_t)r0 * Dm + col) = v01;
            *reinterpret_cast<float2*>(C + (size_t)(r0 + 8) * Dm + col) = v23;
        }
    }
}

__global__ __launch_bounds__(256, 1) void gemm_mma(const float* __restrict__ A,
                                                   const float* __restrict__ W,
                                                   float* __restrict__ C)
{
    extern __shared__ __align__(16) char gsm[];
    gemm_body(A, W, C, gsm);
}

__global__ __launch_bounds__(256, 1) void gemm_qkv(const float* __restrict__ A,
                                                   const float* __restrict__ W0,
                                                   const float* __restrict__ W1,
                                                   const float* __restrict__ W2,
                                                   float* __restrict__ C0,
                                                   float* __restrict__ C1,
                                                   float* __restrict__ C2)
{
    extern __shared__ __align__(16) char gsm[];
    const int z = blockIdx.z;
    const float* W = (z == 0) ? W0 : (z == 1) ? W1 : W2;
    float*       C = (z == 0) ? C0 : (z == 1) ? C1 : C2;
    gemm_body(A, W, C, gsm);
}

// ============ Flash attention with tf32 mma.sync (R4-proven structure) ======
// CTA: 128 Q rows, 8 warps (16 rows each). KV tiles of 64. head dim 64.
#define FA_PP 68
#define FA_PK 68
#define FA_PV 72
#define PS_OFF 0
#define KS_OFF (128 * FA_PP)
#define KS_STRIDE (64 * FA_PK)
#define VS_OFF (KS_OFF + 2 * KS_STRIDE)
#define VS_STRIDE (64 * FA_PV)
#define FA_SMEM ((VS_OFF + 2 * VS_STRIDE) * 4)  // 106496 B
#define NKV (Sq / 64)

__global__ __launch_bounds__(256, 1) void flash_mma(const float* __restrict__ q,
                                                    const float* __restrict__ k,
                                                    const float* __restrict__ v,
                                                    float* __restrict__ o)
{
    extern __shared__ __align__(16) float fsm[];
    const uint32_t usm = smem_to_u32(fsm);

    const int tid  = threadIdx.x;
    const int wid  = tid >> 5;
    const int lane = tid & 31;
    const int grp  = lane >> 2;
    const int tig  = lane & 3;

    const int b  = blockIdx.z;
    const int h  = blockIdx.y;
    const int q0 = blockIdx.x << 7;

    const float* qg = q + (((size_t)(b * Sq + q0) * Hh + h) << 6);
    const float* kg = k + (((size_t)(b * Sq) * Hh + h) << 6);
    const float* vg = v + (((size_t)(b * Sq) * Hh + h) << 6);

    // ---- prologue: stage Q; prefetch K0,V0 and K1,V1 ----
    {
#pragma unroll
        for (int i = 0; i < 8; i++) {
            int e = tid + (i << 8);
            int r = e >> 4, c4 = (e & 15) << 2;
            cp16(usm + (PS_OFF + r * FA_PP + c4) * 4, qg + (size_t)r * 1024 + c4);
        }
#pragma unroll
        for (int i = 0; i < 4; i++) {
            int e = tid + (i << 8);
            int r = e >> 4, c4 = (e & 15) << 2;
            cp16(usm + (KS_OFF + r * FA_PK + c4) * 4, kg + (size_t)r * 1024 + c4);
            cp16(usm + (VS_OFF + r * FA_PV + c4) * 4, vg + (size_t)r * 1024 + c4);
        }
        cp_commit();
#pragma unroll
        for (int i = 0; i < 4; i++) {
            int e = tid + (i << 8);
            int r = e >> 4, c4 = (e & 15) << 2;
            cp16(usm + (KS_OFF + KS_STRIDE + r * FA_PK + c4) * 4, kg + (size_t)(64 + r) * 1024 + c4);
            cp16(usm + (VS_OFF + VS_STRIDE + r * FA_PV + c4) * 4, vg + (size_t)(64 + r) * 1024 + c4);
        }
        cp_commit();
    }
    cp_wait<1>();
    __syncthreads();

    // ---- Q fragments: scale 0.125*log2e folded in (base-2 softmax) ----
    const int lr0 = wid * 16 + grp;
    const float qs = 0.125f * LOG2E;
    uint32_t qf[8][4];
#pragma unroll
    for (int k8 = 0; k8 < 8; k8++) {
        int kc = k8 * 8 + tig;
        qf[k8][0] = f2tf32(fsm[PS_OFF + lr0 * FA_PP + kc] * qs);
        qf[k8][1] = f2tf32(fsm[PS_OFF + (lr0 + 8) * FA_PP + kc] * qs);
        qf[k8][2] = f2tf32(fsm[PS_OFF + lr0 * FA_PP + kc + 4] * qs);
        qf[k8][3] = f2tf32(fsm[PS_OFF + (lr0 + 8) * FA_PP + kc + 4] * qs);
    }
    __syncthreads();

    float m0 = -1e30f, m1 = -1e30f, l0 = 0.f, l1 = 0.f;
    float oac[8][4];
#pragma unroll
    for (int jd = 0; jd < 8; jd++)
#pragma unroll
        for (int t = 0; t < 4; t++) oac[jd][t] = 0.f;

    for (int it = 0; it < NKV; it++) {
        const int buf = it & 1;
        const float* Kb = fsm + KS_OFF + buf * KS_STRIDE;
        const float* Vb = fsm + VS_OFF + buf * VS_STRIDE;

        // ---- S = Q K^T ----
        float sac[8][4];
#pragma unroll
        for (int jn = 0; jn < 8; jn++)
#pragma unroll
            for (int t = 0; t < 4; t++) sac[jn][t] = 0.f;
#pragma unroll
        for (int k8 = 0; k8 < 8; k8++) {
            int kc = k8 * 8 + tig;
            uint32_t bfr[8][2];
#pragma unroll
            for (int jn = 0; jn < 8; jn++) {
                int krow = jn * 8 + grp;
                bfr[jn][0] = f2tf32(Kb[krow * FA_PK + kc]);
                bfr[jn][1] = f2tf32(Kb[krow * FA_PK + kc + 4]);
            }
#pragma unroll
            for (int jn = 0; jn < 8; jn++)
                mma_tf32(sac[jn], qf[k8], bfr[jn]);
        }

        // ---- online softmax (base-2; rows in quads: shfl_xor 1,2) ----
        float mx0 = -1e30f, mx1 = -1e30f;
#pragma unroll
        for (int jn = 0; jn < 8; jn++) {
            mx0 = fmaxf(mx0, fmaxf(sac[jn][0], sac[jn][1]));
            mx1 = fmaxf(mx1, fmaxf(sac[jn][2], sac[jn][3]));
        }
        mx0 = fmaxf(mx0, __shfl_xor_sync(0xffffffffu, mx0, 1));
        mx0 = fmaxf(mx0, __shfl_xor_sync(0xffffffffu, mx0, 2));
        mx1 = fmaxf(mx1, __shfl_xor_sync(0xffffffffu, mx1, 1));
        mx1 = fmaxf(mx1, __shfl_xor_sync(0xffffffffu, mx1, 2));
        float mn0 = fmaxf(m0, mx0), mn1 = fmaxf(m1, mx1);
        float al0 = exp2f(m0 - mn0), al1 = exp2f(m1 - mn1);

        float sum0 = 0.f, sum1 = 0.f;
#pragma unroll
        for (int jn = 0; jn < 8; jn++) {
            float p00 = exp2f(sac[jn][0] - mn0);
            float p01 = exp2f(sac[jn][1] - mn0);
            float p10 = exp2f(sac[jn][2] - mn1);
            float p11 = exp2f(sac[jn][3] - mn1);
            int c = jn * 8 + 2 * tig;
            *reinterpret_cast<float2*>(&fsm[PS_OFF + lr0 * FA_PP + c])       = make_float2(p00, p01);
            *reinterpret_cast<float2*>(&fsm[PS_OFF + (lr0 + 8) * FA_PP + c]) = make_float2(p10, p11);
            sum0 += p00 + p01;
            sum1 += p10 + p11;
        }
        sum0 += __shfl_xor_sync(0xffffffffu, sum0, 1);
        sum0 += __shfl_xor_sync(0xffffffffu, sum0, 2);
        sum1 += __shfl_xor_sync(0xffffffffu, sum1, 1);
        sum1 += __shfl_xor_sync(0xffffffffu, sum1, 2);
        l0 = l0 * al0 + sum0;  m0 = mn0;
        l1 = l1 * al1 + sum1;  m1 = mn1;
#pragma unroll
        for (int jd = 0; jd < 8; jd++) {
            oac[jd][0] *= al0; oac[jd][1] *= al0;
            oac[jd][2] *= al1; oac[jd][3] *= al1;
        }
        __syncwarp();

        // ---- O += P V ----
#pragma unroll
        for (int k8 = 0; k8 < 8; k8++) {
            int kc = k8 * 8 + tig;
            uint32_t afr[4];
            afr[0] = f2tf32(fsm[PS_OFF + lr0 * FA_PP + kc]);
            afr[1] = f2tf32(fsm[PS_OFF + (lr0 + 8) * FA_PP + kc]);
            afr[2] = f2tf32(fsm[PS_OFF + lr0 * FA_PP + kc + 4]);
            afr[3] = f2tf32(fsm[PS_OFF + (lr0 + 8) * FA_PP + kc + 4]);
            uint32_t bfr[8][2];
#pragma unroll
            for (int jd = 0; jd < 8; jd++) {
                int dcol = jd * 8 + grp;
                bfr[jd][0] = f2tf32(Vb[(k8 * 8 + tig) * FA_PV + dcol]);
                bfr[jd][1] = f2tf32(Vb[(k8 * 8 + tig + 4) * FA_PV + dcol]);
            }
#pragma unroll
            for (int jd = 0; jd < 8; jd++)
                mma_tf32(oac[jd], afr, bfr[jd]);
        }

        // ---- prefetch it+2 into buffer `buf` ----
        __syncthreads();
        if (it < NKV - 1) {
            if (it + 2 < NKV) {
                int kv0 = (it + 2) << 6;
#pragma unroll
                for (int i = 0; i < 4; i++) {
                    int e = tid + (i << 8);
                    int r = e >> 4, c4 = (e & 15) << 2;
                    cp16(usm + (KS_OFF + buf * KS_STRIDE + r * FA_PK + c4) * 4,
                         kg + (size_t)(kv0 + r) * 1024 + c4);
                    cp16(usm + (VS_OFF + buf * VS_STRIDE + r * FA_PV + c4) * 4,
                         vg + (size_t)(kv0 + r) * 1024 + c4);
                }
            }
            cp_commit();
            cp_wait<1>();
            __syncthreads();
        }
    }

    // ---- epilogue ----
    const float inv0 = 1.f / l0, inv1 = 1.f / l1;
    float* og  = o + (((size_t)(b * Sq + q0 + lr0) * Hh + h) << 6);
    float* og8 = og + (size_t)8 * 1024;
#pragma unroll
    for (int jd = 0; jd < 8; jd++) {
        int c = jd * 8 + 2 * tig;
        *reinterpret_cast<float2*>(og + c)  = make_float2(oac[jd][0] * inv0, oac[jd][1] * inv0);
        *reinterpret_cast<float2*>(og8 + c) = make_float2(oac[jd][2] * inv1, oac[jd][3] * inv1);
    }
}

// ========= fused: x1 = LN(x + proj); quantum FFN; out = LN(x1 + ffn) =========
__global__ __launch_bounds__(256) void ln_quantum(const float* __restrict__ x,
                                                  const float* __restrict__ proj,
                                                  const float* __restrict__ g1,
                                                  const float* __restrict__ b1,
                                                  const float* __restrict__ Win,
                                                  const float* __restrict__ b_in,
                                                  const float* __restrict__ Wout,
                                                  const float* __restrict__ b_out,
                                                  const float* __restrict__ ry,
                                                  const float* __restrict__ g2,
                                                  const float* __restrict__ b2,
                                                  float* __restrict__ out)
{
    const int row = blockIdx.x;
    const int tid = threadIdx.x;
    const int lane = tid & 31, wid = tid >> 5;
    const float* px = x + (size_t)row * Dm;
    const float* pp = proj + (size_t)row * Dm;

    __shared__ float redw[64];
    __shared__ float angs[8];
    __shared__ float ezs[8];
    __shared__ float2 st[2][DIMq];

    float xv[4];
    {
        float yv[4], sum = 0.f, sq = 0.f;
#pragma unroll
        for (int j = 0; j < 4; j++) {
            int d = tid + (j << 8);
            float t = px[d] + pp[d];
            yv[j] = t; sum += t; sq = fmaf(t, t, sq);
        }
#pragma unroll
        for (int off = 16; off; off >>= 1) {
            sum += __shfl_xor_sync(0xffffffffu, sum, off);
            sq  += __shfl_xor_sync(0xffffffffu, sq, off);
        }
        if (lane == 0) { redw[wid] = sum; redw[8 + wid] = sq; }
        __syncthreads();
        float tsum = 0.f, tsq = 0.f;
#pragma unroll
        for (int w = 0; w < 8; w++) { tsum += redw[w]; tsq += redw[8 + w]; }
        float mean = tsum * (1.f / 1024.f);
        float var  = tsq * (1.f / 1024.f) - mean * mean;
        float rstd = rsqrtf(var + EPSf);
#pragma unroll
        for (int j = 0; j < 4; j++) {
            int d = tid + (j << 8);
            xv[j] = (yv[j] - mean) * rstd * g1[d] + b1[d];
        }
        __syncthreads();
    }

    float accq[8] = {0, 0, 0, 0, 0, 0, 0, 0};
#pragma unroll
    for (int j = 0; j < 4; j++) {
        int d = tid + (j << 8);
#pragma unroll
        for (int qq = 0; qq < 8; qq++)
            accq[qq] = fmaf(xv[j], Win[qq * Dm + d], accq[qq]);
    }
#pragma unroll
    for (int qq = 0; qq < 8; qq++) {
        float vsum = accq[qq];
#pragma unroll
        for (int off = 16; off; off >>= 1)
            vsum += __shfl_xor_sync(0xffffffffu, vsum, off);
        if (lane == 0) redw[wid * 8 + qq] = vsum;
    }
    __syncthreads();
    if (tid < 8) {
        float s = b_in[tid];
#pragma unroll
        for (int w = 0; w < 8; w++) s += redw[w * 8 + tid];
        angs[tid] = s * 0.5f;
    }
    st[0][tid] = make_float2(tid == 0 ? 1.f : 0.f, 0.f);
    __syncthreads();

    int curb = 0;
#pragma unroll
    for (int w = 0; w < 8; w++) {
        int mask = 1 << (7 - w);
        float sn, cs;
        __sincosf(angs[w], &sn, &cs);
        float2 a  = st[curb][tid];
        float2 bb = st[curb][tid ^ mask];
        st[curb ^ 1][tid] = make_float2(fmaf(cs, a.x,  sn * bb.y),
                                        fmaf(cs, a.y, -sn * bb.x));
        curb ^= 1;
        __syncthreads();
    }
#pragma unroll
    for (int w = 0; w < 8; w++) {
        int mask = 1 << (7 - w);
        float sn, cs;
        __sincosf(ry[w] * 0.5f, &sn, &cs);
        float2 a  = st[curb][tid];
        float2 bb = st[curb][tid ^ mask];
        float sg = (tid & mask) ? sn : -sn;
        st[curb ^ 1][tid] = make_float2(fmaf(cs, a.x, sg * bb.x),
                                        fmaf(cs, a.y, sg * bb.y));
        curb ^= 1;
        __syncthreads();
    }
    int src = tid;
#pragma unroll
    for (int c = 6; c >= 0; c--) {
        int cmask = 1 << (7 - c);
        int tmask = cmask >> 1;
        if (src & cmask) src ^= tmask;
    }
    float2 fa = st[curb][src];
    float p = fa.x * fa.x + fa.y * fa.y;

#pragma unroll
    for (int w = 0; w < 8; w++) {
        float vsum = ((tid >> (7 - w)) & 1) ? -p : p;
#pragma unroll
        for (int off = 16; off; off >>= 1)
            vsum += __shfl_xor_sync(0xffffffffu, vsum, off);
        if (lane == 0) redw[wid * 8 + w] = vsum;
    }
    __syncthreads();
    if (tid < 8) {
        float s = 0.f;
#pragma unroll
        for (int w = 0; w < 8; w++) s += redw[w * 8 + tid];
        ezs[tid] = s;
    }
    __syncthreads();
    float e[8];
#pragma unroll
    for (int qq = 0; qq < 8; qq++) e[qq] = ezs[qq];

    float y[4], sum = 0.f, sq = 0.f;
#pragma unroll
    for (int j = 0; j < 4; j++) {
        int d = tid + (j << 8);
        const float4* wrow = reinterpret_cast<const float4*>(Wout + (size_t)d * 8);
        float4 w0 = wrow[0], w1 = wrow[1];
        float acc = b_out[d];
        acc = fmaf(e[0], w0.x, acc); acc = fmaf(e[1], w0.y, acc);
        acc = fmaf(e[2], w0.z, acc); acc = fmaf(e[3], w0.w, acc);
        acc = fmaf(e[4], w1.x, acc); acc = fmaf(e[5], w1.y, acc);
        acc = fmaf(e[6], w1.z, acc); acc = fmaf(e[7], w1.w, acc);
        acc = fmaxf(acc, 0.f);
        float yv = xv[j] + acc;
        y[j] = yv; sum += yv; sq = fmaf(yv, yv, sq);
    }
    __syncthreads();
#pragma unroll
    for (int off = 16; off; off >>= 1) {
        sum += __shfl_xor_sync(0xffffffffu, sum, off);
        sq  += __shfl_xor_sync(0xffffffffu, sq, off);
    }
    if (lane == 0) { redw[wid] = sum; redw[8 + wid] = sq; }
    __syncthreads();
    float tsum = 0.f, tsq = 0.f;
#pragma unroll
    for (int w = 0; w < 8; w++) { tsum += redw[w]; tsq += redw[8 + w]; }
    float mean = tsum * (1.f / 1024.f);
    float var  = tsq * (1.f / 1024.f) - mean * mean;
    float rstd = rsqrtf(var + EPSf);
#pragma unroll
    for (int j = 0; j < 4; j++) {
        int d = tid + (j << 8);
        out[(size_t)row * Dm + d] = (y[j] - mean) * rstd * g2[d] + b2[d];
    }
}

// ---------------- launch ----------------
extern "C" void kernel_launch(void* const* d_in, const int* in_sizes, int n_in,
                              void* d_out, int out_size)
{
    const float* x     = (const float*)d_in[0];
    const float* Wq    = (const float*)d_in[1];
    const float* Wk    = (const float*)d_in[2];
    const float* Wv    = (const float*)d_in[3];
    const float* Wo    = (const float*)d_in[4];
    const float* g1    = (const float*)d_in[5];
    const float* b1    = (const float*)d_in[6];
    const float* g2    = (const float*)d_in[7];
    const float* b2    = (const float*)d_in[8];
    const float* Win   = (const float*)d_in[9];
    const float* b_in  = (const float*)d_in[10];
    const float* Wout  = (const float*)d_in[11];
    const float* b_out = (const float*)d_in[12];
    const float* ry    = (const float*)d_in[13];
    float* out = (float*)d_out;

    float *q, *k, *v, *o, *proj;
    cudaGetSymbolAddress((void**)&q,    g_q);
    cudaGetSymbolAddress((void**)&k,    g_k);
    cudaGetSymbolAddress((void**)&v,    g_v);
    cudaGetSymbolAddress((void**)&o,    g_o);
    cudaGetSymbolAddress((void**)&proj, g_proj);

    cudaFuncSetAttribute(gemm_mma,  cudaFuncAttributeMaxDynamicSharedMemorySize, GSMEM);
    cudaFuncSetAttribute(gemm_qkv,  cudaFuncAttributeMaxDynamicSharedMemorySize, GSMEM);
    cudaFuncSetAttribute(flash_mma, cudaFuncAttributeMaxDynamicSharedMemorySize, FA_SMEM);

    gemm_qkv<<<dim3(Dm / BN, Mtot / BM, 3), 256, GSMEM>>>(x, Wq, Wk, Wv, q, k, v);
    flash_mma<<<dim3(Sq / 128, Hh, Bsz), 256, FA_SMEM>>>(q, k, v, o);
    gemm_mma<<<dim3(Dm / BN, Mtot / BM), 256, GSMEM>>>(o, Wo, proj);
    ln_quantum<<<Mtot, 256>>>(x, proj, g1, b1, Win, b_in, Wout, b_out, ry, g2, b2, out);
}

// round 7
// speedup vs baseline: 1.3387x; 1.0442x over previous
#include <cuda_runtime.h>
#include <math.h>
#include <cstdint>

#define Bsz   2
#define Sq    2048
#define Dm    1024
#define Hh    16
#define Mtot  4096
#define EPSf  1e-5f
#define LOG2E 1.44269504088896f

// ---------------- scratch ----------------
__device__ float g_q[Mtot * Dm];
__device__ float g_k[Mtot * Dm];
__device__ float g_v[Mtot * Dm];
__device__ float g_o[Mtot * Dm];
__device__ float g_proj[Mtot * Dm];

// ======================= helpers =======================
__device__ __forceinline__ uint32_t smem_to_u32(const void* p) {
    uint32_t a;
    asm("{ .reg .u64 t; cvta.to.shared.u64 t, %1; cvt.u32.u64 %0, t; }" : "=r"(a) : "l"(p));
    return a;
}
__device__ __forceinline__ void cp16(uint32_t sm, const void* g) {
    asm volatile("cp.async.cg.shared.global [%0], [%1], 16;" :: "r"(sm), "l"(g));
}
__device__ __forceinline__ void cp_commit() {
    asm volatile("cp.async.commit_group;");
}
template <int N>
__device__ __forceinline__ void cp_wait() {
    asm volatile("cp.async.wait_group %0;" :: "n"(N));
}
__device__ __forceinline__ uint32_t f2tf32(float x) {
    uint32_t r;
    asm("cvt.rna.tf32.f32 %0, %1;" : "=r"(r) : "f"(x));
    return r;
}
__device__ __forceinline__ float f2tf32f(float x) { return __uint_as_float(f2tf32(x)); }
__device__ __forceinline__ void mma_tf32(float c[4], const uint32_t a[4], const uint32_t b[2]) {
    asm volatile(
        "mma.sync.aligned.m16n8k8.row.col.f32.tf32.tf32.f32 "
        "{%0,%1,%2,%3}, {%4,%5,%6,%7}, {%8,%9}, {%0,%1,%2,%3};"
        : "+f"(c[0]), "+f"(c[1]), "+f"(c[2]), "+f"(c[3])
        : "r"(a[0]), "r"(a[1]), "r"(a[2]), "r"(a[3]), "r"(b[0]), "r"(b[1]));
}

// ============ tf32 mma.sync GEMM (unchanged, proven) ============
#define BM 128
#define BN 256
#define BK 32
#define LDP 36
#define A_STAGE_B (BM * LDP * 4)
#define B_STAGE_B (BN * LDP * 4)
#define GSMEM (3 * (A_STAGE_B + B_STAGE_B))
#define NKT (Dm / BK)

__device__ __forceinline__ void gemm_body(const float* __restrict__ A,
                                          const float* __restrict__ W,
                                          float* __restrict__ C,
                                          char* gsm)
{
    const uint32_t usm = smem_to_u32(gsm);
    const uint32_t usmA = usm;
    const uint32_t usmB = usm + 3 * A_STAGE_B;

    const int tid  = threadIdx.x;
    const int wid  = tid >> 5;
    const int lane = tid & 31;
    const int grp  = lane >> 2;
    const int tig  = lane & 3;
    const int wm   = wid >> 2;
    const int wn   = wid & 3;

    const int aRow0 = blockIdx.y * BM;
    const int bRow0 = blockIdx.x * BN;

    int aSm[4], bSm[8];
    int aGm[4], bGm[8];
#pragma unroll
    for (int i = 0; i < 4; i++) {
        int e = tid + (i << 8);
        int r = e >> 3, c4 = (e & 7) << 2;
        aSm[i] = (r * LDP + c4) * 4;
        aGm[i] = r * Dm + c4;
    }
#pragma unroll
    for (int i = 0; i < 8; i++) {
        int e = tid + (i << 8);
        int r = e >> 3, c4 = (e & 7) << 2;
        bSm[i] = (r * LDP + c4) * 4;
        bGm[i] = r * Dm + c4;
    }
    const float* gA = A + (size_t)aRow0 * Dm;
    const float* gB = W + (size_t)bRow0 * Dm;

    float acc[4][8][4];
#pragma unroll
    for (int im = 0; im < 4; im++)
#pragma unroll
        for (int jn = 0; jn < 8; jn++)
#pragma unroll
            for (int t = 0; t < 4; t++) acc[im][jn][t] = 0.f;

#pragma unroll
    for (int p = 0; p < 2; p++) {
        uint32_t sa = usmA + p * A_STAGE_B;
        uint32_t sb = usmB + p * B_STAGE_B;
        const float* ka = gA + p * BK;
        const float* kb = gB + p * BK;
#pragma unroll
        for (int i = 0; i < 4; i++) cp16(sa + aSm[i], ka + aGm[i]);
#pragma unroll
        for (int i = 0; i < 8; i++) cp16(sb + bSm[i], kb + bGm[i]);
        cp_commit();
    }

    for (int kt = 0; kt < NKT; kt++) {
        cp_wait<1>();
        __syncthreads();

        if (kt + 2 < NKT) {
            int s = (kt + 2) % 3;
            uint32_t sa = usmA + s * A_STAGE_B;
            uint32_t sb = usmB + s * B_STAGE_B;
            const float* ka = gA + (kt + 2) * BK;
            const float* kb = gB + (kt + 2) * BK;
#pragma unroll
            for (int i = 0; i < 4; i++) cp16(sa + aSm[i], ka + aGm[i]);
#pragma unroll
            for (int i = 0; i < 8; i++) cp16(sb + bSm[i], kb + bGm[i]);
        }
        cp_commit();

        const float* As = (const float*)(gsm + (kt % 3) * A_STAGE_B);
        const float* Bs = (const float*)(gsm + 3 * A_STAGE_B + (kt % 3) * B_STAGE_B);

#pragma unroll
        for (int k8 = 0; k8 < 4; k8++) {
            const int kb = k8 * 8 + tig;
            uint32_t afr[4][4], bfr[8][2];
#pragma unroll
            for (int im = 0; im < 4; im++) {
                int row = wm * 64 + im * 16 + grp;
                afr[im][0] = f2tf32(As[row * LDP + kb]);
                afr[im][1] = f2tf32(As[(row + 8) * LDP + kb]);
                afr[im][2] = f2tf32(As[row * LDP + kb + 4]);
                afr[im][3] = f2tf32(As[(row + 8) * LDP + kb + 4]);
            }
#pragma unroll
            for (int jn = 0; jn < 8; jn++) {
                int brow = wn * 64 + jn * 8 + grp;
                bfr[jn][0] = f2tf32(Bs[brow * LDP + kb]);
                bfr[jn][1] = f2tf32(Bs[brow * LDP + kb + 4]);
            }
#pragma unroll
            for (int im = 0; im < 4; im++)
#pragma unroll
                for (int jn = 0; jn < 8; jn++)
                    mma_tf32(acc[im][jn], afr[im], bfr[jn]);
        }
        __syncthreads();
    }

    const int rowBase = aRow0 + wm * 64;
    const int colBase = bRow0 + wn * 64;
#pragma unroll
    for (int im = 0; im < 4; im++) {
        int r0 = rowBase + im * 16 + grp;
#pragma unroll
        for (int jn = 0; jn < 8; jn++) {
            int col = colBase + jn * 8 + 2 * tig;
            float2 v01 = make_float2(acc[im][jn][0], acc[im][jn][1]);
            float2 v23 = make_float2(acc[im][jn][2], acc[im][jn][3]);
            *reinterpret_cast<float2*>(C + (size_t)r0 * Dm + col) = v01;
            *reinterpret_cast<float2*>(C + (size_t)(r0 + 8) * Dm + col) = v23;
        }
    }
}

__global__ __launch_bounds__(256, 1) void gemm_mma(const float* __restrict__ A,
                                                   const float* __restrict__ W,
                                                   float* __restrict__ C)
{
    extern __shared__ __align__(16) char gsm[];
    gemm_body(A, W, C, gsm);
}

__global__ __launch_bounds__(256, 1) void gemm_qkv(const float* __restrict__ A,
                                                   const float* __restrict__ W0,
                                                   const float* __restrict__ W1,
                                                   const float* __restrict__ W2,
                                                   float* __restrict__ C0,
                                                   float* __restrict__ C1,
                                                   float* __restrict__ C2)
{
    extern __shared__ __align__(16) char gsm[];
    const int z = blockIdx.z;
    const float* W = (z == 0) ? W0 : (z == 1) ? W1 : W2;
    float*       C = (z == 0) ? C0 : (z == 1) ? C1 : C2;
    gemm_body(A, W, C, gsm);
}

// ============ Flash attention: 32 Q rows/warp, Q pre-rounded in smem ========
// CTA: 256 Q rows, 8 warps (2 x 16-row blocks each). KV tiles of 64.
#define FA_PP 68
#define FA_PK 68
#define FA_PV 72
#define QS_OFF 0
#define PS_OFF (256 * FA_PP)                 // 17408
#define KS_OFF (PS_OFF + 256 * FA_PP)        // 34816
#define KS_STRIDE (64 * FA_PK)               // 4352
#define VS_OFF (KS_OFF + 2 * KS_STRIDE)      // 43520
#define VS_STRIDE (64 * FA_PV)               // 4608
#define FA_SMEM ((VS_OFF + 2 * VS_STRIDE) * 4)  // 210944 B
#define NKV (Sq / 64)

__global__ __launch_bounds__(256, 1) void flash_mma(const float* __restrict__ q,
                                                    const float* __restrict__ k,
                                                    const float* __restrict__ v,
                                                    float* __restrict__ o)
{
    extern __shared__ __align__(16) float fsm[];
    const uint32_t usm = smem_to_u32(fsm);

    const int tid  = threadIdx.x;
    const int wid  = tid >> 5;
    const int lane = tid & 31;
    const int grp  = lane >> 2;
    const int tig  = lane & 3;

    const int b  = blockIdx.z;
    const int h  = blockIdx.y;
    const int q0 = blockIdx.x << 8;          // 256 Q rows per CTA

    const float* qg = q + (((size_t)(b * Sq + q0) * Hh + h) << 6);
    const float* kg = k + (((size_t)(b * Sq) * Hh + h) << 6);
    const float* vg = v + (((size_t)(b * Sq) * Hh + h) << 6);

    // ---- prologue: stage Q (256x64) raw; prefetch K0,V0 and K1,V1 ----
    {
#pragma unroll
        for (int i = 0; i < 16; i++) {
            int e = tid + (i << 8);
            int r = e >> 4, c4 = (e & 15) << 2;
            cp16(usm + (QS_OFF + r * FA_PP + c4) * 4, qg + (size_t)r * 1024 + c4);
        }
#pragma unroll
        for (int i = 0; i < 4; i++) {
            int e = tid + (i << 8);
            int r = e >> 4, c4 = (e & 15) << 2;
            cp16(usm + (KS_OFF + r * FA_PK + c4) * 4, kg + (size_t)r * 1024 + c4);
            cp16(usm + (VS_OFF + r * FA_PV + c4) * 4, vg + (size_t)r * 1024 + c4);
        }
        cp_commit();                         // g0: Q + K0 + V0
#pragma unroll
        for (int i = 0; i < 4; i++) {
            int e = tid + (i << 8);
            int r = e >> 4, c4 = (e & 15) << 2;
            cp16(usm + (KS_OFF + KS_STRIDE + r * FA_PK + c4) * 4, kg + (size_t)(64 + r) * 1024 + c4);
            cp16(usm + (VS_OFF + VS_STRIDE + r * FA_PV + c4) * 4, vg + (size_t)(64 + r) * 1024 + c4);
        }
        cp_commit();                         // g1: K1 + V1
    }
    cp_wait<1>();
    __syncthreads();

    // ---- round Q in place (scale 0.125*log2e folded in) ----
    {
        const float qs = 0.125f * LOG2E;
#pragma unroll
        for (int i = 0; i < 16; i++) {
            int e = tid + (i << 8);
            int r = e >> 4, c4 = (e & 15) << 2;
            float4* p = reinterpret_cast<float4*>(fsm + QS_OFF + r * FA_PP + c4);
            float4 vq = *p;
            vq.x = f2tf32f(vq.x * qs); vq.y = f2tf32f(vq.y * qs);
            vq.z = f2tf32f(vq.z * qs); vq.w = f2tf32f(vq.w * qs);
            *p = vq;
        }
    }
    __syncthreads();

    const int lr0 = wid * 32 + grp;          // rb0 first row (local)
    const int lr1 = lr0 + 16;                // rb1 first row

    float m00 = -1e30f, m01 = -1e30f, m10 = -1e30f, m11 = -1e30f;
    float l00 = 0.f, l01 = 0.f, l10 = 0.f, l11 = 0.f;
    float oac0[8][4], oac1[8][4];
#pragma unroll
    for (int jd = 0; jd < 8; jd++)
#pragma unroll
        for (int t = 0; t < 4; t++) { oac0[jd][t] = 0.f; oac1[jd][t] = 0.f; }

    for (int it = 0; it < NKV; it++) {
        const int buf = it & 1;
        const float* Kb = fsm + KS_OFF + buf * KS_STRIDE;
        const float* Vb = fsm + VS_OFF + buf * VS_STRIDE;

        // ---- S = Q K^T for both row blocks (K fragments shared) ----
        float sac0[8][4], sac1[8][4];
#pragma unroll
        for (int jn = 0; jn < 8; jn++)
#pragma unroll
            for (int t = 0; t < 4; t++) { sac0[jn][t] = 0.f; sac1[jn][t] = 0.f; }
#pragma unroll
        for (int k8 = 0; k8 < 8; k8++) {
            int kc = k8 * 8 + tig;
            uint32_t bfr[8][2];
#pragma unroll
            for (int jn = 0; jn < 8; jn++) {
                int krow = jn * 8 + grp;
                bfr[jn][0] = f2tf32(Kb[krow * FA_PK + kc]);
                bfr[jn][1] = f2tf32(Kb[krow * FA_PK + kc + 4]);
            }
            uint32_t af0[4], af1[4];
            af0[0] = __float_as_uint(fsm[QS_OFF + lr0 * FA_PP + kc]);
            af0[1] = __float_as_uint(fsm[QS_OFF + (lr0 + 8) * FA_PP + kc]);
            af0[2] = __float_as_uint(fsm[QS_OFF + lr0 * FA_PP + kc + 4]);
            af0[3] = __float_as_uint(fsm[QS_OFF + (lr0 + 8) * FA_PP + kc + 4]);
            af1[0] = __float_as_uint(fsm[QS_OFF + lr1 * FA_PP + kc]);
            af1[1] = __float_as_uint(fsm[QS_OFF + (lr1 + 8) * FA_PP + kc]);
            af1[2] = __float_as_uint(fsm[QS_OFF + lr1 * FA_PP + kc + 4]);
            af1[3] = __float_as_uint(fsm[QS_OFF + (lr1 + 8) * FA_PP + kc + 4]);
#pragma unroll
            for (int jn = 0; jn < 8; jn++) {
                mma_tf32(sac0[jn], af0, bfr[jn]);
                mma_tf32(sac1[jn], af1, bfr[jn]);
            }
        }

        // ---- online softmax (base-2), rb0 ----
        {
            float mx0 = -1e30f, mx1 = -1e30f;
#pragma unroll
            for (int jn = 0; jn < 8; jn++) {
                mx0 = fmaxf(mx0, fmaxf(sac0[jn][0], sac0[jn][1]));
                mx1 = fmaxf(mx1, fmaxf(sac0[jn][2], sac0[jn][3]));
            }
            mx0 = fmaxf(mx0, __shfl_xor_sync(0xffffffffu, mx0, 1));
            mx0 = fmaxf(mx0, __shfl_xor_sync(0xffffffffu, mx0, 2));
            mx1 = fmaxf(mx1, __shfl_xor_sync(0xffffffffu, mx1, 1));
            mx1 = fmaxf(mx1, __shfl_xor_sync(0xffffffffu, mx1, 2));
            float mn0 = fmaxf(m00, mx0), mn1 = fmaxf(m01, mx1);
            float al0 = exp2f(m00 - mn0), al1 = exp2f(m01 - mn1);
            float sum0 = 0.f, sum1 = 0.f;
#pragma unroll
            for (int jn = 0; jn < 8; jn++) {
                float p00 = f2tf32f(exp2f(sac0[jn][0] - mn0));
                float p01 = f2tf32f(exp2f(sac0[jn][1] - mn0));
                float p10 = f2tf32f(exp2f(sac0[jn][2] - mn1));
                float p11 = f2tf32f(exp2f(sac0[jn][3] - mn1));
                int c = jn * 8 + 2 * tig;
                *reinterpret_cast<float2*>(&fsm[PS_OFF + lr0 * FA_PP + c])       = make_float2(p00, p01);
                *reinterpret_cast<float2*>(&fsm[PS_OFF + (lr0 + 8) * FA_PP + c]) = make_float2(p10, p11);
                sum0 += p00 + p01;  sum1 += p10 + p11;
            }
            sum0 += __shfl_xor_sync(0xffffffffu, sum0, 1);
            sum0 += __shfl_xor_sync(0xffffffffu, sum0, 2);
            sum1 += __shfl_xor_sync(0xffffffffu, sum1, 1);
            sum1 += __shfl_xor_sync(0xffffffffu, sum1, 2);
            l00 = l00 * al0 + sum0;  m00 = mn0;
            l01 = l01 * al1 + sum1;  m01 = mn1;
#pragma unroll
            for (int jd = 0; jd < 8; jd++) {
                oac0[jd][0] *= al0; oac0[jd][1] *= al0;
                oac0[jd][2] *= al1; oac0[jd][3] *= al1;
            }
        }
        // ---- rb1 ----
        {
            float mx0 = -1e30f, mx1 = -1e30f;
#pragma unroll
            for (int jn = 0; jn < 8; jn++) {
                mx0 = fmaxf(mx0, fmaxf(sac1[jn][0], sac1[jn][1]));
                mx1 = fmaxf(mx1, fmaxf(sac1[jn][2], sac1[jn][3]));
            }
            mx0 = fmaxf(mx0, __shfl_xor_sync(0xffffffffu, mx0, 1));
            mx0 = fmaxf(mx0, __shfl_xor_sync(0xffffffffu, mx0, 2));
            mx1 = fmaxf(mx1, __shfl_xor_sync(0xffffffffu, mx1, 1));
            mx1 = fmaxf(mx1, __shfl_xor_sync(0xffffffffu, mx1, 2));
            float mn0 = fmaxf(m10, mx0), mn1 = fmaxf(m11, mx1);
            float al0 = exp2f(m10 - mn0), al1 = exp2f(m11 - mn1);
            float sum0 = 0.f, sum1 = 0.f;
#pragma unroll
            for (int jn = 0; jn < 8; jn++) {
                float p00 = f2tf32f(exp2f(sac1[jn][0] - mn0));
                float p01 = f2tf32f(exp2f(sac1[jn][1] - mn0));
                float p10 = f2tf32f(exp2f(sac1[jn][2] - mn1));
                float p11 = f2tf32f(exp2f(sac1[jn][3] - mn1));
                int c = jn * 8 + 2 * tig;
                *reinterpret_cast<float2*>(&fsm[PS_OFF + lr1 * FA_PP + c])       = make_float2(p00, p01);
                *reinterpret_cast<float2*>(&fsm[PS_OFF + (lr1 + 8) * FA_PP + c]) = make_float2(p10, p11);
                sum0 += p00 + p01;  sum1 += p10 + p11;
            }
            sum0 += __shfl_xor_sync(0xffffffffu, sum0, 1);
            sum0 += __shfl_xor_sync(0xffffffffu, sum0, 2);
            sum1 += __shfl_xor_sync(0xffffffffu, sum1, 1);
            sum1 += __shfl_xor_sync(0xffffffffu, sum1, 2);
            l10 = l10 * al0 + sum0;  m10 = mn0;
            l11 = l11 * al1 + sum1;  m11 = mn1;
#pragma unroll
            for (int jd = 0; jd < 8; jd++) {
                oac1[jd][0] *= al0; oac1[jd][1] *= al0;
                oac1[jd][2] *= al1; oac1[jd][3] *= al1;
            }
        }
        __syncwarp();

        // ---- O += P V (V fragments shared across row blocks) ----
#pragma unroll
        for (int k8 = 0; k8 < 8; k8++) {
            int kc = k8 * 8 + tig;
            uint32_t bfr[8][2];
#pragma unroll
            for (int jd = 0; jd < 8; jd++) {
                int dcol = jd * 8 + grp;
                bfr[jd][0] = f2tf32(Vb[(k8 * 8 + tig) * FA_PV + dcol]);
                bfr[jd][1] = f2tf32(Vb[(k8 * 8 + tig + 4) * FA_PV + dcol]);
            }
            uint32_t af0[4], af1[4];
            af0[0] = __float_as_uint(fsm[PS_OFF + lr0 * FA_PP + kc]);
            af0[1] = __float_as_uint(fsm[PS_OFF + (lr0 + 8) * FA_PP + kc]);
            af0[2] = __float_as_uint(fsm[PS_OFF + lr0 * FA_PP + kc + 4]);
            af0[3] = __float_as_uint(fsm[PS_OFF + (lr0 + 8) * FA_PP + kc + 4]);
            af1[0] = __float_as_uint(fsm[PS_OFF + lr1 * FA_PP + kc]);
            af1[1] = __float_as_uint(fsm[PS_OFF + (lr1 + 8) * FA_PP + kc]);
            af1[2] = __float_as_uint(fsm[PS_OFF + lr1 * FA_PP + kc + 4]);
            af1[3] = __float_as_uint(fsm[PS_OFF + (lr1 + 8) * FA_PP + kc + 4]);
#pragma unroll
            for (int jd = 0; jd < 8; jd++) {
                mma_tf32(oac0[jd], af0, bfr[jd]);
                mma_tf32(oac1[jd], af1, bfr[jd]);
            }
        }

        // ---- prefetch it+2 into buffer `buf` ----
        __syncthreads();
        if (it < NKV - 1) {
            if (it + 2 < NKV) {
                int kv0 = (it + 2) << 6;
#pragma unroll
                for (int i = 0; i < 4; i++) {
                    int e = tid + (i << 8);
                    int r = e >> 4, c4 = (e & 15) << 2;
                    cp16(usm + (KS_OFF + buf * KS_STRIDE + r * FA_PK + c4) * 4,
                         kg + (size_t)(kv0 + r) * 1024 + c4);
                    cp16(usm + (VS_OFF + buf * VS_STRIDE + r * FA_PV + c4) * 4,
                         vg + (size_t)(kv0 + r) * 1024 + c4);
                }
            }
            cp_commit();
            cp_wait<1>();
            __syncthreads();
        }
    }

    // ---- epilogue ----
    {
        float inv0 = 1.f / l00, inv1 = 1.f / l01;
        float* og  = o + (((size_t)(b * Sq + q0 + lr0) * Hh + h) << 6);
        float* og8 = og + (size_t)8 * 1024;
#pragma unroll
        for (int jd = 0; jd < 8; jd++) {
            int c = jd * 8 + 2 * tig;
            *reinterpret_cast<float2*>(og + c)  = make_float2(oac0[jd][0] * inv0, oac0[jd][1] * inv0);
            *reinterpret_cast<float2*>(og8 + c) = make_float2(oac0[jd][2] * inv1, oac0[jd][3] * inv1);
        }
    }
    {
        float inv0 = 1.f / l10, inv1 = 1.f / l11;
        float* og  = o + (((size_t)(b * Sq + q0 + lr1) * Hh + h) << 6);
        float* og8 = og + (size_t)8 * 1024;
#pragma unroll
        for (int jd = 0; jd < 8; jd++) {
            int c = jd * 8 + 2 * tig;
            *reinterpret_cast<float2*>(og + c)  = make_float2(oac1[jd][0] * inv0, oac1[jd][1] * inv0);
            *reinterpret_cast<float2*>(og8 + c) = make_float2(oac1[jd][2] * inv1, oac1[jd][3] * inv1);
        }
    }
}

// ========= warp-per-token: LN1 + quantum FFN + LN2, no block syncs =========
// statevector idx i (8 bits, MSB=wire0): j = i>>5 (3 bits, regs), lane = i&31.
__global__ __launch_bounds__(256) void ln_quantum(const float* __restrict__ x,
                                                  const float* __restrict__ proj,
                                                  const float* __restrict__ g1,
                                                  const float* __restrict__ b1,
                                                  const float* __restrict__ Win,
                                                  const float* __restrict__ b_in,
                                                  const float* __restrict__ Wout,
                                                  const float* __restrict__ b_out,
                                                  const float* __restrict__ ry,
                                                  const float* __restrict__ g2,
                                                  const float* __restrict__ b2,
                                                  float* __restrict__ out)
{
    const int tid  = threadIdx.x;
    const int wid  = tid >> 5;
    const int lane = tid & 31;
    const int row  = blockIdx.x * 8 + wid;

    const float4* px4 = reinterpret_cast<const float4*>(x    + (size_t)row * Dm);
    const float4* pp4 = reinterpret_cast<const float4*>(proj + (size_t)row * Dm);
    const float4* g14 = reinterpret_cast<const float4*>(g1);
    const float4* b14 = reinterpret_cast<const float4*>(b1);

    // ---- LN1: y = x + proj -> xv = LN(y) ----
    float xv[32];
    float sum = 0.f, sq = 0.f;
#pragma unroll
    for (int kk = 0; kk < 8; kk++) {
        float4 a = px4[lane + 32 * kk];
        float4 bb = pp4[lane + 32 * kk];
        float t0 = a.x + bb.x, t1 = a.y + bb.y, t2 = a.z + bb.z, t3 = a.w + bb.w;
        xv[4 * kk + 0] = t0; xv[4 * kk + 1] = t1; xv[4 * kk + 2] = t2; xv[4 * kk + 3] = t3;
        sum += t0 + t1 + t2 + t3;
        sq = fmaf(t0, t0, sq); sq = fmaf(t1, t1, sq);
        sq = fmaf(t2, t2, sq); sq = fmaf(t3, t3, sq);
    }
#pragma unroll
    for (int off = 16; off; off >>= 1) {
        sum += __shfl_xor_sync(0xffffffffu, sum, off);
        sq  += __shfl_xor_sync(0xffffffffu, sq, off);
    }
    {
        float mean = sum * (1.f / 1024.f);
        float var  = sq * (1.f / 1024.f) - mean * mean;
        float rstd = rsqrtf(var + EPSf);
#pragma unroll
        for (int kk = 0; kk < 8; kk++) {
            float4 gg = g14[lane + 32 * kk];
            float4 bbv = b14[lane + 32 * kk];
            xv[4 * kk + 0] = (xv[4 * kk + 0] - mean) * rstd * gg.x + bbv.x;
            xv[4 * kk + 1] = (xv[4 * kk + 1] - mean) * rstd * gg.y + bbv.y;
            xv[4 * kk + 2] = (xv[4 * kk + 2] - mean) * rstd * gg.z + bbv.z;
            xv[4 * kk + 3] = (xv[4 * kk + 3] - mean) * rstd * gg.w + bbv.w;
        }
    }

    // ---- angles: ang[q] = 0.5 * (xv . Win[q] + b_in[q]) ----
    const float4* Win4 = reinterpret_cast<const float4*>(Win);
    float ang[8];
#pragma unroll
    for (int qq = 0; qq < 8; qq++) {
        float acc = 0.f;
#pragma unroll
        for (int kk = 0; kk < 8; kk++) {
            float4 w = Win4[qq * 256 + lane + 32 * kk];
            acc = fmaf(xv[4 * kk + 0], w.x, acc);
            acc = fmaf(xv[4 * kk + 1], w.y, acc);
            acc = fmaf(xv[4 * kk + 2], w.z, acc);
            acc = fmaf(xv[4 * kk + 3], w.w, acc);
        }
#pragma unroll
        for (int off = 16; off; off >>= 1)
            acc += __shfl_xor_sync(0xffffffffu, acc, off);
        ang[qq] = (acc + b_in[qq]) * 0.5f;
    }

    // ---- statevector: 8 complex amps per lane ----
    float re[8], im[8];
#pragma unroll
    for (int j = 0; j < 8; j++) { re[j] = 0.f; im[j] = 0.f; }
    if (lane == 0) re[0] = 1.f;

    // RX gates: wires 0..2 -> register permute (j^4, j^2, j^1); wires 3..7 -> shfl
#pragma unroll
    for (int w = 0; w < 3; w++) {
        int mj = 4 >> w;
        float sn, cs; __sincosf(ang[w], &sn, &cs);
        float nre[8], nim[8];
#pragma unroll
        for (int j = 0; j < 8; j++) {
            int pj = j ^ mj;
            nre[j] = fmaf(cs, re[j],  sn * im[pj]);
            nim[j] = fmaf(cs, im[j], -sn * re[pj]);
        }
#pragma unroll
        for (int j = 0; j < 8; j++) { re[j] = nre[j]; im[j] = nim[j]; }
    }
#pragma unroll
    for (int w = 3; w < 8; w++) {
        int m = 1 << (7 - w);
        float sn, cs; __sincosf(ang[w], &sn, &cs);
#pragma unroll
        for (int j = 0; j < 8; j++) {
            float pre = __shfl_xor_sync(0xffffffffu, re[j], m);
            float pim = __shfl_xor_sync(0xffffffffu, im[j], m);
            float nr = fmaf(cs, re[j],  sn * pim);
            float ni = fmaf(cs, im[j], -sn * pre);
            re[j] = nr; im[j] = ni;
        }
    }
    // RY gates: new = c*a + sg*a_partner, sg = (i&m)? s : -s
#pragma unroll
    for (int w = 0; w < 3; w++) {
        int mj = 4 >> w;
        float sn, cs; __sincosf(ry[w] * 0.5f, &sn, &cs);
        float nre[8], nim[8];
#pragma unroll
        for (int j = 0; j < 8; j++) {
            int pj = j ^ mj;
            float sg = (j & mj) ? sn : -sn;
            nre[j] = fmaf(cs, re[j], sg * re[pj]);
            nim[j] = fmaf(cs, im[j], sg * im[pj]);
        }
#pragma unroll
        for (int j = 0; j < 8; j++) { re[j] = nre[j]; im[j] = nim[j]; }
    }
#pragma unroll
    for (int w = 3; w < 8; w++) {
        int m = 1 << (7 - w);
        float sn, cs; __sincosf(ry[w] * 0.5f, &sn, &cs);
        float sg = (lane & m) ? sn : -sn;
#pragma unroll
        for (int j = 0; j < 8; j++) {
            float pre = __shfl_xor_sync(0xffffffffu, re[j], m);
            float pim = __shfl_xor_sync(0xffffffffu, im[j], m);
            re[j] = fmaf(cs, re[j], sg * pre);
            im[j] = fmaf(cs, im[j], sg * pim);
        }
    }

    // ---- CNOT chain permutation: src = i ^ ((i>>1) & 127) ----
    // src_j = j ^ ((j>>1)&3) (static), src_lane = lane ^ ((lane>>1)&15) ^ ((j&1)<<4)
    float p[8];
    {
        int sl0 = lane ^ ((lane >> 1) & 15);     // j even
        int sl1 = sl0 ^ 16;                      // j odd
        float nre[8], nim[8];
#pragma unroll
        for (int j = 0; j < 8; j++) {
            int sj = j ^ ((j >> 1) & 3);
            int sl = (j & 1) ? sl1 : sl0;
            float rr, ii;
            switch (sj) {
                case 0: rr = __shfl_sync(0xffffffffu, re[0], sl); ii = __shfl_sync(0xffffffffu, im[0], sl); break;
                case 1: rr = __shfl_sync(0xffffffffu, re[1], sl); ii = __shfl_sync(0xffffffffu, im[1], sl); break;
                case 2: rr = __shfl_sync(0xffffffffu, re[2], sl); ii = __shfl_sync(0xffffffffu, im[2], sl); break;
                case 3: rr = __shfl_sync(0xffffffffu, re[3], sl); ii = __shfl_sync(0xffffffffu, im[3], sl); break;
                case 4: rr = __shfl_sync(0xffffffffu, re[4], sl); ii = __shfl_sync(0xffffffffu, im[4], sl); break;
                case 5: rr = __shfl_sync(0xffffffffu, re[5], sl); ii = __shfl_sync(0xffffffffu, im[5], sl); break;
                case 6: rr = __shfl_sync(0xffffffffu, re[6], sl); ii = __shfl_sync(0xffffffffu, im[6], sl); break;
                default: rr = __shfl_sync(0xffffffffu, re[7], sl); ii = __shfl_sync(0xffffffffu, im[7], sl); break;
            }
            nre[j] = rr; nim[j] = ii;
        }
#pragma unroll
        for (int j = 0; j < 8; j++) p[j] = nre[j] * nre[j] + nim[j] * nim[j];
    }

    // ---- expZ ----
    float e[8];
    {
        float ptot = 0.f;
#pragma unroll
        for (int j = 0; j < 8; j++) ptot += p[j];
        float e0 = 0.f, e1 = 0.f, e2 = 0.f;
#pragma unroll
        for (int j = 0; j < 8; j++) {
            e0 += (j & 4) ? -p[j] : p[j];
            e1 += (j & 2) ? -p[j] : p[j];
            e2 += (j & 1) ? -p[j] : p[j];
        }
        e[0] = e0; e[1] = e1; e[2] = e2;
        e[3] = (lane & 16) ? -ptot : ptot;
        e[4] = (lane & 8)  ? -ptot : ptot;
        e[5] = (lane & 4)  ? -ptot : ptot;
        e[6] = (lane & 2)  ? -ptot : ptot;
        e[7] = (lane & 1)  ? -ptot : ptot;
#pragma unroll
        for (int w = 0; w < 8; w++) {
#pragma unroll
            for (int off = 16; off; off >>= 1)
                e[w] += __shfl_xor_sync(0xffffffffu, e[w], off);
        }
    }

    // ---- ffn: y = xv + relu(e . Wout[d] + b_out[d]); LN2; store ----
    const float4* bo4 = reinterpret_cast<const float4*>(b_out);
    sum = 0.f; sq = 0.f;
#pragma unroll
    for (int kk = 0; kk < 8; kk++) {
        int c4i = lane + 32 * kk;            // float4 index; col d0 = 4*c4i
        float4 bo = bo4[c4i];
        float accd[4] = {bo.x, bo.y, bo.z, bo.w};
#pragma unroll
        for (int dd = 0; dd < 4; dd++) {
            const float4* wrow = reinterpret_cast<const float4*>(Wout + (size_t)(4 * c4i + dd) * 8);
            float4 w0 = wrow[0], w1 = wrow[1];
            float acc = accd[dd];
            acc = fmaf(e[0], w0.x, acc); acc = fmaf(e[1], w0.y, acc);
            acc = fmaf(e[2], w0.z, acc); acc = fmaf(e[3], w0.w, acc);
            acc = fmaf(e[4], w1.x, acc); acc = fmaf(e[5], w1.y, acc);
            acc = fmaf(e[6], w1.z, acc); acc = fmaf(e[7], w1.w, acc);
            acc = fmaxf(acc, 0.f);
            float yv = xv[4 * kk + dd] + acc;
            xv[4 * kk + dd] = yv;
            sum += yv; sq = fmaf(yv, yv, sq);
        }
    }
#pragma unroll
    for (int off = 16; off; off >>= 1) {
        sum += __shfl_xor_sync(0xffffffffu, sum, off);
        sq  += __shfl_xor_sync(0xffffffffu, sq, off);
    }
    {
        float mean = sum * (1.f / 1024.f);
        float var  = sq * (1.f / 1024.f) - mean * mean;
        float rstd = rsqrtf(var + EPSf);
        const float4* g24 = reinterpret_cast<const float4*>(g2);
        const float4* b24 = reinterpret_cast<const float4*>(b2);
        float4* out4 = reinterpret_cast<float4*>(out + (size_t)row * Dm);
#pragma unroll
        for (int kk = 0; kk < 8; kk++) {
            float4 gg = g24[lane + 32 * kk];
            float4 bbv = b24[lane + 32 * kk];
            float4 ov;
            ov.x = (xv[4 * kk + 0] - mean) * rstd * gg.x + bbv.x;
            ov.y = (xv[4 * kk + 1] - mean) * rstd * gg.y + bbv.y;
            ov.z = (xv[4 * kk + 2] - mean) * rstd * gg.z + bbv.z;
            ov.w = (xv[4 * kk + 3] - mean) * rstd * gg.w + bbv.w;
            out4[lane + 32 * kk] = ov;
        }
    }
}

// ---------------- launch ----------------
extern "C" void kernel_launch(void* const* d_in, const int* in_sizes, int n_in,
                              void* d_out, int out_size)
{
    const float* x     = (const float*)d_in[0];
    const float* Wq    = (const float*)d_in[1];
    const float* Wk    = (const float*)d_in[2];
    const float* Wv    = (const float*)d_in[3];
    const float* Wo    = (const float*)d_in[4];
    const float* g1    = (const float*)d_in[5];
    const float* b1    = (const float*)d_in[6];
    const float* g2    = (const float*)d_in[7];
    const float* b2    = (const float*)d_in[8];
    const float* Win   = (const float*)d_in[9];
    const float* b_in  = (const float*)d_in[10];
    const float* Wout  = (const float*)d_in[11];
    const float* b_out = (const float*)d_in[12];
    const float* ry    = (const float*)d_in[13];
    float* out = (float*)d_out;

    float *q, *k, *v, *o, *proj;
    cudaGetSymbolAddress((void**)&q,    g_q);
    cudaGetSymbolAddress((void**)&k,    g_k);
    cudaGetSymbolAddress((void**)&v,    g_v);
    cudaGetSymbolAddress((void**)&o,    g_o);
    cudaGetSymbolAddress((void**)&proj, g_proj);

    cudaFuncSetAttribute(gemm_mma,  cudaFuncAttributeMaxDynamicSharedMemorySize, GSMEM);
    cudaFuncSetAttribute(gemm_qkv,  cudaFuncAttributeMaxDynamicSharedMemorySize, GSMEM);
    cudaFuncSetAttribute(flash_mma, cudaFuncAttributeMaxDynamicSharedMemorySize, FA_SMEM);

    gemm_qkv<<<dim3(Dm / BN, Mtot / BM, 3), 256, GSMEM>>>(x, Wq, Wk, Wv, q, k, v);
    flash_mma<<<dim3(Sq / 256, Hh, Bsz), 256, FA_SMEM>>>(q, k, v, o);
    gemm_mma<<<dim3(Dm / BN, Mtot / BM), 256, GSMEM>>>(o, Wo, proj);
    ln_quantum<<<Mtot / 8, 256>>>(x, proj, g1, b1, Win, b_in, Wout, b_out, ry, g2, b2, out);
}

// round 8
// speedup vs baseline: 1.4190x; 1.0600x over previous
#include <cuda_runtime.h>
#include <math.h>
#include <cstdint>

#define Bsz   2
#define Sq    2048
#define Dm    1024
#define Hh    16
#define Mtot  4096
#define DIMq  256
#define EPSf  1e-5f
#define LOG2E 1.44269504088896f

// ---------------- scratch ----------------
__device__ float g_q[Mtot * Dm];
__device__ float g_k[Mtot * Dm];
__device__ float g_v[Mtot * Dm];
__device__ float g_o[Mtot * Dm];
__device__ float g_proj[Mtot * Dm];

// ======================= helpers =======================
__device__ __forceinline__ uint32_t smem_to_u32(const void* p) {
    uint32_t a;
    asm("{ .reg .u64 t; cvta.to.shared.u64 t, %1; cvt.u32.u64 %0, t; }" : "=r"(a) : "l"(p));
    return a;
}
__device__ __forceinline__ void cp16(uint32_t sm, const void* g) {
    asm volatile("cp.async.cg.shared.global [%0], [%1], 16;" :: "r"(sm), "l"(g));
}
__device__ __forceinline__ void cp_commit() {
    asm volatile("cp.async.commit_group;");
}
template <int N>
__device__ __forceinline__ void cp_wait() {
    asm volatile("cp.async.wait_group %0;" :: "n"(N));
}
__device__ __forceinline__ uint32_t f2tf32(float x) {
    uint32_t r;
    asm("cvt.rna.tf32.f32 %0, %1;" : "=r"(r) : "f"(x));
    return r;
}
__device__ __forceinline__ float f2tf32f(float x) { return __uint_as_float(f2tf32(x)); }
__device__ __forceinline__ uint32_t f2bf2(float lo, float hi) {
    uint32_t r;
    asm("cvt.rn.bf16x2.f32 %0, %1, %2;" : "=r"(r) : "f"(hi), "f"(lo));
    return r;
}
__device__ __forceinline__ void mma_tf32(float c[4], const uint32_t a[4], const uint32_t b[2]) {
    asm volatile(
        "mma.sync.aligned.m16n8k8.row.col.f32.tf32.tf32.f32 "
        "{%0,%1,%2,%3}, {%4,%5,%6,%7}, {%8,%9}, {%0,%1,%2,%3};"
        : "+f"(c[0]), "+f"(c[1]), "+f"(c[2]), "+f"(c[3])
        : "r"(a[0]), "r"(a[1]), "r"(a[2]), "r"(a[3]), "r"(b[0]), "r"(b[1]));
}
__device__ __forceinline__ void mma_bf16(float c[4], const uint32_t a[4], const uint32_t b[2]) {
    asm volatile(
        "mma.sync.aligned.m16n8k16.row.col.f32.bf16.bf16.f32 "
        "{%0,%1,%2,%3}, {%4,%5,%6,%7}, {%8,%9}, {%0,%1,%2,%3};"
        : "+f"(c[0]), "+f"(c[1]), "+f"(c[2]), "+f"(c[3])
        : "r"(a[0]), "r"(a[1]), "r"(a[2]), "r"(a[3]), "r"(b[0]), "r"(b[1]));
}

// ============ bf16 mma.sync GEMM: C[M,1024] = A[M,1024] * W[1024,1024]^T =====
#define BM 128
#define BN 256
#define BK 32
#define LDP 36
#define A_STAGE_B (BM * LDP * 4)
#define B_STAGE_B (BN * LDP * 4)
#define GSMEM (3 * (A_STAGE_B + B_STAGE_B))
#define NKT (Dm / BK)

__device__ __forceinline__ void gemm_body(const float* __restrict__ A,
                                          const float* __restrict__ W,
                                          float* __restrict__ C,
                                          char* gsm)
{
    const uint32_t usm = smem_to_u32(gsm);
    const uint32_t usmA = usm;
    const uint32_t usmB = usm + 3 * A_STAGE_B;

    const int tid  = threadIdx.x;
    const int wid  = tid >> 5;
    const int lane = tid & 31;
    const int grp  = lane >> 2;
    const int tig  = lane & 3;
    const int wm   = wid >> 2;
    const int wn   = wid & 3;

    const int aRow0 = blockIdx.y * BM;
    const int bRow0 = blockIdx.x * BN;

    int aSm[4], bSm[8];
    int aGm[4], bGm[8];
#pragma unroll
    for (int i = 0; i < 4; i++) {
        int e = tid + (i << 8);
        int r = e >> 3, c4 = (e & 7) << 2;
        aSm[i] = (r * LDP + c4) * 4;
        aGm[i] = r * Dm + c4;
    }
#pragma unroll
    for (int i = 0; i < 8; i++) {
        int e = tid + (i << 8);
        int r = e >> 3, c4 = (e & 7) << 2;
        bSm[i] = (r * LDP + c4) * 4;
        bGm[i] = r * Dm + c4;
    }
    const float* gA = A + (size_t)aRow0 * Dm;
    const float* gB = W + (size_t)bRow0 * Dm;

    float acc[4][8][4];
#pragma unroll
    for (int im = 0; im < 4; im++)
#pragma unroll
        for (int jn = 0; jn < 8; jn++)
#pragma unroll
            for (int t = 0; t < 4; t++) acc[im][jn][t] = 0.f;

#pragma unroll
    for (int p = 0; p < 2; p++) {
        uint32_t sa = usmA + p * A_STAGE_B;
        uint32_t sb = usmB + p * B_STAGE_B;
        const float* ka = gA + p * BK;
        const float* kb = gB + p * BK;
#pragma unroll
        for (int i = 0; i < 4; i++) cp16(sa + aSm[i], ka + aGm[i]);
#pragma unroll
        for (int i = 0; i < 8; i++) cp16(sb + bSm[i], kb + bGm[i]);
        cp_commit();
    }

    for (int kt = 0; kt < NKT; kt++) {
        cp_wait<1>();
        __syncthreads();

        if (kt + 2 < NKT) {
            int s = (kt + 2) % 3;
            uint32_t sa = usmA + s * A_STAGE_B;
            uint32_t sb = usmB + s * B_STAGE_B;
            const float* ka = gA + (kt + 2) * BK;
            const float* kb = gB + (kt + 2) * BK;
#pragma unroll
            for (int i = 0; i < 4; i++) cp16(sa + aSm[i], ka + aGm[i]);
#pragma unroll
            for (int i = 0; i < 8; i++) cp16(sb + bSm[i], kb + bGm[i]);
        }
        cp_commit();

        const float* As = (const float*)(gsm + (kt % 3) * A_STAGE_B);
        const float* Bs = (const float*)(gsm + 3 * A_STAGE_B + (kt % 3) * B_STAGE_B);

#pragma unroll
        for (int k16 = 0; k16 < 2; k16++) {
            const int kb = k16 * 16 + 2 * tig;
            uint32_t afr[4][4], bfr[8][2];
#pragma unroll
            for (int im = 0; im < 4; im++) {
                int row = wm * 64 + im * 16 + grp;
                float2 a00 = *reinterpret_cast<const float2*>(As + row * LDP + kb);
                float2 a80 = *reinterpret_cast<const float2*>(As + (row + 8) * LDP + kb);
                float2 a08 = *reinterpret_cast<const float2*>(As + row * LDP + kb + 8);
                float2 a88 = *reinterpret_cast<const float2*>(As + (row + 8) * LDP + kb + 8);
                afr[im][0] = f2bf2(a00.x, a00.y);
                afr[im][1] = f2bf2(a80.x, a80.y);
                afr[im][2] = f2bf2(a08.x, a08.y);
                afr[im][3] = f2bf2(a88.x, a88.y);
            }
#pragma unroll
            for (int jn = 0; jn < 8; jn++) {
                int brow = wn * 64 + jn * 8 + grp;
                float2 b0 = *reinterpret_cast<const float2*>(Bs + brow * LDP + kb);
                float2 b8 = *reinterpret_cast<const float2*>(Bs + brow * LDP + kb + 8);
                bfr[jn][0] = f2bf2(b0.x, b0.y);
                bfr[jn][1] = f2bf2(b8.x, b8.y);
            }
#pragma unroll
            for (int im = 0; im < 4; im++)
#pragma unroll
                for (int jn = 0; jn < 8; jn++)
                    mma_bf16(acc[im][jn], afr[im], bfr[jn]);
        }
        __syncthreads();
    }

    const int rowBase = aRow0 + wm * 64;
    const int colBase = bRow0 + wn * 64;
#pragma unroll
    for (int im = 0; im < 4; im++) {
        int r0 = rowBase + im * 16 + grp;
#pragma unroll
        for (int jn = 0; jn < 8; jn++) {
            int col = colBase + jn * 8 + 2 * tig;
            float2 v01 = make_float2(acc[im][jn][0], acc[im][jn][1]);
            float2 v23 = make_float2(acc[im][jn][2], acc[im][jn][3]);
            *reinterpret_cast<float2*>(C + (size_t)r0 * Dm + col) = v01;
            *reinterpret_cast<float2*>(C + (size_t)(r0 + 8) * Dm + col) = v23;
        }
    }
}

__global__ __launch_bounds__(256, 1) void gemm_mma(const float* __restrict__ A,
                                                   const float* __restrict__ W,
                                                   float* __restrict__ C)
{
    extern __shared__ __align__(16) char gsm[];
    gemm_body(A, W, C, gsm);
}

__global__ __launch_bounds__(256, 1) void gemm_qkv(const float* __restrict__ A,
                                                   const float* __restrict__ W0,
                                                   const float* __restrict__ W1,
                                                   const float* __restrict__ W2,
                                                   float* __restrict__ C0,
                                                   float* __restrict__ C1,
                                                   float* __restrict__ C2)
{
    extern __shared__ __align__(16) char gsm[];
    const int z = blockIdx.z;
    const float* W = (z == 0) ? W0 : (z == 1) ? W1 : W2;
    float*       C = (z == 0) ? C0 : (z == 1) ? C1 : C2;
    gemm_body(A, W, C, gsm);
}

// ============ Flash attention: 32 Q rows/warp (R7-proven, tf32) =============
#define FA_PP 68
#define FA_PK 68
#define FA_PV 72
#define QS_OFF 0
#define PS_OFF (256 * FA_PP)
#define KS_OFF (PS_OFF + 256 * FA_PP)
#define KS_STRIDE (64 * FA_PK)
#define VS_OFF (KS_OFF + 2 * KS_STRIDE)
#define VS_STRIDE (64 * FA_PV)
#define FA_SMEM ((VS_OFF + 2 * VS_STRIDE) * 4)
#define NKV (Sq / 64)

__global__ __launch_bounds__(256, 1) void flash_mma(const float* __restrict__ q,
                                                    const float* __restrict__ k,
                                                    const float* __restrict__ v,
                                                    float* __restrict__ o)
{
    extern __shared__ __align__(16) float fsm[];
    const uint32_t usm = smem_to_u32(fsm);

    const int tid  = threadIdx.x;
    const int wid  = tid >> 5;
    const int lane = tid & 31;
    const int grp  = lane >> 2;
    const int tig  = lane & 3;

    const int b  = blockIdx.z;
    const int h  = blockIdx.y;
    const int q0 = blockIdx.x << 8;

    const float* qg = q + (((size_t)(b * Sq + q0) * Hh + h) << 6);
    const float* kg = k + (((size_t)(b * Sq) * Hh + h) << 6);
    const float* vg = v + (((size_t)(b * Sq) * Hh + h) << 6);

    {
#pragma unroll
        for (int i = 0; i < 16; i++) {
            int e = tid + (i << 8);
            int r = e >> 4, c4 = (e & 15) << 2;
            cp16(usm + (QS_OFF + r * FA_PP + c4) * 4, qg + (size_t)r * 1024 + c4);
        }
#pragma unroll
        for (int i = 0; i < 4; i++) {
            int e = tid + (i << 8);
            int r = e >> 4, c4 = (e & 15) << 2;
            cp16(usm + (KS_OFF + r * FA_PK + c4) * 4, kg + (size_t)r * 1024 + c4);
            cp16(usm + (VS_OFF + r * FA_PV + c4) * 4, vg + (size_t)r * 1024 + c4);
        }
        cp_commit();
#pragma unroll
        for (int i = 0; i < 4; i++) {
            int e = tid + (i << 8);
            int r = e >> 4, c4 = (e & 15) << 2;
            cp16(usm + (KS_OFF + KS_STRIDE + r * FA_PK + c4) * 4, kg + (size_t)(64 + r) * 1024 + c4);
            cp16(usm + (VS_OFF + VS_STRIDE + r * FA_PV + c4) * 4, vg + (size_t)(64 + r) * 1024 + c4);
        }
        cp_commit();
    }
    cp_wait<1>();
    __syncthreads();

    {
        const float qs = 0.125f * LOG2E;
#pragma unroll
        for (int i = 0; i < 16; i++) {
            int e = tid + (i << 8);
            int r = e >> 4, c4 = (e & 15) << 2;
            float4* p = reinterpret_cast<float4*>(fsm + QS_OFF + r * FA_PP + c4);
            float4 vq = *p;
            vq.x = f2tf32f(vq.x * qs); vq.y = f2tf32f(vq.y * qs);
            vq.z = f2tf32f(vq.z * qs); vq.w = f2tf32f(vq.w * qs);
            *p = vq;
        }
    }
    __syncthreads();

    const int lr0 = wid * 32 + grp;
    const int lr1 = lr0 + 16;

    float m00 = -1e30f, m01 = -1e30f, m10 = -1e30f, m11 = -1e30f;
    float l00 = 0.f, l01 = 0.f, l10 = 0.f, l11 = 0.f;
    float oac0[8][4], oac1[8][4];
#pragma unroll
    for (int jd = 0; jd < 8; jd++)
#pragma unroll
        for (int t = 0; t < 4; t++) { oac0[jd][t] = 0.f; oac1[jd][t] = 0.f; }

    for (int it = 0; it < NKV; it++) {
        const int buf = it & 1;
        const float* Kb = fsm + KS_OFF + buf * KS_STRIDE;
        const float* Vb = fsm + VS_OFF + buf * VS_STRIDE;

        float sac0[8][4], sac1[8][4];
#pragma unroll
        for (int jn = 0; jn < 8; jn++)
#pragma unroll
            for (int t = 0; t < 4; t++) { sac0[jn][t] = 0.f; sac1[jn][t] = 0.f; }
#pragma unroll
        for (int k8 = 0; k8 < 8; k8++) {
            int kc = k8 * 8 + tig;
            uint32_t bfr[8][2];
#pragma unroll
            for (int jn = 0; jn < 8; jn++) {
                int krow = jn * 8 + grp;
                bfr[jn][0] = f2tf32(Kb[krow * FA_PK + kc]);
                bfr[jn][1] = f2tf32(Kb[krow * FA_PK + kc + 4]);
            }
            uint32_t af0[4], af1[4];
            af0[0] = __float_as_uint(fsm[QS_OFF + lr0 * FA_PP + kc]);
            af0[1] = __float_as_uint(fsm[QS_OFF + (lr0 + 8) * FA_PP + kc]);
            af0[2] = __float_as_uint(fsm[QS_OFF + lr0 * FA_PP + kc + 4]);
            af0[3] = __float_as_uint(fsm[QS_OFF + (lr0 + 8) * FA_PP + kc + 4]);
            af1[0] = __float_as_uint(fsm[QS_OFF + lr1 * FA_PP + kc]);
            af1[1] = __float_as_uint(fsm[QS_OFF + (lr1 + 8) * FA_PP + kc]);
            af1[2] = __float_as_uint(fsm[QS_OFF + lr1 * FA_PP + kc + 4]);
            af1[3] = __float_as_uint(fsm[QS_OFF + (lr1 + 8) * FA_PP + kc + 4]);
#pragma unroll
            for (int jn = 0; jn < 8; jn++) {
                mma_tf32(sac0[jn], af0, bfr[jn]);
                mma_tf32(sac1[jn], af1, bfr[jn]);
            }
        }

        {
            float mx0 = -1e30f, mx1 = -1e30f;
#pragma unroll
            for (int jn = 0; jn < 8; jn++) {
                mx0 = fmaxf(mx0, fmaxf(sac0[jn][0], sac0[jn][1]));
                mx1 = fmaxf(mx1, fmaxf(sac0[jn][2], sac0[jn][3]));
            }
            mx0 = fmaxf(mx0, __shfl_xor_sync(0xffffffffu, mx0, 1));
            mx0 = fmaxf(mx0, __shfl_xor_sync(0xffffffffu, mx0, 2));
            mx1 = fmaxf(mx1, __shfl_xor_sync(0xffffffffu, mx1, 1));
            mx1 = fmaxf(mx1, __shfl_xor_sync(0xffffffffu, mx1, 2));
            float mn0 = fmaxf(m00, mx0), mn1 = fmaxf(m01, mx1);
            float al0 = exp2f(m00 - mn0), al1 = exp2f(m01 - mn1);
            float sum0 = 0.f, sum1 = 0.f;
#pragma unroll
            for (int jn = 0; jn < 8; jn++) {
                float p00 = f2tf32f(exp2f(sac0[jn][0] - mn0));
                float p01 = f2tf32f(exp2f(sac0[jn][1] - mn0));
                float p10 = f2tf32f(exp2f(sac0[jn][2] - mn1));
                float p11 = f2tf32f(exp2f(sac0[jn][3] - mn1));
                int c = jn * 8 + 2 * tig;
                *reinterpret_cast<float2*>(&fsm[PS_OFF + lr0 * FA_PP + c])       = make_float2(p00, p01);
                *reinterpret_cast<float2*>(&fsm[PS_OFF + (lr0 + 8) * FA_PP + c]) = make_float2(p10, p11);
                sum0 += p00 + p01;  sum1 += p10 + p11;
            }
            sum0 += __shfl_xor_sync(0xffffffffu, sum0, 1);
            sum0 += __shfl_xor_sync(0xffffffffu, sum0, 2);
            sum1 += __shfl_xor_sync(0xffffffffu, sum1, 1);
            sum1 += __shfl_xor_sync(0xffffffffu, sum1, 2);
            l00 = l00 * al0 + sum0;  m00 = mn0;
            l01 = l01 * al1 + sum1;  m01 = mn1;
#pragma unroll
            for (int jd = 0; jd < 8; jd++) {
                oac0[jd][0] *= al0; oac0[jd][1] *= al0;
                oac0[jd][2] *= al1; oac0[jd][3] *= al1;
            }
        }
        {
            float mx0 = -1e30f, mx1 = -1e30f;
#pragma unroll
            for (int jn = 0; jn < 8; jn++) {
                mx0 = fmaxf(mx0, fmaxf(sac1[jn][0], sac1[jn][1]));
                mx1 = fmaxf(mx1, fmaxf(sac1[jn][2], sac1[jn][3]));
            }
            mx0 = fmaxf(mx0, __shfl_xor_sync(0xffffffffu, mx0, 1));
            mx0 = fmaxf(mx0, __shfl_xor_sync(0xffffffffu, mx0, 2));
            mx1 = fmaxf(mx1, __shfl_xor_sync(0xffffffffu, mx1, 1));
            mx1 = fmaxf(mx1, __shfl_xor_sync(0xffffffffu, mx1, 2));
            float mn0 = fmaxf(m10, mx0), mn1 = fmaxf(m11, mx1);
            float al0 = exp2f(m10 - mn0), al1 = exp2f(m11 - mn1);
            float sum0 = 0.f, sum1 = 0.f;
#pragma unroll
            for (int jn = 0; jn < 8; jn++) {
                float p00 = f2tf32f(exp2f(sac1[jn][0] - mn0));
                float p01 = f2tf32f(exp2f(sac1[jn][1] - mn0));
                float p10 = f2tf32f(exp2f(sac1[jn][2] - mn1));
                float p11 = f2tf32f(exp2f(sac1[jn][3] - mn1));
                int c = jn * 8 + 2 * tig;
                *reinterpret_cast<float2*>(&fsm[PS_OFF + lr1 * FA_PP + c])       = make_float2(p00, p01);
                *reinterpret_cast<float2*>(&fsm[PS_OFF + (lr1 + 8) * FA_PP + c]) = make_float2(p10, p11);
                sum0 += p00 + p01;  sum1 += p10 + p11;
            }
            sum0 += __shfl_xor_sync(0xffffffffu, sum0, 1);
            sum0 += __shfl_xor_sync(0xffffffffu, sum0, 2);
            sum1 += __shfl_xor_sync(0xffffffffu, sum1, 1);
            sum1 += __shfl_xor_sync(0xffffffffu, sum1, 2);
            l10 = l10 * al0 + sum0;  m10 = mn0;
            l11 = l11 * al1 + sum1;  m11 = mn1;
#pragma unroll
            for (int jd = 0; jd < 8; jd++) {
                oac1[jd][0] *= al0; oac1[jd][1] *= al0;
                oac1[jd][2] *= al1; oac1[jd][3] *= al1;
            }
        }
        __syncwarp();

#pragma unroll
        for (int k8 = 0; k8 < 8; k8++) {
            int kc = k8 * 8 + tig;
            uint32_t bfr[8][2];
#pragma unroll
            for (int jd = 0; jd < 8; jd++) {
                int dcol = jd * 8 + grp;
                bfr[jd][0] = f2tf32(Vb[(k8 * 8 + tig) * FA_PV + dcol]);
                bfr[jd][1] = f2tf32(Vb[(k8 * 8 + tig + 4) * FA_PV + dcol]);
            }
            uint32_t af0[4], af1[4];
            af0[0] = __float_as_uint(fsm[PS_OFF + lr0 * FA_PP + kc]);
            af0[1] = __float_as_uint(fsm[PS_OFF + (lr0 + 8) * FA_PP + kc]);
            af0[2] = __float_as_uint(fsm[PS_OFF + lr0 * FA_PP + kc + 4]);
            af0[3] = __float_as_uint(fsm[PS_OFF + (lr0 + 8) * FA_PP + kc + 4]);
            af1[0] = __float_as_uint(fsm[PS_OFF + lr1 * FA_PP + kc]);
            af1[1] = __float_as_uint(fsm[PS_OFF + (lr1 + 8) * FA_PP + kc]);
            af1[2] = __float_as_uint(fsm[PS_OFF + lr1 * FA_PP + kc + 4]);
            af1[3] = __float_as_uint(fsm[PS_OFF + (lr1 + 8) * FA_PP + kc + 4]);
#pragma unroll
            for (int jd = 0; jd < 8; jd++) {
                mma_tf32(oac0[jd], af0, bfr[jd]);
                mma_tf32(oac1[jd], af1, bfr[jd]);
            }
        }

        __syncthreads();
        if (it < NKV - 1) {
            if (it + 2 < NKV) {
                int kv0 = (it + 2) << 6;
#pragma unroll
                for (int i = 0; i < 4; i++) {
                    int e = tid + (i << 8);
                    int r = e >> 4, c4 = (e & 15) << 2;
                    cp16(usm + (KS_OFF + buf * KS_STRIDE + r * FA_PK + c4) * 4,
                         kg + (size_t)(kv0 + r) * 1024 + c4);
                    cp16(usm + (VS_OFF + buf * VS_STRIDE + r * FA_PV + c4) * 4,
                         vg + (size_t)(kv0 + r) * 1024 + c4);
                }
            }
            cp_commit();
            cp_wait<1>();
            __syncthreads();
        }
    }

    {
        float inv0 = 1.f / l00, inv1 = 1.f / l01;
        float* og  = o + (((size_t)(b * Sq + q0 + lr0) * Hh + h) << 6);
        float* og8 = og + (size_t)8 * 1024;
#pragma unroll
        for (int jd = 0; jd < 8; jd++) {
            int c = jd * 8 + 2 * tig;
            *reinterpret_cast<float2*>(og + c)  = make_float2(oac0[jd][0] * inv0, oac0[jd][1] * inv0);
            *reinterpret_cast<float2*>(og8 + c) = make_float2(oac0[jd][2] * inv1, oac0[jd][3] * inv1);
        }
    }
    {
        float inv0 = 1.f / l10, inv1 = 1.f / l11;
        float* og  = o + (((size_t)(b * Sq + q0 + lr1) * Hh + h) << 6);
        float* og8 = og + (size_t)8 * 1024;
#pragma unroll
        for (int jd = 0; jd < 8; jd++) {
            int c = jd * 8 + 2 * tig;
            *reinterpret_cast<float2*>(og + c)  = make_float2(oac1[jd][0] * inv0, oac1[jd][1] * inv0);
            *reinterpret_cast<float2*>(og8 + c) = make_float2(oac1[jd][2] * inv1, oac1[jd][3] * inv1);
        }
    }
}

// ========= fused LN1 + quantum FFN + LN2 (R6-proven block version) =========
__global__ __launch_bounds__(256) void ln_quantum(const float* __restrict__ x,
                                                  const float* __restrict__ proj,
                                                  const float* __restrict__ g1,
                                                  const float* __restrict__ b1,
                                                  const float* __restrict__ Win,
                                                  const float* __restrict__ b_in,
                                                  const float* __restrict__ Wout,
                                                  const float* __restrict__ b_out,
                                                  const float* __restrict__ ry,
                                                  const float* __restrict__ g2,
                                                  const float* __restrict__ b2,
                                                  float* __restrict__ out)
{
    const int row = blockIdx.x;
    const int tid = threadIdx.x;
    const int lane = tid & 31, wid = tid >> 5;
    const float* px = x + (size_t)row * Dm;
    const float* pp = proj + (size_t)row * Dm;

    __shared__ float redw[64];
    __shared__ float angs[8];
    __shared__ float ezs[8];
    __shared__ float2 st[2][DIMq];

    float xv[4];
    {
        float yv[4], sum = 0.f, sq = 0.f;
#pragma unroll
        for (int j = 0; j < 4; j++) {
            int d = tid + (j << 8);
            float t = px[d] + pp[d];
            yv[j] = t; sum += t; sq = fmaf(t, t, sq);
        }
#pragma unroll
        for (int off = 16; off; off >>= 1) {
            sum += __shfl_xor_sync(0xffffffffu, sum, off);
            sq  += __shfl_xor_sync(0xffffffffu, sq, off);
        }
        if (lane == 0) { redw[wid] = sum; redw[8 + wid] = sq; }
        __syncthreads();
        float tsum = 0.f, tsq = 0.f;
#pragma unroll
        for (int w = 0; w < 8; w++) { tsum += redw[w]; tsq += redw[8 + w]; }
        float mean = tsum * (1.f / 1024.f);
        float var  = tsq * (1.f / 1024.f) - mean * mean;
        float rstd = rsqrtf(var + EPSf);
#pragma unroll
        for (int j = 0; j < 4; j++) {
            int d = tid + (j << 8);
            xv[j] = (yv[j] - mean) * rstd * g1[d] + b1[d];
        }
        __syncthreads();
    }

    float accq[8] = {0, 0, 0, 0, 0, 0, 0, 0};
#pragma unroll
    for (int j = 0; j < 4; j++) {
        int d = tid + (j << 8);
#pragma unroll
        for (int qq = 0; qq < 8; qq++)
            accq[qq] = fmaf(xv[j], Win[qq * Dm + d], accq[qq]);
    }
#pragma unroll
    for (int qq = 0; qq < 8; qq++) {
        float vsum = accq[qq];
#pragma unroll
        for (int off = 16; off; off >>= 1)
            vsum += __shfl_xor_sync(0xffffffffu, vsum, off);
        if (lane == 0) redw[wid * 8 + qq] = vsum;
    }
    __syncthreads();
    if (tid < 8) {
        float s = b_in[tid];
#pragma unroll
        for (int w = 0; w < 8; w++) s += redw[w * 8 + tid];
        angs[tid] = s * 0.5f;
    }
    st[0][tid] = make_float2(tid == 0 ? 1.f : 0.f, 0.f);
    __syncthreads();

    int curb = 0;
#pragma unroll
    for (int w = 0; w < 8; w++) {
        int mask = 1 << (7 - w);
        float sn, cs;
        __sincosf(angs[w], &sn, &cs);
        float2 a  = st[curb][tid];
        float2 bb = st[curb][tid ^ mask];
        st[curb ^ 1][tid] = make_float2(fmaf(cs, a.x,  sn * bb.y),
                                        fmaf(cs, a.y, -sn * bb.x));
        curb ^= 1;
        __syncthreads();
    }
#pragma unroll
    for (int w = 0; w < 8; w++) {
        int mask = 1 << (7 - w);
        float sn, cs;
        __sincosf(ry[w] * 0.5f, &sn, &cs);
        float2 a  = st[curb][tid];
        float2 bb = st[curb][tid ^ mask];
        float sg = (tid & mask) ? sn : -sn;
        st[curb ^ 1][tid] = make_float2(fmaf(cs, a.x, sg * bb.x),
                                        fmaf(cs, a.y, sg * bb.y));
        curb ^= 1;
        __syncthreads();
    }
    int src = tid;
#pragma unroll
    for (int c = 6; c >= 0; c--) {
        int cmask = 1 << (7 - c);
        int tmask = cmask >> 1;
        if (src & cmask) src ^= tmask;
    }
    float2 fa = st[curb][src];
    float p = fa.x * fa.x + fa.y * fa.y;

#pragma unroll
    for (int w = 0; w < 8; w++) {
        float vsum = ((tid >> (7 - w)) & 1) ? -p : p;
#pragma unroll
        for (int off = 16; off; off >>= 1)
            vsum += __shfl_xor_sync(0xffffffffu, vsum, off);
        if (lane == 0) redw[wid * 8 + w] = vsum;
    }
    __syncthreads();
    if (tid < 8) {
        float s = 0.f;
#pragma unroll
        for (int w = 0; w < 8; w++) s += redw[w * 8 + tid];
        ezs[tid] = s;
    }
    __syncthreads();
    float e[8];
#pragma unroll
    for (int qq = 0; qq < 8; qq++) e[qq] = ezs[qq];

    float y[4], sum = 0.f, sq = 0.f;
#pragma unroll
    for (int j = 0; j < 4; j++) {
        int d = tid + (j << 8);
        const float4* wrow = reinterpret_cast<const float4*>(Wout + (size_t)d * 8);
        float4 w0 = wrow[0], w1 = wrow[1];
        float acc = b_out[d];
        acc = fmaf(e[0], w0.x, acc); acc = fmaf(e[1], w0.y, acc);
        acc = fmaf(e[2], w0.z, acc); acc = fmaf(e[3], w0.w, acc);
        acc = fmaf(e[4], w1.x, acc); acc = fmaf(e[5], w1.y, acc);
        acc = fmaf(e[6], w1.z, acc); acc = fmaf(e[7], w1.w, acc);
        acc = fmaxf(acc, 0.f);
        float yv = xv[j] + acc;
        y[j] = yv; sum += yv; sq = fmaf(yv, yv, sq);
    }
    __syncthreads();
#pragma unroll
    for (int off = 16; off; off >>= 1) {
        sum += __shfl_xor_sync(0xffffffffu, sum, off);
        sq  += __shfl_xor_sync(0xffffffffu, sq, off);
    }
    if (lane == 0) { redw[wid] = sum; redw[8 + wid] = sq; }
    __syncthreads();
    float tsum = 0.f, tsq = 0.f;
#pragma unroll
    for (int w = 0; w < 8; w++) { tsum += redw[w]; tsq += redw[8 + w]; }
    float mean = tsum * (1.f / 1024.f);
    float var  = tsq * (1.f / 1024.f) - mean * mean;
    float rstd = rsqrtf(var + EPSf);
#pragma unroll
    for (int j = 0; j < 4; j++) {
        int d = tid + (j << 8);
        out[(size_t)row * Dm + d] = (y[j] - mean) * rstd * g2[d] + b2[d];
    }
}

// ---------------- launch ----------------
extern "C" void kernel_launch(void* const* d_in, const int* in_sizes, int n_in,
                              void* d_out, int out_size)
{
    const float* x     = (const float*)d_in[0];
    const float* Wq    = (const float*)d_in[1];
    const float* Wk    = (const float*)d_in[2];
    const float* Wv    = (const float*)d_in[3];
    const float* Wo    = (const float*)d_in[4];
    const float* g1    = (const float*)d_in[5];
    const float* b1    = (const float*)d_in[6];
    const float* g2    = (const float*)d_in[7];
    const float* b2    = (const float*)d_in[8];
    const float* Win   = (const float*)d_in[9];
    const float* b_in  = (const float*)d_in[10];
    const float* Wout  = (const float*)d_in[11];
    const float* b_out = (const float*)d_in[12];
    const float* ry    = (const float*)d_in[13];
    float* out = (float*)d_out;

    float *q, *k, *v, *o, *proj;
    cudaGetSymbolAddress((void**)&q,    g_q);
    cudaGetSymbolAddress((void**)&k,    g_k);
    cudaGetSymbolAddress((void**)&v,    g_v);
    cudaGetSymbolAddress((void**)&o,    g_o);
    cudaGetSymbolAddress((void**)&proj, g_proj);

    cudaFuncSetAttribute(gemm_mma,  cudaFuncAttributeMaxDynamicSharedMemorySize, GSMEM);
    cudaFuncSetAttribute(gemm_qkv,  cudaFuncAttributeMaxDynamicSharedMemorySize, GSMEM);
    cudaFuncSetAttribute(flash_mma, cudaFuncAttributeMaxDynamicSharedMemorySize, FA_SMEM);

    gemm_qkv<<<dim3(Dm / BN, Mtot / BM, 3), 256, GSMEM>>>(x, Wq, Wk, Wv, q, k, v);
    flash_mma<<<dim3(Sq / 256, Hh, Bsz), 256, FA_SMEM>>>(q, k, v, o);
    gemm_mma<<<dim3(Dm / BN, Mtot / BM), 256, GSMEM>>>(o, Wo, proj);
    ln_quantum<<<Mtot, 256>>>(x, proj, g1, b1, Win, b_in, Wout, b_out, ry, g2, b2, out);
}

// round 9
// speedup vs baseline: 1.5424x; 1.0869x over previous
#include <cuda_runtime.h>
#include <math.h>
#include <cstdint>

#define Bsz   2
#define Sq    2048
#define Dm    1024
#define Hh    16
#define Mtot  4096
#define DIMq  256
#define EPSf  1e-5f
#define LOG2E 1.44269504088896f

// ---------------- scratch ----------------
__device__ float g_q[Mtot * Dm];
__device__ float g_k[Mtot * Dm];
__device__ float g_v[Mtot * Dm];
__device__ float g_o[Mtot * Dm];
__device__ float g_proj[Mtot * Dm];

// ======================= helpers =======================
__device__ __forceinline__ uint32_t smem_to_u32(const void* p) {
    uint32_t a;
    asm("{ .reg .u64 t; cvta.to.shared.u64 t, %1; cvt.u32.u64 %0, t; }" : "=r"(a) : "l"(p));
    return a;
}
__device__ __forceinline__ void cp16(uint32_t sm, const void* g) {
    asm volatile("cp.async.cg.shared.global [%0], [%1], 16;" :: "r"(sm), "l"(g));
}
__device__ __forceinline__ void cp_commit() {
    asm volatile("cp.async.commit_group;");
}
template <int N>
__device__ __forceinline__ void cp_wait() {
    asm volatile("cp.async.wait_group %0;" :: "n"(N));
}
__device__ __forceinline__ uint32_t f2bf2(float lo, float hi) {
    uint32_t r;
    asm("cvt.rn.bf16x2.f32 %0, %1, %2;" : "=r"(r) : "f"(hi), "f"(lo));
    return r;
}
__device__ __forceinline__ void mma_bf16(float c[4], const uint32_t a[4], const uint32_t b[2]) {
    asm volatile(
        "mma.sync.aligned.m16n8k16.row.col.f32.bf16.bf16.f32 "
        "{%0,%1,%2,%3}, {%4,%5,%6,%7}, {%8,%9}, {%0,%1,%2,%3};"
        : "+f"(c[0]), "+f"(c[1]), "+f"(c[2]), "+f"(c[3])
        : "r"(a[0]), "r"(a[1]), "r"(a[2]), "r"(a[3]), "r"(b[0]), "r"(b[1]));
}

// ============ bf16 mma.sync GEMM (R8-proven) ============
#define BM 128
#define BN 256
#define BK 32
#define LDP 36
#define A_STAGE_B (BM * LDP * 4)
#define B_STAGE_B (BN * LDP * 4)
#define GSMEM (3 * (A_STAGE_B + B_STAGE_B))
#define NKT (Dm / BK)

__device__ __forceinline__ void gemm_body(const float* __restrict__ A,
                                          const float* __restrict__ W,
                                          float* __restrict__ C,
                                          char* gsm)
{
    const uint32_t usm = smem_to_u32(gsm);
    const uint32_t usmA = usm;
    const uint32_t usmB = usm + 3 * A_STAGE_B;

    const int tid  = threadIdx.x;
    const int wid  = tid >> 5;
    const int lane = tid & 31;
    const int grp  = lane >> 2;
    const int tig  = lane & 3;
    const int wm   = wid >> 2;
    const int wn   = wid & 3;

    const int aRow0 = blockIdx.y * BM;
    const int bRow0 = blockIdx.x * BN;

    int aSm[4], bSm[8];
    int aGm[4], bGm[8];
#pragma unroll
    for (int i = 0; i < 4; i++) {
        int e = tid + (i << 8);
        int r = e >> 3, c4 = (e & 7) << 2;
        aSm[i] = (r * LDP + c4) * 4;
        aGm[i] = r * Dm + c4;
    }
#pragma unroll
    for (int i = 0; i < 8; i++) {
        int e = tid + (i << 8);
        int r = e >> 3, c4 = (e & 7) << 2;
        bSm[i] = (r * LDP + c4) * 4;
        bGm[i] = r * Dm + c4;
    }
    const float* gA = A + (size_t)aRow0 * Dm;
    const float* gB = W + (size_t)bRow0 * Dm;

    float acc[4][8][4];
#pragma unroll
    for (int im = 0; im < 4; im++)
#pragma unroll
        for (int jn = 0; jn < 8; jn++)
#pragma unroll
            for (int t = 0; t < 4; t++) acc[im][jn][t] = 0.f;

#pragma unroll
    for (int p = 0; p < 2; p++) {
        uint32_t sa = usmA + p * A_STAGE_B;
        uint32_t sb = usmB + p * B_STAGE_B;
        const float* ka = gA + p * BK;
        const float* kb = gB + p * BK;
#pragma unroll
        for (int i = 0; i < 4; i++) cp16(sa + aSm[i], ka + aGm[i]);
#pragma unroll
        for (int i = 0; i < 8; i++) cp16(sb + bSm[i], kb + bGm[i]);
        cp_commit();
    }

    for (int kt = 0; kt < NKT; kt++) {
        cp_wait<1>();
        __syncthreads();

        if (kt + 2 < NKT) {
            int s = (kt + 2) % 3;
            uint32_t sa = usmA + s * A_STAGE_B;
            uint32_t sb = usmB + s * B_STAGE_B;
            const float* ka = gA + (kt + 2) * BK;
            const float* kb = gB + (kt + 2) * BK;
#pragma unroll
            for (int i = 0; i < 4; i++) cp16(sa + aSm[i], ka + aGm[i]);
#pragma unroll
            for (int i = 0; i < 8; i++) cp16(sb + bSm[i], kb + bGm[i]);
        }
        cp_commit();

        const float* As = (const float*)(gsm + (kt % 3) * A_STAGE_B);
        const float* Bs = (const float*)(gsm + 3 * A_STAGE_B + (kt % 3) * B_STAGE_B);

#pragma unroll
        for (int k16 = 0; k16 < 2; k16++) {
            const int kb = k16 * 16 + 2 * tig;
            uint32_t afr[4][4], bfr[8][2];
#pragma unroll
            for (int im = 0; im < 4; im++) {
                int row = wm * 64 + im * 16 + grp;
                float2 a00 = *reinterpret_cast<const float2*>(As + row * LDP + kb);
                float2 a80 = *reinterpret_cast<const float2*>(As + (row + 8) * LDP + kb);
                float2 a08 = *reinterpret_cast<const float2*>(As + row * LDP + kb + 8);
                float2 a88 = *reinterpret_cast<const float2*>(As + (row + 8) * LDP + kb + 8);
                afr[im][0] = f2bf2(a00.x, a00.y);
                afr[im][1] = f2bf2(a80.x, a80.y);
                afr[im][2] = f2bf2(a08.x, a08.y);
                afr[im][3] = f2bf2(a88.x, a88.y);
            }
#pragma unroll
            for (int jn = 0; jn < 8; jn++) {
                int brow = wn * 64 + jn * 8 + grp;
                float2 b0 = *reinterpret_cast<const float2*>(Bs + brow * LDP + kb);
                float2 b8 = *reinterpret_cast<const float2*>(Bs + brow * LDP + kb + 8);
                bfr[jn][0] = f2bf2(b0.x, b0.y);
                bfr[jn][1] = f2bf2(b8.x, b8.y);
            }
#pragma unroll
            for (int im = 0; im < 4; im++)
#pragma unroll
                for (int jn = 0; jn < 8; jn++)
                    mma_bf16(acc[im][jn], afr[im], bfr[jn]);
        }
        __syncthreads();
    }

    const int rowBase = aRow0 + wm * 64;
    const int colBase = bRow0 + wn * 64;
#pragma unroll
    for (int im = 0; im < 4; im++) {
        int r0 = rowBase + im * 16 + grp;
#pragma unroll
        for (int jn = 0; jn < 8; jn++) {
            int col = colBase + jn * 8 + 2 * tig;
            float2 v01 = make_float2(acc[im][jn][0], acc[im][jn][1]);
            float2 v23 = make_float2(acc[im][jn][2], acc[im][jn][3]);
            *reinterpret_cast<float2*>(C + (size_t)r0 * Dm + col) = v01;
            *reinterpret_cast<float2*>(C + (size_t)(r0 + 8) * Dm + col) = v23;
        }
    }
}

__global__ __launch_bounds__(256, 1) void gemm_mma(const float* __restrict__ A,
                                                   const float* __restrict__ W,
                                                   float* __restrict__ C)
{
    extern __shared__ __align__(16) char gsm[];
    gemm_body(A, W, C, gsm);
}

__global__ __launch_bounds__(256, 1) void gemm_qkv(const float* __restrict__ A,
                                                   const float* __restrict__ W0,
                                                   const float* __restrict__ W1,
                                                   const float* __restrict__ W2,
                                                   float* __restrict__ C0,
                                                   float* __restrict__ C1,
                                                   float* __restrict__ C2)
{
    extern __shared__ __align__(16) char gsm[];
    const int z = blockIdx.z;
    const float* W = (z == 0) ? W0 : (z == 1) ? W1 : W2;
    float*       C = (z == 0) ? C0 : (z == 1) ? C1 : C2;
    gemm_body(A, W, C, gsm);
}

// ============ Flash attention: bf16 m16n8k16, 32 Q rows/warp ================
// smem (words): Q 256x68 fp32 | Ppacked 256x36 u32 | K 2x64x68 | V 2x64x68
#define FA_PP 68
#define FA_PK 68
#define FA_PV 68
#define PPW   36
#define QS_OFF 0
#define PP_OFF (256 * FA_PP)                 // 17408
#define KS_OFF (PP_OFF + 256 * PPW)          // 26624
#define KS_STRIDE (64 * FA_PK)
#define VS_OFF (KS_OFF + 2 * KS_STRIDE)      // 35328
#define VS_STRIDE (64 * FA_PV)
#define FA_SMEM ((VS_OFF + 2 * VS_STRIDE) * 4)  // 176128 B
#define NKV (Sq / 64)

__global__ __launch_bounds__(256, 1) void flash_mma(const float* __restrict__ q,
                                                    const float* __restrict__ k,
                                                    const float* __restrict__ v,
                                                    float* __restrict__ o)
{
    extern __shared__ __align__(16) float fsm[];
    const uint32_t usm = smem_to_u32(fsm);
    uint32_t* pp = reinterpret_cast<uint32_t*>(fsm) + PP_OFF;

    const int tid  = threadIdx.x;
    const int wid  = tid >> 5;
    const int lane = tid & 31;
    const int grp  = lane >> 2;
    const int tig  = lane & 3;

    const int b  = blockIdx.z;
    const int h  = blockIdx.y;
    const int q0 = blockIdx.x << 8;

    const float* qg = q + (((size_t)(b * Sq + q0) * Hh + h) << 6);
    const float* kg = k + (((size_t)(b * Sq) * Hh + h) << 6);
    const float* vg = v + (((size_t)(b * Sq) * Hh + h) << 6);

    // ---- prologue ----
    {
#pragma unroll
        for (int i = 0; i < 16; i++) {
            int e = tid + (i << 8);
            int r = e >> 4, c4 = (e & 15) << 2;
            cp16(usm + (QS_OFF + r * FA_PP + c4) * 4, qg + (size_t)r * 1024 + c4);
        }
#pragma unroll
        for (int i = 0; i < 4; i++) {
            int e = tid + (i << 8);
            int r = e >> 4, c4 = (e & 15) << 2;
            cp16(usm + (KS_OFF + r * FA_PK + c4) * 4, kg + (size_t)r * 1024 + c4);
            cp16(usm + (VS_OFF + r * FA_PV + c4) * 4, vg + (size_t)r * 1024 + c4);
        }
        cp_commit();
#pragma unroll
        for (int i = 0; i < 4; i++) {
            int e = tid + (i << 8);
            int r = e >> 4, c4 = (e & 15) << 2;
            cp16(usm + (KS_OFF + KS_STRIDE + r * FA_PK + c4) * 4, kg + (size_t)(64 + r) * 1024 + c4);
            cp16(usm + (VS_OFF + VS_STRIDE + r * FA_PV + c4) * 4, vg + (size_t)(64 + r) * 1024 + c4);
        }
        cp_commit();
    }
    cp_wait<1>();
    __syncthreads();

    // ---- scale Q in place (0.125*log2e folded in; bf16 cvt at fragment load)
    {
        const float qs = 0.125f * LOG2E;
#pragma unroll
        for (int i = 0; i < 16; i++) {
            int e = tid + (i << 8);
            int r = e >> 4, c4 = (e & 15) << 2;
            float4* p = reinterpret_cast<float4*>(fsm + QS_OFF + r * FA_PP + c4);
            float4 vq = *p;
            vq.x *= qs; vq.y *= qs; vq.z *= qs; vq.w *= qs;
            *p = vq;
        }
    }
    __syncthreads();

    const int lr0 = wid * 32 + grp;
    const int lr1 = lr0 + 16;

    float m00 = -1e30f, m01 = -1e30f, m10 = -1e30f, m11 = -1e30f;
    float l00 = 0.f, l01 = 0.f, l10 = 0.f, l11 = 0.f;
    float oac0[8][4], oac1[8][4];
#pragma unroll
    for (int jd = 0; jd < 8; jd++)
#pragma unroll
        for (int t = 0; t < 4; t++) { oac0[jd][t] = 0.f; oac1[jd][t] = 0.f; }

    for (int it = 0; it < NKV; it++) {
        const int buf = it & 1;
        const float* Kb = fsm + KS_OFF + buf * KS_STRIDE;
        const float* Vb = fsm + VS_OFF + buf * VS_STRIDE;

        // ---- S = Q K^T (bf16 m16n8k16) ----
        float sac0[8][4], sac1[8][4];
#pragma unroll
        for (int jn = 0; jn < 8; jn++)
#pragma unroll
            for (int t = 0; t < 4; t++) { sac0[jn][t] = 0.f; sac1[jn][t] = 0.f; }
#pragma unroll
        for (int k16 = 0; k16 < 4; k16++) {
            const int kb = k16 * 16 + 2 * tig;
            uint32_t bfr[8][2];
#pragma unroll
            for (int jn = 0; jn < 8; jn++) {
                int krow = jn * 8 + grp;
                float2 b0 = *reinterpret_cast<const float2*>(Kb + krow * FA_PK + kb);
                float2 b8 = *reinterpret_cast<const float2*>(Kb + krow * FA_PK + kb + 8);
                bfr[jn][0] = f2bf2(b0.x, b0.y);
                bfr[jn][1] = f2bf2(b8.x, b8.y);
            }
            uint32_t af0[4], af1[4];
            {
                float2 q00 = *reinterpret_cast<const float2*>(fsm + QS_OFF + lr0 * FA_PP + kb);
                float2 q80 = *reinterpret_cast<const float2*>(fsm + QS_OFF + (lr0 + 8) * FA_PP + kb);
                float2 q08 = *reinterpret_cast<const float2*>(fsm + QS_OFF + lr0 * FA_PP + kb + 8);
                float2 q88 = *reinterpret_cast<const float2*>(fsm + QS_OFF + (lr0 + 8) * FA_PP + kb + 8);
                af0[0] = f2bf2(q00.x, q00.y); af0[1] = f2bf2(q80.x, q80.y);
                af0[2] = f2bf2(q08.x, q08.y); af0[3] = f2bf2(q88.x, q88.y);
            }
            {
                float2 q00 = *reinterpret_cast<const float2*>(fsm + QS_OFF + lr1 * FA_PP + kb);
                float2 q80 = *reinterpret_cast<const float2*>(fsm + QS_OFF + (lr1 + 8) * FA_PP + kb);
                float2 q08 = *reinterpret_cast<const float2*>(fsm + QS_OFF + lr1 * FA_PP + kb + 8);
                float2 q88 = *reinterpret_cast<const float2*>(fsm + QS_OFF + (lr1 + 8) * FA_PP + kb + 8);
                af1[0] = f2bf2(q00.x, q00.y); af1[1] = f2bf2(q80.x, q80.y);
                af1[2] = f2bf2(q08.x, q08.y); af1[3] = f2bf2(q88.x, q88.y);
            }
#pragma unroll
            for (int jn = 0; jn < 8; jn++) {
                mma_bf16(sac0[jn], af0, bfr[jn]);
                mma_bf16(sac1[jn], af1, bfr[jn]);
            }
        }

        // ---- online softmax (base-2), P packed to bf16x2 ----
        {
            float mx0 = -1e30f, mx1 = -1e30f;
#pragma unroll
            for (int jn = 0; jn < 8; jn++) {
                mx0 = fmaxf(mx0, fmaxf(sac0[jn][0], sac0[jn][1]));
                mx1 = fmaxf(mx1, fmaxf(sac0[jn][2], sac0[jn][3]));
            }
            mx0 = fmaxf(mx0, __shfl_xor_sync(0xffffffffu, mx0, 1));
            mx0 = fmaxf(mx0, __shfl_xor_sync(0xffffffffu, mx0, 2));
            mx1 = fmaxf(mx1, __shfl_xor_sync(0xffffffffu, mx1, 1));
            mx1 = fmaxf(mx1, __shfl_xor_sync(0xffffffffu, mx1, 2));
            float mn0 = fmaxf(m00, mx0), mn1 = fmaxf(m01, mx1);
            float al0 = exp2f(m00 - mn0), al1 = exp2f(m01 - mn1);
            float sum0 = 0.f, sum1 = 0.f;
#pragma unroll
            for (int jn = 0; jn < 8; jn++) {
                float p00 = exp2f(sac0[jn][0] - mn0);
                float p01 = exp2f(sac0[jn][1] - mn0);
                float p10 = exp2f(sac0[jn][2] - mn1);
                float p11 = exp2f(sac0[jn][3] - mn1);
                int ci = jn * 4 + tig;
                pp[lr0 * PPW + ci]       = f2bf2(p00, p01);
                pp[(lr0 + 8) * PPW + ci] = f2bf2(p10, p11);
                sum0 += p00 + p01;  sum1 += p10 + p11;
            }
            sum0 += __shfl_xor_sync(0xffffffffu, sum0, 1);
            sum0 += __shfl_xor_sync(0xffffffffu, sum0, 2);
            sum1 += __shfl_xor_sync(0xffffffffu, sum1, 1);
            sum1 += __shfl_xor_sync(0xffffffffu, sum1, 2);
            l00 = l00 * al0 + sum0;  m00 = mn0;
            l01 = l01 * al1 + sum1;  m01 = mn1;
#pragma unroll
            for (int jd = 0; jd < 8; jd++) {
                oac0[jd][0] *= al0; oac0[jd][1] *= al0;
                oac0[jd][2] *= al1; oac0[jd][3] *= al1;
            }
        }
        {
            float mx0 = -1e30f, mx1 = -1e30f;
#pragma unroll
            for (int jn = 0; jn < 8; jn++) {
                mx0 = fmaxf(mx0, fmaxf(sac1[jn][0], sac1[jn][1]));
                mx1 = fmaxf(mx1, fmaxf(sac1[jn][2], sac1[jn][3]));
            }
            mx0 = fmaxf(mx0, __shfl_xor_sync(0xffffffffu, mx0, 1));
            mx0 = fmaxf(mx0, __shfl_xor_sync(0xffffffffu, mx0, 2));
            mx1 = fmaxf(mx1, __shfl_xor_sync(0xffffffffu, mx1, 1));
            mx1 = fmaxf(mx1, __shfl_xor_sync(0xffffffffu, mx1, 2));
            float mn0 = fmaxf(m10, mx0), mn1 = fmaxf(m11, mx1);
            float al0 = exp2f(m10 - mn0), al1 = exp2f(m11 - mn1);
            float sum0 = 0.f, sum1 = 0.f;
#pragma unroll
            for (int jn = 0; jn < 8; jn++) {
                float p00 = exp2f(sac1[jn][0] - mn0);
                float p01 = exp2f(sac1[jn][1] - mn0);
                float p10 = exp2f(sac1[jn][2] - mn1);
                float p11 = exp2f(sac1[jn][3] - mn1);
                int ci = jn * 4 + tig;
                pp[lr1 * PPW + ci]       = f2bf2(p00, p01);
                pp[(lr1 + 8) * PPW + ci] = f2bf2(p10, p11);
                sum0 += p00 + p01;  sum1 += p10 + p11;
            }
            sum0 += __shfl_xor_sync(0xffffffffu, sum0, 1);
            sum0 += __shfl_xor_sync(0xffffffffu, sum0, 2);
            sum1 += __shfl_xor_sync(0xffffffffu, sum1, 1);
            sum1 += __shfl_xor_sync(0xffffffffu, sum1, 2);
            l10 = l10 * al0 + sum0;  m10 = mn0;
            l11 = l11 * al1 + sum1;  m11 = mn1;
#pragma unroll
            for (int jd = 0; jd < 8; jd++) {
                oac1[jd][0] *= al0; oac1[jd][1] *= al0;
                oac1[jd][2] *= al1; oac1[jd][3] *= al1;
            }
        }
        __syncwarp();

        // ---- O += P V (bf16; A = packed P, single LDS.32 per reg) ----
#pragma unroll
        for (int k16 = 0; k16 < 4; k16++) {
            const int vr = k16 * 16 + 2 * tig;
            const int pi = k16 * 8 + tig;
            uint32_t bfr[8][2];
#pragma unroll
            for (int jd = 0; jd < 8; jd++) {
                int dcol = jd * 8 + grp;
                bfr[jd][0] = f2bf2(Vb[vr * FA_PV + dcol],       Vb[(vr + 1) * FA_PV + dcol]);
                bfr[jd][1] = f2bf2(Vb[(vr + 8) * FA_PV + dcol], Vb[(vr + 9) * FA_PV + dcol]);
            }
            uint32_t af0[4], af1[4];
            af0[0] = pp[lr0 * PPW + pi];       af0[1] = pp[(lr0 + 8) * PPW + pi];
            af0[2] = pp[lr0 * PPW + pi + 4];   af0[3] = pp[(lr0 + 8) * PPW + pi + 4];
            af1[0] = pp[lr1 * PPW + pi];       af1[1] = pp[(lr1 + 8) * PPW + pi];
            af1[2] = pp[lr1 * PPW + pi + 4];   af1[3] = pp[(lr1 + 8) * PPW + pi + 4];
#pragma unroll
            for (int jd = 0; jd < 8; jd++) {
                mma_bf16(oac0[jd], af0, bfr[jd]);
                mma_bf16(oac1[jd], af1, bfr[jd]);
            }
        }

        // ---- prefetch it+2 ----
        __syncthreads();
        if (it < NKV - 1) {
            if (it + 2 < NKV) {
                int kv0 = (it + 2) << 6;
#pragma unroll
                for (int i = 0; i < 4; i++) {
                    int e = tid + (i << 8);
                    int r = e >> 4, c4 = (e & 15) << 2;
                    cp16(usm + (KS_OFF + buf * KS_STRIDE + r * FA_PK + c4) * 4,
                         kg + (size_t)(kv0 + r) * 1024 + c4);
                    cp16(usm + (VS_OFF + buf * VS_STRIDE + r * FA_PV + c4) * 4,
                         vg + (size_t)(kv0 + r) * 1024 + c4);
                }
            }
            cp_commit();
            cp_wait<1>();
            __syncthreads();
        }
    }

    // ---- epilogue ----
    {
        float inv0 = 1.f / l00, inv1 = 1.f / l01;
        float* og  = o + (((size_t)(b * Sq + q0 + lr0) * Hh + h) << 6);
        float* og8 = og + (size_t)8 * 1024;
#pragma unroll
        for (int jd = 0; jd < 8; jd++) {
            int c = jd * 8 + 2 * tig;
            *reinterpret_cast<float2*>(og + c)  = make_float2(oac0[jd][0] * inv0, oac0[jd][1] * inv0);
            *reinterpret_cast<float2*>(og8 + c) = make_float2(oac0[jd][2] * inv1, oac0[jd][3] * inv1);
        }
    }
    {
        float inv0 = 1.f / l10, inv1 = 1.f / l11;
        float* og  = o + (((size_t)(b * Sq + q0 + lr1) * Hh + h) << 6);
        float* og8 = og + (size_t)8 * 1024;
#pragma unroll
        for (int jd = 0; jd < 8; jd++) {
            int c = jd * 8 + 2 * tig;
            *reinterpret_cast<float2*>(og + c)  = make_float2(oac1[jd][0] * inv0, oac1[jd][1] * inv0);
            *reinterpret_cast<float2*>(og8 + c) = make_float2(oac1[jd][2] * inv1, oac1[jd][3] * inv1);
        }
    }
}

// ========= fused LN1 + quantum FFN + LN2 (R6-proven block version) =========
__global__ __launch_bounds__(256) void ln_quantum(const float* __restrict__ x,
                                                  const float* __restrict__ proj,
                                                  const float* __restrict__ g1,
                                                  const float* __restrict__ b1,
                                                  const float* __restrict__ Win,
                                                  const float* __restrict__ b_in,
                                                  const float* __restrict__ Wout,
                                                  const float* __restrict__ b_out,
                                                  const float* __restrict__ ry,
                                                  const float* __restrict__ g2,
                                                  const float* __restrict__ b2,
                                                  float* __restrict__ out)
{
    const int row = blockIdx.x;
    const int tid = threadIdx.x;
    const int lane = tid & 31, wid = tid >> 5;
    const float* px = x + (size_t)row * Dm;
    const float* pp = proj + (size_t)row * Dm;

    __shared__ float redw[64];
    __shared__ float angs[8];
    __shared__ float ezs[8];
    __shared__ float2 st[2][DIMq];

    float xv[4];
    {
        float yv[4], sum = 0.f, sq = 0.f;
#pragma unroll
        for (int j = 0; j < 4; j++) {
            int d = tid + (j << 8);
            float t = px[d] + pp[d];
            yv[j] = t; sum += t; sq = fmaf(t, t, sq);
        }
#pragma unroll
        for (int off = 16; off; off >>= 1) {
            sum += __shfl_xor_sync(0xffffffffu, sum, off);
            sq  += __shfl_xor_sync(0xffffffffu, sq, off);
        }
        if (lane == 0) { redw[wid] = sum; redw[8 + wid] = sq; }
        __syncthreads();
        float tsum = 0.f, tsq = 0.f;
#pragma unroll
        for (int w = 0; w < 8; w++) { tsum += redw[w]; tsq += redw[8 + w]; }
        float mean = tsum * (1.f / 1024.f);
        float var  = tsq * (1.f / 1024.f) - mean * mean;
        float rstd = rsqrtf(var + EPSf);
#pragma unroll
        for (int j = 0; j < 4; j++) {
            int d = tid + (j << 8);
            xv[j] = (yv[j] - mean) * rstd * g1[d] + b1[d];
        }
        __syncthreads();
    }

    float accq[8] = {0, 0, 0, 0, 0, 0, 0, 0};
#pragma unroll
    for (int j = 0; j < 4; j++) {
        int d = tid + (j << 8);
#pragma unroll
        for (int qq = 0; qq < 8; qq++)
            accq[qq] = fmaf(xv[j], Win[qq * Dm + d], accq[qq]);
    }
#pragma unroll
    for (int qq = 0; qq < 8; qq++) {
        float vsum = accq[qq];
#pragma unroll
        for (int off = 16; off; off >>= 1)
            vsum += __shfl_xor_sync(0xffffffffu, vsum, off);
        if (lane == 0) redw[wid * 8 + qq] = vsum;
    }
    __syncthreads();
    if (tid < 8) {
        float s = b_in[tid];
#pragma unroll
        for (int w = 0; w < 8; w++) s += redw[w * 8 + tid];
        angs[tid] = s * 0.5f;
    }
    st[0][tid] = make_float2(tid == 0 ? 1.f : 0.f, 0.f);
    __syncthreads();

    int curb = 0;
#pragma unroll
    for (int w = 0; w < 8; w++) {
        int mask = 1 << (7 - w);
        float sn, cs;
        __sincosf(angs[w], &sn, &cs);
        float2 a  = st[curb][tid];
        float2 bb = st[curb][tid ^ mask];
        st[curb ^ 1][tid] = make_float2(fmaf(cs, a.x,  sn * bb.y),
                                        fmaf(cs, a.y, -sn * bb.x));
        curb ^= 1;
        __syncthreads();
    }
#pragma unroll
    for (int w = 0; w < 8; w++) {
        int mask = 1 << (7 - w);
        float sn, cs;
        __sincosf(ry[w] * 0.5f, &sn, &cs);
        float2 a  = st[curb][tid];
        float2 bb = st[curb][tid ^ mask];
        float sg = (tid & mask) ? sn : -sn;
        st[curb ^ 1][tid] = make_float2(fmaf(cs, a.x, sg * bb.x),
                                        fmaf(cs, a.y, sg * bb.y));
        curb ^= 1;
        __syncthreads();
    }
    int src = tid;
#pragma unroll
    for (int c = 6; c >= 0; c--) {
        int cmask = 1 << (7 - c);
        int tmask = cmask >> 1;
        if (src & cmask) src ^= tmask;
    }
    float2 fa = st[curb][src];
    float p = fa.x * fa.x + fa.y * fa.y;

#pragma unroll
    for (int w = 0; w < 8; w++) {
        float vsum = ((tid >> (7 - w)) & 1) ? -p : p;
#pragma unroll
        for (int off = 16; off; off >>= 1)
            vsum += __shfl_xor_sync(0xffffffffu, vsum, off);
        if (lane == 0) redw[wid * 8 + w] = vsum;
    }
    __syncthreads();
    if (tid < 8) {
        float s = 0.f;
#pragma unroll
        for (int w = 0; w < 8; w++) s += redw[w * 8 + tid];
        ezs[tid] = s;
    }
    __syncthreads();
    float e[8];
#pragma unroll
    for (int qq = 0; qq < 8; qq++) e[qq] = ezs[qq];

    float y[4], sum = 0.f, sq = 0.f;
#pragma unroll
    for (int j = 0; j < 4; j++) {
        int d = tid + (j << 8);
        const float4* wrow = reinterpret_cast<const float4*>(Wout + (size_t)d * 8);
        float4 w0 = wrow[0], w1 = wrow[1];
        float acc = b_out[d];
        acc = fmaf(e[0], w0.x, acc); acc = fmaf(e[1], w0.y, acc);
        acc = fmaf(e[2], w0.z, acc); acc = fmaf(e[3], w0.w, acc);
        acc = fmaf(e[4], w1.x, acc); acc = fmaf(e[5], w1.y, acc);
        acc = fmaf(e[6], w1.z, acc); acc = fmaf(e[7], w1.w, acc);
        acc = fmaxf(acc, 0.f);
        float yv = xv[j] + acc;
        y[j] = yv; sum += yv; sq = fmaf(yv, yv, sq);
    }
    __syncthreads();
#pragma unroll
    for (int off = 16; off; off >>= 1) {
        sum += __shfl_xor_sync(0xffffffffu, sum, off);
        sq  += __shfl_xor_sync(0xffffffffu, sq, off);
    }
    if (lane == 0) { redw[wid] = sum; redw[8 + wid] = sq; }
    __syncthreads();
    float tsum = 0.f, tsq = 0.f;
#pragma unroll
    for (int w = 0; w < 8; w++) { tsum += redw[w]; tsq += redw[8 + w]; }
    float mean = tsum * (1.f / 1024.f);
    float var  = tsq * (1.f / 1024.f) - mean * mean;
    float rstd = rsqrtf(var + EPSf);
#pragma unroll
    for (int j = 0; j < 4; j++) {
        int d = tid + (j << 8);
        out[(size_t)row * Dm + d] = (y[j] - mean) * rstd * g2[d] + b2[d];
    }
}

// ---------------- launch ----------------
extern "C" void kernel_launch(void* const* d_in, const int* in_sizes, int n_in,
                              void* d_out, int out_size)
{
    const float* x     = (const float*)d_in[0];
    const float* Wq    = (const float*)d_in[1];
    const float* Wk    = (const float*)d_in[2];
    const float* Wv    = (const float*)d_in[3];
    const float* Wo    = (const float*)d_in[4];
    const float* g1    = (const float*)d_in[5];
    const float* b1    = (const float*)d_in[6];
    const float* g2    = (const float*)d_in[7];
    const float* b2    = (const float*)d_in[8];
    const float* Win   = (const float*)d_in[9];
    const float* b_in  = (const float*)d_in[10];
    const float* Wout  = (const float*)d_in[11];
    const float* b_out = (const float*)d_in[12];
    const float* ry    = (const float*)d_in[13];
    float* out = (float*)d_out;

    float *q, *k, *v, *o, *proj;
    cudaGetSymbolAddress((void**)&q,    g_q);
    cudaGetSymbolAddress((void**)&k,    g_k);
    cudaGetSymbolAddress((void**)&v,    g_v);
    cudaGetSymbolAddress((void**)&o,    g_o);
    cudaGetSymbolAddress((void**)&proj, g_proj);

    cudaFuncSetAttribute(gemm_mma,  cudaFuncAttributeMaxDynamicSharedMemorySize, GSMEM);
    cudaFuncSetAttribute(gemm_qkv,  cudaFuncAttributeMaxDynamicSharedMemorySize, GSMEM);
    cudaFuncSetAttribute(flash_mma, cudaFuncAttributeMaxDynamicSharedMemorySize, FA_SMEM);

    gemm_qkv<<<dim3(Dm / BN, Mtot / BM, 3), 256, GSMEM>>>(x, Wq, Wk, Wv, q, k, v);
    flash_mma<<<dim3(Sq / 256, Hh, Bsz), 256, FA_SMEM>>>(q, k, v, o);
    gemm_mma<<<dim3(Dm / BN, Mtot / BM), 256, GSMEM>>>(o, Wo, proj);
    ln_quantum<<<Mtot, 256>>>(x, proj, g1, b1, Win, b_in, Wout, b_out, ry, g2, b2, out);
}

// round 10
// speedup vs baseline: 1.6195x; 1.0500x over previous
#include <cuda_runtime.h>
#include <math.h>
#include <cstdint>

#define Bsz   2
#define Sq    2048
#define Dm    1024
#define Hh    16
#define Mtot  4096
#define DIMq  256
#define EPSf  1e-5f
#define LOG2E 1.44269504088896f

// ---------------- scratch ----------------
__device__ float g_q[Mtot * Dm];
__device__ float g_k[Mtot * Dm];
__device__ float g_v[Mtot * Dm];
__device__ float g_o[Mtot * Dm];
__device__ float g_proj[Mtot * Dm];

// ======================= helpers =======================
__device__ __forceinline__ uint32_t smem_to_u32(const void* p) {
    uint32_t a;
    asm("{ .reg .u64 t; cvta.to.shared.u64 t, %1; cvt.u32.u64 %0, t; }" : "=r"(a) : "l"(p));
    return a;
}
__device__ __forceinline__ void cp16(uint32_t sm, const void* g) {
    asm volatile("cp.async.cg.shared.global [%0], [%1], 16;" :: "r"(sm), "l"(g));
}
__device__ __forceinline__ void cp_commit() {
    asm volatile("cp.async.commit_group;");
}
template <int N>
__device__ __forceinline__ void cp_wait() {
    asm volatile("cp.async.wait_group %0;" :: "n"(N));
}
__device__ __forceinline__ uint32_t f2bf2(float lo, float hi) {
    uint32_t r;
    asm("cvt.rn.bf16x2.f32 %0, %1, %2;" : "=r"(r) : "f"(hi), "f"(lo));
    return r;
}
__device__ __forceinline__ void mma_bf16(float c[4], const uint32_t a[4], const uint32_t b[2]) {
    asm volatile(
        "mma.sync.aligned.m16n8k16.row.col.f32.bf16.bf16.f32 "
        "{%0,%1,%2,%3}, {%4,%5,%6,%7}, {%8,%9}, {%0,%1,%2,%3};"
        : "+f"(c[0]), "+f"(c[1]), "+f"(c[2]), "+f"(c[3])
        : "r"(a[0]), "r"(a[1]), "r"(a[2]), "r"(a[3]), "r"(b[0]), "r"(b[1]));
}

// ============ bf16 mma.sync GEMM (R8-proven, single-sync pipeline) ============
#define BM 128
#define BN 256
#define BK 32
#define LDP 36
#define A_STAGE_B (BM * LDP * 4)
#define B_STAGE_B (BN * LDP * 4)
#define GSMEM (3 * (A_STAGE_B + B_STAGE_B))
#define NKT (Dm / BK)

__device__ __forceinline__ void gemm_body(const float* __restrict__ A,
                                          const float* __restrict__ W,
                                          float* __restrict__ C,
                                          char* gsm)
{
    const uint32_t usm = smem_to_u32(gsm);
    const uint32_t usmA = usm;
    const uint32_t usmB = usm + 3 * A_STAGE_B;

    const int tid  = threadIdx.x;
    const int wid  = tid >> 5;
    const int lane = tid & 31;
    const int grp  = lane >> 2;
    const int tig  = lane & 3;
    const int wm   = wid >> 2;
    const int wn   = wid & 3;

    const int aRow0 = blockIdx.y * BM;
    const int bRow0 = blockIdx.x * BN;

    int aSm[4], bSm[8];
    int aGm[4], bGm[8];
#pragma unroll
    for (int i = 0; i < 4; i++) {
        int e = tid + (i << 8);
        int r = e >> 3, c4 = (e & 7) << 2;
        aSm[i] = (r * LDP + c4) * 4;
        aGm[i] = r * Dm + c4;
    }
#pragma unroll
    for (int i = 0; i < 8; i++) {
        int e = tid + (i << 8);
        int r = e >> 3, c4 = (e & 7) << 2;
        bSm[i] = (r * LDP + c4) * 4;
        bGm[i] = r * Dm + c4;
    }
    const float* gA = A + (size_t)aRow0 * Dm;
    const float* gB = W + (size_t)bRow0 * Dm;

    float acc[4][8][4];
#pragma unroll
    for (int im = 0; im < 4; im++)
#pragma unroll
        for (int jn = 0; jn < 8; jn++)
#pragma unroll
            for (int t = 0; t < 4; t++) acc[im][jn][t] = 0.f;

#pragma unroll
    for (int p = 0; p < 2; p++) {
        uint32_t sa = usmA + p * A_STAGE_B;
        uint32_t sb = usmB + p * B_STAGE_B;
        const float* ka = gA + p * BK;
        const float* kb = gB + p * BK;
#pragma unroll
        for (int i = 0; i < 4; i++) cp16(sa + aSm[i], ka + aGm[i]);
#pragma unroll
        for (int i = 0; i < 8; i++) cp16(sb + bSm[i], kb + bGm[i]);
        cp_commit();
    }

    for (int kt = 0; kt < NKT; kt++) {
        cp_wait<1>();
        __syncthreads();   // stage kt ready; all warps done with kt-1 -> buffer (kt+2)%3 free

        if (kt + 2 < NKT) {
            int s = (kt + 2) % 3;
            uint32_t sa = usmA + s * A_STAGE_B;
            uint32_t sb = usmB + s * B_STAGE_B;
            const float* ka = gA + (kt + 2) * BK;
            const float* kb = gB + (kt + 2) * BK;
#pragma unroll
            for (int i = 0; i < 4; i++) cp16(sa + aSm[i], ka + aGm[i]);
#pragma unroll
            for (int i = 0; i < 8; i++) cp16(sb + bSm[i], kb + bGm[i]);
        }
        cp_commit();

        const float* As = (const float*)(gsm + (kt % 3) * A_STAGE_B);
        const float* Bs = (const float*)(gsm + 3 * A_STAGE_B + (kt % 3) * B_STAGE_B);

#pragma unroll
        for (int k16 = 0; k16 < 2; k16++) {
            const int kb = k16 * 16 + 2 * tig;
            uint32_t afr[4][4], bfr[8][2];
#pragma unroll
            for (int im = 0; im < 4; im++) {
                int row = wm * 64 + im * 16 + grp;
                float2 a00 = *reinterpret_cast<const float2*>(As + row * LDP + kb);
                float2 a80 = *reinterpret_cast<const float2*>(As + (row + 8) * LDP + kb);
                float2 a08 = *reinterpret_cast<const float2*>(As + row * LDP + kb + 8);
                float2 a88 = *reinterpret_cast<const float2*>(As + (row + 8) * LDP + kb + 8);
                afr[im][0] = f2bf2(a00.x, a00.y);
                afr[im][1] = f2bf2(a80.x, a80.y);
                afr[im][2] = f2bf2(a08.x, a08.y);
                afr[im][3] = f2bf2(a88.x, a88.y);
            }
#pragma unroll
            for (int jn = 0; jn < 8; jn++) {
                int brow = wn * 64 + jn * 8 + grp;
                float2 b0 = *reinterpret_cast<const float2*>(Bs + brow * LDP + kb);
                float2 b8 = *reinterpret_cast<const float2*>(Bs + brow * LDP + kb + 8);
                bfr[jn][0] = f2bf2(b0.x, b0.y);
                bfr[jn][1] = f2bf2(b8.x, b8.y);
            }
#pragma unroll
            for (int im = 0; im < 4; im++)
#pragma unroll
                for (int jn = 0; jn < 8; jn++)
                    mma_bf16(acc[im][jn], afr[im], bfr[jn]);
        }
        // no trailing sync: next iteration's top barrier orders buffer reuse
    }

    const int rowBase = aRow0 + wm * 64;
    const int colBase = bRow0 + wn * 64;
#pragma unroll
    for (int im = 0; im < 4; im++) {
        int r0 = rowBase + im * 16 + grp;
#pragma unroll
        for (int jn = 0; jn < 8; jn++) {
            int col = colBase + jn * 8 + 2 * tig;
            float2 v01 = make_float2(acc[im][jn][0], acc[im][jn][1]);
            float2 v23 = make_float2(acc[im][jn][2], acc[im][jn][3]);
            *reinterpret_cast<float2*>(C + (size_t)r0 * Dm + col) = v01;
            *reinterpret_cast<float2*>(C + (size_t)(r0 + 8) * Dm + col) = v23;
        }
    }
}

__global__ __launch_bounds__(256, 1) void gemm_mma(const float* __restrict__ A,
                                                   const float* __restrict__ W,
                                                   float* __restrict__ C)
{
    extern __shared__ __align__(16) char gsm[];
    gemm_body(A, W, C, gsm);
}

__global__ __launch_bounds__(256, 1) void gemm_qkv(const float* __restrict__ A,
                                                   const float* __restrict__ W0,
                                                   const float* __restrict__ W1,
                                                   const float* __restrict__ W2,
                                                   float* __restrict__ C0,
                                                   float* __restrict__ C1,
                                                   float* __restrict__ C2)
{
    extern __shared__ __align__(16) char gsm[];
    const int z = blockIdx.z;
    const float* W = (z == 0) ? W0 : (z == 1) ? W1 : W2;
    float*       C = (z == 0) ? C0 : (z == 1) ? C1 : C2;
    gemm_body(A, W, C, gsm);
}

// ============ Flash attention: bf16, packed Q, 3-stage KV, single sync ======
// smem (words): Qpacked 256x36 u32 | Ppacked 256x36 u32 | K 3x64x68 | V 3x64x68
#define FA_PK 68
#define FA_PV 68
#define PPW   36
#define QP_OFF 0
#define PP_OFF (256 * PPW)                   // 9216 (u32 index)
#define KS_OFF (2 * 256 * PPW)               // 18432 (float index)
#define KS_STRIDE (64 * FA_PK)               // 4352
#define VS_OFF (KS_OFF + 3 * KS_STRIDE)      // 31488
#define FA_SMEM ((VS_OFF + 3 * KS_STRIDE) * 4)  // 178176 B
#define NKV (Sq / 64)

__global__ __launch_bounds__(256, 1) void flash_mma(const float* __restrict__ q,
                                                    const float* __restrict__ k,
                                                    const float* __restrict__ v,
                                                    float* __restrict__ o)
{
    extern __shared__ __align__(16) float fsm[];
    const uint32_t usm = smem_to_u32(fsm);
    uint32_t* qp = reinterpret_cast<uint32_t*>(fsm) + QP_OFF;
    uint32_t* pp = reinterpret_cast<uint32_t*>(fsm) + PP_OFF;

    const int tid  = threadIdx.x;
    const int wid  = tid >> 5;
    const int lane = tid & 31;
    const int grp  = lane >> 2;
    const int tig  = lane & 3;

    const int b  = blockIdx.z;
    const int h  = blockIdx.y;
    const int q0 = blockIdx.x << 8;

    const float* qg = q + (((size_t)(b * Sq + q0) * Hh + h) << 6);
    const float* kg = k + (((size_t)(b * Sq) * Hh + h) << 6);
    const float* vg = v + (((size_t)(b * Sq) * Hh + h) << 6);

    // ---- prologue: KV stages 0,1 via cp.async; Q via LDG -> packed bf16 ----
#pragma unroll
    for (int p = 0; p < 2; p++) {
#pragma unroll
        for (int i = 0; i < 4; i++) {
            int e = tid + (i << 8);
            int r = e >> 4, c4 = (e & 15) << 2;
            cp16(usm + (KS_OFF + p * KS_STRIDE + r * FA_PK + c4) * 4, kg + (size_t)(p * 64 + r) * 1024 + c4);
            cp16(usm + (VS_OFF + p * KS_STRIDE + r * FA_PV + c4) * 4, vg + (size_t)(p * 64 + r) * 1024 + c4);
        }
        cp_commit();
    }
    {
        const float qs = 0.125f * LOG2E;
#pragma unroll
        for (int i = 0; i < 16; i++) {
            int e = tid + (i << 8);
            int r = e >> 4, c4 = (e & 15) << 2;
            float4 vq = *reinterpret_cast<const float4*>(qg + (size_t)r * 1024 + c4);
            uint2 pk;
            pk.x = f2bf2(vq.x * qs, vq.y * qs);
            pk.y = f2bf2(vq.z * qs, vq.w * qs);
            *reinterpret_cast<uint2*>(qp + r * PPW + (c4 >> 1)) = pk;
        }
    }

    const int lr0 = wid * 32 + grp;
    const int lr1 = lr0 + 16;

    float m00 = -1e30f, m01 = -1e30f, m10 = -1e30f, m11 = -1e30f;
    float l00 = 0.f, l01 = 0.f, l10 = 0.f, l11 = 0.f;
    float oac0[8][4], oac1[8][4];
#pragma unroll
    for (int jd = 0; jd < 8; jd++)
#pragma unroll
        for (int t = 0; t < 4; t++) { oac0[jd][t] = 0.f; oac1[jd][t] = 0.f; }

    for (int it = 0; it < NKV; it++) {
        cp_wait<1>();
        __syncthreads();   // stage it ready; all warps done it-1 -> buffer (it+2)%3 free; Q pack visible

        // prefetch it+2 into buffer (it+2)%3
        if (it + 2 < NKV) {
            int s = (it + 2) % 3;
            int kv0 = (it + 2) << 6;
#pragma unroll
            for (int i = 0; i < 4; i++) {
                int e = tid + (i << 8);
                int r = e >> 4, c4 = (e & 15) << 2;
                cp16(usm + (KS_OFF + s * KS_STRIDE + r * FA_PK + c4) * 4,
                     kg + (size_t)(kv0 + r) * 1024 + c4);
                cp16(usm + (VS_OFF + s * KS_STRIDE + r * FA_PV + c4) * 4,
                     vg + (size_t)(kv0 + r) * 1024 + c4);
            }
        }
        cp_commit();

        const float* Kb = fsm + KS_OFF + (it % 3) * KS_STRIDE;
        const float* Vb = fsm + VS_OFF + (it % 3) * KS_STRIDE;

        // ---- S = Q K^T (bf16; A = packed Q, single LDS.32 per reg) ----
        float sac0[8][4], sac1[8][4];
#pragma unroll
        for (int jn = 0; jn < 8; jn++)
#pragma unroll
            for (int t = 0; t < 4; t++) { sac0[jn][t] = 0.f; sac1[jn][t] = 0.f; }
#pragma unroll
        for (int k16 = 0; k16 < 4; k16++) {
            const int kb = k16 * 16 + 2 * tig;
            const int pi = k16 * 8 + tig;
            uint32_t bfr[8][2];
#pragma unroll
            for (int jn = 0; jn < 8; jn++) {
                int krow = jn * 8 + grp;
                float2 b0 = *reinterpret_cast<const float2*>(Kb + krow * FA_PK + kb);
                float2 b8 = *reinterpret_cast<const float2*>(Kb + krow * FA_PK + kb + 8);
                bfr[jn][0] = f2bf2(b0.x, b0.y);
                bfr[jn][1] = f2bf2(b8.x, b8.y);
            }
            uint32_t af0[4], af1[4];
            af0[0] = qp[lr0 * PPW + pi];       af0[1] = qp[(lr0 + 8) * PPW + pi];
            af0[2] = qp[lr0 * PPW + pi + 4];   af0[3] = qp[(lr0 + 8) * PPW + pi + 4];
            af1[0] = qp[lr1 * PPW + pi];       af1[1] = qp[(lr1 + 8) * PPW + pi];
            af1[2] = qp[lr1 * PPW + pi + 4];   af1[3] = qp[(lr1 + 8) * PPW + pi + 4];
#pragma unroll
            for (int jn = 0; jn < 8; jn++) {
                mma_bf16(sac0[jn], af0, bfr[jn]);
                mma_bf16(sac1[jn], af1, bfr[jn]);
            }
        }

        // ---- online softmax (base-2), P packed to bf16x2 ----
        {
            float mx0 = -1e30f, mx1 = -1e30f;
#pragma unroll
            for (int jn = 0; jn < 8; jn++) {
                mx0 = fmaxf(mx0, fmaxf(sac0[jn][0], sac0[jn][1]));
                mx1 = fmaxf(mx1, fmaxf(sac0[jn][2], sac0[jn][3]));
            }
            mx0 = fmaxf(mx0, __shfl_xor_sync(0xffffffffu, mx0, 1));
            mx0 = fmaxf(mx0, __shfl_xor_sync(0xffffffffu, mx0, 2));
            mx1 = fmaxf(mx1, __shfl_xor_sync(0xffffffffu, mx1, 1));
            mx1 = fmaxf(mx1, __shfl_xor_sync(0xffffffffu, mx1, 2));
            float mn0 = fmaxf(m00, mx0), mn1 = fmaxf(m01, mx1);
            float al0 = exp2f(m00 - mn0), al1 = exp2f(m01 - mn1);
            float sum0 = 0.f, sum1 = 0.f;
#pragma unroll
            for (int jn = 0; jn < 8; jn++) {
                float p00 = exp2f(sac0[jn][0] - mn0);
                float p01 = exp2f(sac0[jn][1] - mn0);
                float p10 = exp2f(sac0[jn][2] - mn1);
                float p11 = exp2f(sac0[jn][3] - mn1);
                int ci = jn * 4 + tig;
                pp[lr0 * PPW + ci]       = f2bf2(p00, p01);
                pp[(lr0 + 8) * PPW + ci] = f2bf2(p10, p11);
                sum0 += p00 + p01;  sum1 += p10 + p11;
            }
            sum0 += __shfl_xor_sync(0xffffffffu, sum0, 1);
            sum0 += __shfl_xor_sync(0xffffffffu, sum0, 2);
            sum1 += __shfl_xor_sync(0xffffffffu, sum1, 1);
            sum1 += __shfl_xor_sync(0xffffffffu, sum1, 2);
            l00 = l00 * al0 + sum0;  m00 = mn0;
            l01 = l01 * al1 + sum1;  m01 = mn1;
#pragma unroll
            for (int jd = 0; jd < 8; jd++) {
                oac0[jd][0] *= al0; oac0[jd][1] *= al0;
                oac0[jd][2] *= al1; oac0[jd][3] *= al1;
            }
        }
        {
            float mx0 = -1e30f, mx1 = -1e30f;
#pragma unroll
            for (int jn = 0; jn < 8; jn++) {
                mx0 = fmaxf(mx0, fmaxf(sac1[jn][0], sac1[jn][1]));
                mx1 = fmaxf(mx1, fmaxf(sac1[jn][2], sac1[jn][3]));
            }
            mx0 = fmaxf(mx0, __shfl_xor_sync(0xffffffffu, mx0, 1));
            mx0 = fmaxf(mx0, __shfl_xor_sync(0xffffffffu, mx0, 2));
            mx1 = fmaxf(mx1, __shfl_xor_sync(0xffffffffu, mx1, 1));
            mx1 = fmaxf(mx1, __shfl_xor_sync(0xffffffffu, mx1, 2));
            float mn0 = fmaxf(m10, mx0), mn1 = fmaxf(m11, mx1);
            float al0 = exp2f(m10 - mn0), al1 = exp2f(m11 - mn1);
            float sum0 = 0.f, sum1 = 0.f;
#pragma unroll
            for (int jn = 0; jn < 8; jn++) {
                float p00 = exp2f(sac1[jn][0] - mn0);
                float p01 = exp2f(sac1[jn][1] - mn0);
                float p10 = exp2f(sac1[jn][2] - mn1);
                float p11 = exp2f(sac1[jn][3] - mn1);
                int ci = jn * 4 + tig;
                pp[lr1 * PPW + ci]       = f2bf2(p00, p01);
                pp[(lr1 + 8) * PPW + ci] = f2bf2(p10, p11);
                sum0 += p00 + p01;  sum1 += p10 + p11;
            }
            sum0 += __shfl_xor_sync(0xffffffffu, sum0, 1);
            sum0 += __shfl_xor_sync(0xffffffffu, sum0, 2);
            sum1 += __shfl_xor_sync(0xffffffffu, sum1, 1);
            sum1 += __shfl_xor_sync(0xffffffffu, sum1, 2);
            l10 = l10 * al0 + sum0;  m10 = mn0;
            l11 = l11 * al1 + sum1;  m11 = mn1;
#pragma unroll
            for (int jd = 0; jd < 8; jd++) {
                oac1[jd][0] *= al0; oac1[jd][1] *= al0;
                oac1[jd][2] *= al1; oac1[jd][3] *= al1;
            }
        }
        __syncwarp();

        // ---- O += P V (bf16; A = packed P, single LDS.32 per reg) ----
#pragma unroll
        for (int k16 = 0; k16 < 4; k16++) {
            const int vr = k16 * 16 + 2 * tig;
            const int pi = k16 * 8 + tig;
            uint32_t bfr[8][2];
#pragma unroll
            for (int jd = 0; jd < 8; jd++) {
                int dcol = jd * 8 + grp;
                bfr[jd][0] = f2bf2(Vb[vr * FA_PV + dcol],       Vb[(vr + 1) * FA_PV + dcol]);
                bfr[jd][1] = f2bf2(Vb[(vr + 8) * FA_PV + dcol], Vb[(vr + 9) * FA_PV + dcol]);
            }
            uint32_t af0[4], af1[4];
            af0[0] = pp[lr0 * PPW + pi];       af0[1] = pp[(lr0 + 8) * PPW + pi];
            af0[2] = pp[lr0 * PPW + pi + 4];   af0[3] = pp[(lr0 + 8) * PPW + pi + 4];
            af1[0] = pp[lr1 * PPW + pi];       af1[1] = pp[(lr1 + 8) * PPW + pi];
            af1[2] = pp[lr1 * PPW + pi + 4];   af1[3] = pp[(lr1 + 8) * PPW + pi + 4];
#pragma unroll
            for (int jd = 0; jd < 8; jd++) {
                mma_bf16(oac0[jd], af0, bfr[jd]);
                mma_bf16(oac1[jd], af1, bfr[jd]);
            }
        }
        // no trailing sync: next iteration's top barrier orders buffer reuse
    }

    // ---- epilogue ----
    {
        float inv0 = 1.f / l00, inv1 = 1.f / l01;
        float* og  = o + (((size_t)(b * Sq + q0 + lr0) * Hh + h) << 6);
        float* og8 = og + (size_t)8 * 1024;
#pragma unroll
        for (int jd = 0; jd < 8; jd++) {
            int c = jd * 8 + 2 * tig;
            *reinterpret_cast<float2*>(og + c)  = make_float2(oac0[jd][0] * inv0, oac0[jd][1] * inv0);
            *reinterpret_cast<float2*>(og8 + c) = make_float2(oac0[jd][2] * inv1, oac0[jd][3] * inv1);
        }
    }
    {
        float inv0 = 1.f / l10, inv1 = 1.f / l11;
        float* og  = o + (((size_t)(b * Sq + q0 + lr1) * Hh + h) << 6);
        float* og8 = og + (size_t)8 * 1024;
#pragma unroll
        for (int jd = 0; jd < 8; jd++) {
            int c = jd * 8 + 2 * tig;
            *reinterpret_cast<float2*>(og + c)  = make_float2(oac1[jd][0] * inv0, oac1[jd][1] * inv0);
            *reinterpret_cast<float2*>(og8 + c) = make_float2(oac1[jd][2] * inv1, oac1[jd][3] * inv1);
        }
    }
}

// ========= fused LN1 + quantum FFN + LN2 (R6-proven block version) =========
__global__ __launch_bounds__(256) void ln_quantum(const float* __restrict__ x,
                                                  const float* __restrict__ proj,
                                                  const float* __restrict__ g1,
                                                  const float* __restrict__ b1,
                                                  const float* __restrict__ Win,
                                                  const float* __restrict__ b_in,
                                                  const float* __restrict__ Wout,
                                                  const float* __restrict__ b_out,
                                                  const float* __restrict__ ry,
                                                  const float* __restrict__ g2,
                                                  const float* __restrict__ b2,
                                                  float* __restrict__ out)
{
    const int row = blockIdx.x;
    const int tid = threadIdx.x;
    const int lane = tid & 31, wid = tid >> 5;
    const float* px = x + (size_t)row * Dm;
    const float* pp = proj + (size_t)row * Dm;

    __shared__ float redw[64];
    __shared__ float angs[8];
    __shared__ float ezs[8];
    __shared__ float2 st[2][DIMq];

    float xv[4];
    {
        float yv[4], sum = 0.f, sq = 0.f;
#pragma unroll
        for (int j = 0; j < 4; j++) {
            int d = tid + (j << 8);
            float t = px[d] + pp[d];
            yv[j] = t; sum += t; sq = fmaf(t, t, sq);
        }
#pragma unroll
        for (int off = 16; off; off >>= 1) {
            sum += __shfl_xor_sync(0xffffffffu, sum, off);
            sq  += __shfl_xor_sync(0xffffffffu, sq, off);
        }
        if (lane == 0) { redw[wid] = sum; redw[8 + wid] = sq; }
        __syncthreads();
        float tsum = 0.f, tsq = 0.f;
#pragma unroll
        for (int w = 0; w < 8; w++) { tsum += redw[w]; tsq += redw[8 + w]; }
        float mean = tsum * (1.f / 1024.f);
        float var  = tsq * (1.f / 1024.f) - mean * mean;
        float rstd = rsqrtf(var + EPSf);
#pragma unroll
        for (int j = 0; j < 4; j++) {
            int d = tid + (j << 8);
            xv[j] = (yv[j] - mean) * rstd * g1[d] + b1[d];
        }
        __syncthreads();
    }

    float accq[8] = {0, 0, 0, 0, 0, 0, 0, 0};
#pragma unroll
    for (int j = 0; j < 4; j++) {
        int d = tid + (j << 8);
#pragma unroll
        for (int qq = 0; qq < 8; qq++)
            accq[qq] = fmaf(xv[j], Win[qq * Dm + d], accq[qq]);
    }
#pragma unroll
    for (int qq = 0; qq < 8; qq++) {
        float vsum = accq[qq];
#pragma unroll
        for (int off = 16; off; off >>= 1)
            vsum += __shfl_xor_sync(0xffffffffu, vsum, off);
        if (lane == 0) redw[wid * 8 + qq] = vsum;
    }
    __syncthreads();
    if (tid < 8) {
        float s = b_in[tid];
#pragma unroll
        for (int w = 0; w < 8; w++) s += redw[w * 8 + tid];
        angs[tid] = s * 0.5f;
    }
    st[0][tid] = make_float2(tid == 0 ? 1.f : 0.f, 0.f);
    __syncthreads();

    int curb = 0;
#pragma unroll
    for (int w = 0; w < 8; w++) {
        int mask = 1 << (7 - w);
        float sn, cs;
        __sincosf(angs[w], &sn, &cs);
        float2 a  = st[curb][tid];
        float2 bb = st[curb][tid ^ mask];
        st[curb ^ 1][tid] = make_float2(fmaf(cs, a.x,  sn * bb.y),
                                        fmaf(cs, a.y, -sn * bb.x));
        curb ^= 1;
        __syncthreads();
    }
#pragma unroll
    for (int w = 0; w < 8; w++) {
        int mask = 1 << (7 - w);
        float sn, cs;
        __sincosf(ry[w] * 0.5f, &sn, &cs);
        float2 a  = st[curb][tid];
        float2 bb = st[curb][tid ^ mask];
        float sg = (tid & mask) ? sn : -sn;
        st[curb ^ 1][tid] = make_float2(fmaf(cs, a.x, sg * bb.x),
                                        fmaf(cs, a.y, sg * bb.y));
        curb ^= 1;
        __syncthreads();
    }
    int src = tid;
#pragma unroll
    for (int c = 6; c >= 0; c--) {
        int cmask = 1 << (7 - c);
        int tmask = cmask >> 1;
        if (src & cmask) src ^= tmask;
    }
    float2 fa = st[curb][src];
    float p = fa.x * fa.x + fa.y * fa.y;

#pragma unroll
    for (int w = 0; w < 8; w++) {
        float vsum = ((tid >> (7 - w)) & 1) ? -p : p;
#pragma unroll
        for (int off = 16; off; off >>= 1)
            vsum += __shfl_xor_sync(0xffffffffu, vsum, off);
        if (lane == 0) redw[wid * 8 + w] = vsum;
    }
    __syncthreads();
    if (tid < 8) {
        float s = 0.f;
#pragma unroll
        for (int w = 0; w < 8; w++) s += redw[w * 8 + tid];
        ezs[tid] = s;
    }
    __syncthreads();
    float e[8];
#pragma unroll
    for (int qq = 0; qq < 8; qq++) e[qq] = ezs[qq];

    float y[4], sum = 0.f, sq = 0.f;
#pragma unroll
    for (int j = 0; j < 4; j++) {
        int d = tid + (j << 8);
        const float4* wrow = reinterpret_cast<const float4*>(Wout + (size_t)d * 8);
        float4 w0 = wrow[0], w1 = wrow[1];
        float acc = b_out[d];
        acc = fmaf(e[0], w0.x, acc); acc = fmaf(e[1], w0.y, acc);
        acc = fmaf(e[2], w0.z, acc); acc = fmaf(e[3], w0.w, acc);
        acc = fmaf(e[4], w1.x, acc); acc = fmaf(e[5], w1.y, acc);
        acc = fmaf(e[6], w1.z, acc); acc = fmaf(e[7], w1.w, acc);
        acc = fmaxf(acc, 0.f);
        float yv = xv[j] + acc;
        y[j] = yv; sum += yv; sq = fmaf(yv, yv, sq);
    }
    __syncthreads();
#pragma unroll
    for (int off = 16; off; off >>= 1) {
        sum += __shfl_xor_sync(0xffffffffu, sum, off);
        sq  += __shfl_xor_sync(0xffffffffu, sq, off);
    }
    if (lane == 0) { redw[wid] = sum; redw[8 + wid] = sq; }
    __syncthreads();
    float tsum = 0.f, tsq = 0.f;
#pragma unroll
    for (int w = 0; w < 8; w++) { tsum += redw[w]; tsq += redw[8 + w]; }
    float mean = tsum * (1.f / 1024.f);
    float var  = tsq * (1.f / 1024.f) - mean * mean;
    float rstd = rsqrtf(var + EPSf);
#pragma unroll
    for (int j = 0; j < 4; j++) {
        int d = tid + (j << 8);
        out[(size_t)row * Dm + d] = (y[j] - mean) * rstd * g2[d] + b2[d];
    }
}

// ---------------- launch ----------------
extern "C" void kernel_launch(void* const* d_in, const int* in_sizes, int n_in,
                              void* d_out, int out_size)
{
    const float* x     = (const float*)d_in[0];
    const float* Wq    = (const float*)d_in[1];
    const float* Wk    = (const float*)d_in[2];
    const float* Wv    = (const float*)d_in[3];
    const float* Wo    = (const float*)d_in[4];
    const float* g1    = (const float*)d_in[5];
    const float* b1    = (const float*)d_in[6];
    const float* g2    = (const float*)d_in[7];
    const float* b2    = (const float*)d_in[8];
    const float* Win   = (const float*)d_in[9];
    const float* b_in  = (const float*)d_in[10];
    const float* Wout  = (const float*)d_in[11];
    const float* b_out = (const float*)d_in[12];
    const float* ry    = (const float*)d_in[13];
    float* out = (float*)d_out;

    float *q, *k, *v, *o, *proj;
    cudaGetSymbolAddress((void**)&q,    g_q);
    cudaGetSymbolAddress((void**)&k,    g_k);
    cudaGetSymbolAddress((void**)&v,    g_v);
    cudaGetSymbolAddress((void**)&o,    g_o);
    cudaGetSymbolAddress((void**)&proj, g_proj);

    cudaFuncSetAttribute(gemm_mma,  cudaFuncAttributeMaxDynamicSharedMemorySize, GSMEM);
    cudaFuncSetAttribute(gemm_qkv,  cudaFuncAttributeMaxDynamicSharedMemorySize, GSMEM);
    cudaFuncSetAttribute(flash_mma, cudaFuncAttributeMaxDynamicSharedMemorySize, FA_SMEM);

    gemm_qkv<<<dim3(Dm / BN, Mtot / BM, 3), 256, GSMEM>>>(x, Wq, Wk, Wv, q, k, v);
    flash_mma<<<dim3(Sq / 256, Hh, Bsz), 256, FA_SMEM>>>(q, k, v, o);
    gemm_mma<<<dim3(Dm / BN, Mtot / BM), 256, GSMEM>>>(o, Wo, proj);
    ln_quantum<<<Mtot, 256>>>(x, proj, g1, b1, Win, b_in, Wout, b_out, ry, g2, b2, out);
}

// round 11
// speedup vs baseline: 1.8026x; 1.1131x over previous
#include <cuda_runtime.h>
#include <math.h>
#include <cstdint>

#define Bsz   2
#define Sq    2048
#define Dm    1024
#define Hh    16
#define Mtot  4096
#define DIMq  256
#define EPSf  1e-5f
#define LOG2E 1.44269504088896f

// ---------------- scratch ----------------
__device__ uint32_t g_qp[Mtot * 512];   // packed bf16x2, pre-scaled
__device__ uint32_t g_kp[Mtot * 512];   // packed bf16x2
__device__ float    g_v[Mtot * Dm];
__device__ float    g_o[Mtot * Dm];
__device__ float    g_proj[Mtot * Dm];

// ======================= helpers =======================
__device__ __forceinline__ uint32_t smem_to_u32(const void* p) {
    uint32_t a;
    asm("{ .reg .u64 t; cvta.to.shared.u64 t, %1; cvt.u32.u64 %0, t; }" : "=r"(a) : "l"(p));
    return a;
}
__device__ __forceinline__ void cp16(uint32_t sm, const void* g) {
    asm volatile("cp.async.cg.shared.global [%0], [%1], 16;" :: "r"(sm), "l"(g));
}
__device__ __forceinline__ void cp_commit() {
    asm volatile("cp.async.commit_group;");
}
template <int N>
__device__ __forceinline__ void cp_wait() {
    asm volatile("cp.async.wait_group %0;" :: "n"(N));
}
__device__ __forceinline__ uint32_t f2bf2(float lo, float hi) {
    uint32_t r;
    asm("cvt.rn.bf16x2.f32 %0, %1, %2;" : "=r"(r) : "f"(hi), "f"(lo));
    return r;
}
__device__ __forceinline__ void mma_bf16(float c[4], const uint32_t a[4], const uint32_t b[2]) {
    asm volatile(
        "mma.sync.aligned.m16n8k16.row.col.f32.bf16.bf16.f32 "
        "{%0,%1,%2,%3}, {%4,%5,%6,%7}, {%8,%9}, {%0,%1,%2,%3};"
        : "+f"(c[0]), "+f"(c[1]), "+f"(c[2]), "+f"(c[3])
        : "r"(a[0]), "r"(a[1]), "r"(a[2]), "r"(a[3]), "r"(b[0]), "r"(b[1]));
}

// ============ bf16 mma.sync GEMM (single-sync pipeline) ============
// outmode 0: fp32 -> Cf; outmode 1: pack bf16x2*scale -> Cp
#define BM 128
#define BN 256
#define BK 32
#define LDP 36
#define A_STAGE_B (BM * LDP * 4)
#define B_STAGE_B (BN * LDP * 4)
#define GSMEM (3 * (A_STAGE_B + B_STAGE_B))
#define NKT (Dm / BK)

__device__ __forceinline__ void gemm_body(const float* __restrict__ A,
                                          const float* __restrict__ W,
                                          float* __restrict__ Cf,
                                          uint32_t* __restrict__ Cp,
                                          int outmode, float scale,
                                          char* gsm)
{
    const uint32_t usm = smem_to_u32(gsm);
    const uint32_t usmA = usm;
    const uint32_t usmB = usm + 3 * A_STAGE_B;

    const int tid  = threadIdx.x;
    const int wid  = tid >> 5;
    const int lane = tid & 31;
    const int grp  = lane >> 2;
    const int tig  = lane & 3;
    const int wm   = wid >> 2;
    const int wn   = wid & 3;

    const int aRow0 = blockIdx.y * BM;
    const int bRow0 = blockIdx.x * BN;

    int aSm[4], bSm[8];
    int aGm[4], bGm[8];
#pragma unroll
    for (int i = 0; i < 4; i++) {
        int e = tid + (i << 8);
        int r = e >> 3, c4 = (e & 7) << 2;
        aSm[i] = (r * LDP + c4) * 4;
        aGm[i] = r * Dm + c4;
    }
#pragma unroll
    for (int i = 0; i < 8; i++) {
        int e = tid + (i << 8);
        int r = e >> 3, c4 = (e & 7) << 2;
        bSm[i] = (r * LDP + c4) * 4;
        bGm[i] = r * Dm + c4;
    }
    const float* gA = A + (size_t)aRow0 * Dm;
    const float* gB = W + (size_t)bRow0 * Dm;

    float acc[4][8][4];
#pragma unroll
    for (int im = 0; im < 4; im++)
#pragma unroll
        for (int jn = 0; jn < 8; jn++)
#pragma unroll
            for (int t = 0; t < 4; t++) acc[im][jn][t] = 0.f;

#pragma unroll
    for (int p = 0; p < 2; p++) {
        uint32_t sa = usmA + p * A_STAGE_B;
        uint32_t sb = usmB + p * B_STAGE_B;
        const float* ka = gA + p * BK;
        const float* kb = gB + p * BK;
#pragma unroll
        for (int i = 0; i < 4; i++) cp16(sa + aSm[i], ka + aGm[i]);
#pragma unroll
        for (int i = 0; i < 8; i++) cp16(sb + bSm[i], kb + bGm[i]);
        cp_commit();
    }

    for (int kt = 0; kt < NKT; kt++) {
        cp_wait<1>();
        __syncthreads();

        if (kt + 2 < NKT) {
            int s = (kt + 2) % 3;
            uint32_t sa = usmA + s * A_STAGE_B;
            uint32_t sb = usmB + s * B_STAGE_B;
            const float* ka = gA + (kt + 2) * BK;
            const float* kb = gB + (kt + 2) * BK;
#pragma unroll
            for (int i = 0; i < 4; i++) cp16(sa + aSm[i], ka + aGm[i]);
#pragma unroll
            for (int i = 0; i < 8; i++) cp16(sb + bSm[i], kb + bGm[i]);
        }
        cp_commit();

        const float* As = (const float*)(gsm + (kt % 3) * A_STAGE_B);
        const float* Bs = (const float*)(gsm + 3 * A_STAGE_B + (kt % 3) * B_STAGE_B);

#pragma unroll
        for (int k16 = 0; k16 < 2; k16++) {
            const int kb = k16 * 16 + 2 * tig;
            uint32_t afr[4][4], bfr[8][2];
#pragma unroll
            for (int im = 0; im < 4; im++) {
                int row = wm * 64 + im * 16 + grp;
                float2 a00 = *reinterpret_cast<const float2*>(As + row * LDP + kb);
                float2 a80 = *reinterpret_cast<const float2*>(As + (row + 8) * LDP + kb);
                float2 a08 = *reinterpret_cast<const float2*>(As + row * LDP + kb + 8);
                float2 a88 = *reinterpret_cast<const float2*>(As + (row + 8) * LDP + kb + 8);
                afr[im][0] = f2bf2(a00.x, a00.y);
                afr[im][1] = f2bf2(a80.x, a80.y);
                afr[im][2] = f2bf2(a08.x, a08.y);
                afr[im][3] = f2bf2(a88.x, a88.y);
            }
#pragma unroll
            for (int jn = 0; jn < 8; jn++) {
                int brow = wn * 64 + jn * 8 + grp;
                float2 b0 = *reinterpret_cast<const float2*>(Bs + brow * LDP + kb);
                float2 b8 = *reinterpret_cast<const float2*>(Bs + brow * LDP + kb + 8);
                bfr[jn][0] = f2bf2(b0.x, b0.y);
                bfr[jn][1] = f2bf2(b8.x, b8.y);
            }
#pragma unroll
            for (int im = 0; im < 4; im++)
#pragma unroll
                for (int jn = 0; jn < 8; jn++)
                    mma_bf16(acc[im][jn], afr[im], bfr[jn]);
        }
    }

    const int rowBase = aRow0 + wm * 64;
    const int colBase = bRow0 + wn * 64;
    if (outmode == 0) {
#pragma unroll
        for (int im = 0; im < 4; im++) {
            int r0 = rowBase + im * 16 + grp;
#pragma unroll
            for (int jn = 0; jn < 8; jn++) {
                int col = colBase + jn * 8 + 2 * tig;
                float2 v01 = make_float2(acc[im][jn][0], acc[im][jn][1]);
                float2 v23 = make_float2(acc[im][jn][2], acc[im][jn][3]);
                *reinterpret_cast<float2*>(Cf + (size_t)r0 * Dm + col) = v01;
                *reinterpret_cast<float2*>(Cf + (size_t)(r0 + 8) * Dm + col) = v23;
            }
        }
    } else {
#pragma unroll
        for (int im = 0; im < 4; im++) {
            int r0 = rowBase + im * 16 + grp;
#pragma unroll
            for (int jn = 0; jn < 8; jn++) {
                int col = colBase + jn * 8 + 2 * tig;
                Cp[(size_t)r0 * 512 + (col >> 1)] =
                    f2bf2(acc[im][jn][0] * scale, acc[im][jn][1] * scale);
                Cp[(size_t)(r0 + 8) * 512 + (col >> 1)] =
                    f2bf2(acc[im][jn][2] * scale, acc[im][jn][3] * scale);
            }
        }
    }
}

__global__ __launch_bounds__(256, 1) void gemm_mma(const float* __restrict__ A,
                                                   const float* __restrict__ W,
                                                   float* __restrict__ C)
{
    extern __shared__ __align__(16) char gsm[];
    gemm_body(A, W, C, nullptr, 0, 1.f, gsm);
}

__global__ __launch_bounds__(256, 1) void gemm_qkv(const float* __restrict__ A,
                                                   const float* __restrict__ W0,
                                                   const float* __restrict__ W1,
                                                   const float* __restrict__ W2,
                                                   uint32_t* __restrict__ Qp,
                                                   uint32_t* __restrict__ Kp,
                                                   float* __restrict__ Vf)
{
    extern __shared__ __align__(16) char gsm[];
    const int z = blockIdx.z;
    if (z == 0)      gemm_body(A, W0, nullptr, Qp, 1, 0.125f * LOG2E, gsm);
    else if (z == 1) gemm_body(A, W1, nullptr, Kp, 1, 1.f, gsm);
    else             gemm_body(A, W2, Vf, nullptr, 0, 1.f, gsm);
}

// ============ Flash attention: packed bf16 Q/K from global ================
// smem (u32 words): Qp 256x36 | Pp 256x36 | Kp 3x64x36 | V(f32) 3x64x68
#define PPW   36
#define KPW   36
#define FA_PV 68
#define QP_OFF 0
#define PP_OFF (256 * PPW)                   // 9216
#define KP_OFF (2 * 256 * PPW)               // 18432
#define KP_STRIDE (64 * KPW)                 // 2304
#define VS_OFF (KP_OFF + 3 * KP_STRIDE)      // 25344
#define VS_STRIDE (64 * FA_PV)               // 4352
#define FA_SMEM ((VS_OFF + 3 * VS_STRIDE) * 4)  // 153600 B
#define NKV (Sq / 64)

__global__ __launch_bounds__(256, 1) void flash_mma(const uint32_t* __restrict__ qpg,
                                                    const uint32_t* __restrict__ kpg,
                                                    const float* __restrict__ v,
                                                    float* __restrict__ o)
{
    extern __shared__ __align__(16) float fsm[];
    const uint32_t usm = smem_to_u32(fsm);
    uint32_t* qp = reinterpret_cast<uint32_t*>(fsm) + QP_OFF;
    uint32_t* pp = reinterpret_cast<uint32_t*>(fsm) + PP_OFF;
    const uint32_t* kp = reinterpret_cast<uint32_t*>(fsm) + KP_OFF;

    const int tid  = threadIdx.x;
    const int wid  = tid >> 5;
    const int lane = tid & 31;
    const int grp  = lane >> 2;
    const int tig  = lane & 3;

    const int b  = blockIdx.z;
    const int h  = blockIdx.y;
    const int q0 = blockIdx.x << 8;

    const uint32_t* qg = qpg + (size_t)(b * Sq + q0) * 512 + h * 32;
    const uint32_t* kg = kpg + (size_t)(b * Sq) * 512 + h * 32;
    const float*    vg = v + (((size_t)(b * Sq) * Hh + h) << 6);

    // ---- prologue: group0 = {K0, V0, Q}; group1 = {K1, V1} ----
    {
#pragma unroll
        for (int i = 0; i < 2; i++) {             // K0: 512 chunks
            int e = tid + (i << 8);
            int r = e >> 3, c4 = (e & 7) << 2;
            cp16(usm + (KP_OFF + r * KPW + c4) * 4, kg + (size_t)r * 512 + c4);
        }
#pragma unroll
        for (int i = 0; i < 4; i++) {             // V0
            int e = tid + (i << 8);
            int r = e >> 4, c4 = (e & 15) << 2;
            cp16(usm + (VS_OFF + r * FA_PV + c4) * 4, vg + (size_t)r * 1024 + c4);
        }
#pragma unroll
        for (int i = 0; i < 8; i++) {             // Q: 2048 chunks
            int e = tid + (i << 8);
            int r = e >> 3, c4 = (e & 7) << 2;
            cp16(usm + (QP_OFF + r * PPW + c4) * 4, qg + (size_t)r * 512 + c4);
        }
        cp_commit();
#pragma unroll
        for (int i = 0; i < 2; i++) {             // K1
            int e = tid + (i << 8);
            int r = e >> 3, c4 = (e & 7) << 2;
            cp16(usm + (KP_OFF + KP_STRIDE + r * KPW + c4) * 4, kg + (size_t)(64 + r) * 512 + c4);
        }
#pragma unroll
        for (int i = 0; i < 4; i++) {             // V1
            int e = tid + (i << 8);
            int r = e >> 4, c4 = (e & 15) << 2;
            cp16(usm + (VS_OFF + VS_STRIDE + r * FA_PV + c4) * 4, vg + (size_t)(64 + r) * 1024 + c4);
        }
        cp_commit();
    }

    const int lr0 = wid * 32 + grp;
    const int lr1 = lr0 + 16;

    float m00 = -1e30f, m01 = -1e30f, m10 = -1e30f, m11 = -1e30f;
    float l00 = 0.f, l01 = 0.f, l10 = 0.f, l11 = 0.f;
    float oac0[8][4], oac1[8][4];
#pragma unroll
    for (int jd = 0; jd < 8; jd++)
#pragma unroll
        for (int t = 0; t < 4; t++) { oac0[jd][t] = 0.f; oac1[jd][t] = 0.f; }

    for (int it = 0; it < NKV; it++) {
        cp_wait<1>();
        __syncthreads();   // stage it ready; buffer (it+2)%3 free (all warps past it-1)

        if (it + 2 < NKV) {
            int s = (it + 2) % 3;
            int kv0 = (it + 2) << 6;
#pragma unroll
            for (int i = 0; i < 2; i++) {
                int e = tid + (i << 8);
                int r = e >> 3, c4 = (e & 7) << 2;
                cp16(usm + (KP_OFF + s * KP_STRIDE + r * KPW + c4) * 4,
                     kg + (size_t)(kv0 + r) * 512 + c4);
            }
#pragma unroll
            for (int i = 0; i < 4; i++) {
                int e = tid + (i << 8);
                int r = e >> 4, c4 = (e & 15) << 2;
                cp16(usm + (VS_OFF + s * VS_STRIDE + r * FA_PV + c4) * 4,
                     vg + (size_t)(kv0 + r) * 1024 + c4);
            }
        }
        cp_commit();

        const uint32_t* Kb = kp + (it % 3) * KP_STRIDE;
        const float*    Vb = fsm + VS_OFF + (it % 3) * VS_STRIDE;

        // ---- S = Q K^T (all fragments single LDS.32, zero cvt) ----
        float sac0[8][4], sac1[8][4];
#pragma unroll
        for (int jn = 0; jn < 8; jn++)
#pragma unroll
            for (int t = 0; t < 4; t++) { sac0[jn][t] = 0.f; sac1[jn][t] = 0.f; }
#pragma unroll
        for (int k16 = 0; k16 < 4; k16++) {
            const int pi = k16 * 8 + tig;
            uint32_t bfr[8][2];
#pragma unroll
            for (int jn = 0; jn < 8; jn++) {
                int krow = jn * 8 + grp;
                bfr[jn][0] = Kb[krow * KPW + pi];
                bfr[jn][1] = Kb[krow * KPW + pi + 4];
            }
            uint32_t af0[4], af1[4];
            af0[0] = qp[lr0 * PPW + pi];       af0[1] = qp[(lr0 + 8) * PPW + pi];
            af0[2] = qp[lr0 * PPW + pi + 4];   af0[3] = qp[(lr0 + 8) * PPW + pi + 4];
            af1[0] = qp[lr1 * PPW + pi];       af1[1] = qp[(lr1 + 8) * PPW + pi];
            af1[2] = qp[lr1 * PPW + pi + 4];   af1[3] = qp[(lr1 + 8) * PPW + pi + 4];
#pragma unroll
            for (int jn = 0; jn < 8; jn++) {
                mma_bf16(sac0[jn], af0, bfr[jn]);
                mma_bf16(sac1[jn], af1, bfr[jn]);
            }
        }

        // ---- online softmax (base-2; Q already carries log2e scale) ----
        {
            float mx0 = -1e30f, mx1 = -1e30f;
#pragma unroll
            for (int jn = 0; jn < 8; jn++) {
                mx0 = fmaxf(mx0, fmaxf(sac0[jn][0], sac0[jn][1]));
                mx1 = fmaxf(mx1, fmaxf(sac0[jn][2], sac0[jn][3]));
            }
            mx0 = fmaxf(mx0, __shfl_xor_sync(0xffffffffu, mx0, 1));
            mx0 = fmaxf(mx0, __shfl_xor_sync(0xffffffffu, mx0, 2));
            mx1 = fmaxf(mx1, __shfl_xor_sync(0xffffffffu, mx1, 1));
            mx1 = fmaxf(mx1, __shfl_xor_sync(0xffffffffu, mx1, 2));
            float mn0 = fmaxf(m00, mx0), mn1 = fmaxf(m01, mx1);
            float al0 = exp2f(m00 - mn0), al1 = exp2f(m01 - mn1);
            float sum0 = 0.f, sum1 = 0.f;
#pragma unroll
            for (int jn = 0; jn < 8; jn++) {
                float p00 = exp2f(sac0[jn][0] - mn0);
                float p01 = exp2f(sac0[jn][1] - mn0);
                float p10 = exp2f(sac0[jn][2] - mn1);
                float p11 = exp2f(sac0[jn][3] - mn1);
                int ci = jn * 4 + tig;
                pp[lr0 * PPW + ci]       = f2bf2(p00, p01);
                pp[(lr0 + 8) * PPW + ci] = f2bf2(p10, p11);
                sum0 += p00 + p01;  sum1 += p10 + p11;
            }
            sum0 += __shfl_xor_sync(0xffffffffu, sum0, 1);
            sum0 += __shfl_xor_sync(0xffffffffu, sum0, 2);
            sum1 += __shfl_xor_sync(0xffffffffu, sum1, 1);
            sum1 += __shfl_xor_sync(0xffffffffu, sum1, 2);
            l00 = l00 * al0 + sum0;  m00 = mn0;
            l01 = l01 * al1 + sum1;  m01 = mn1;
#pragma unroll
            for (int jd = 0; jd < 8; jd++) {
                oac0[jd][0] *= al0; oac0[jd][1] *= al0;
                oac0[jd][2] *= al1; oac0[jd][3] *= al1;
            }
        }
        {
            float mx0 = -1e30f, mx1 = -1e30f;
#pragma unroll
            for (int jn = 0; jn < 8; jn++) {
                mx0 = fmaxf(mx0, fmaxf(sac1[jn][0], sac1[jn][1]));
                mx1 = fmaxf(mx1, fmaxf(sac1[jn][2], sac1[jn][3]));
            }
            mx0 = fmaxf(mx0, __shfl_xor_sync(0xffffffffu, mx0, 1));
            mx0 = fmaxf(mx0, __shfl_xor_sync(0xffffffffu, mx0, 2));
            mx1 = fmaxf(mx1, __shfl_xor_sync(0xffffffffu, mx1, 1));
            mx1 = fmaxf(mx1, __shfl_xor_sync(0xffffffffu, mx1, 2));
            float mn0 = fmaxf(m10, mx0), mn1 = fmaxf(m11, mx1);
            float al0 = exp2f(m10 - mn0), al1 = exp2f(m11 - mn1);
            float sum0 = 0.f, sum1 = 0.f;
#pragma unroll
            for (int jn = 0; jn < 8; jn++) {
                float p00 = exp2f(sac1[jn][0] - mn0);
                float p01 = exp2f(sac1[jn][1] - mn0);
                float p10 = exp2f(sac1[jn][2] - mn1);
                float p11 = exp2f(sac1[jn][3] - mn1);
                int ci = jn * 4 + tig;
                pp[lr1 * PPW + ci]       = f2bf2(p00, p01);
                pp[(lr1 + 8) * PPW + ci] = f2bf2(p10, p11);
                sum0 += p00 + p01;  sum1 += p10 + p11;
            }
            sum0 += __shfl_xor_sync(0xffffffffu, sum0, 1);
            sum0 += __shfl_xor_sync(0xffffffffu, sum0, 2);
            sum1 += __shfl_xor_sync(0xffffffffu, sum1, 1);
            sum1 += __shfl_xor_sync(0xffffffffu, sum1, 2);
            l10 = l10 * al0 + sum0;  m10 = mn0;
            l11 = l11 * al1 + sum1;  m11 = mn1;
#pragma unroll
            for (int jd = 0; jd < 8; jd++) {
                oac1[jd][0] *= al0; oac1[jd][1] *= al0;
                oac1[jd][2] *= al1; oac1[jd][3] *= al1;
            }
        }
        __syncwarp();

        // ---- O += P V ----
#pragma unroll
        for (int k16 = 0; k16 < 4; k16++) {
            const int vr = k16 * 16 + 2 * tig;
            const int pi = k16 * 8 + tig;
            uint32_t bfr[8][2];
#pragma unroll
            for (int jd = 0; jd < 8; jd++) {
                int dcol = jd * 8 + grp;
                bfr[jd][0] = f2bf2(Vb[vr * FA_PV + dcol],       Vb[(vr + 1) * FA_PV + dcol]);
                bfr[jd][1] = f2bf2(Vb[(vr + 8) * FA_PV + dcol], Vb[(vr + 9) * FA_PV + dcol]);
            }
            uint32_t af0[4], af1[4];
            af0[0] = pp[lr0 * PPW + pi];       af0[1] = pp[(lr0 + 8) * PPW + pi];
            af0[2] = pp[lr0 * PPW + pi + 4];   af0[3] = pp[(lr0 + 8) * PPW + pi + 4];
            af1[0] = pp[lr1 * PPW + pi];       af1[1] = pp[(lr1 + 8) * PPW + pi];
            af1[2] = pp[lr1 * PPW + pi + 4];   af1[3] = pp[(lr1 + 8) * PPW + pi + 4];
#pragma unroll
            for (int jd = 0; jd < 8; jd++) {
                mma_bf16(oac0[jd], af0, bfr[jd]);
                mma_bf16(oac1[jd], af1, bfr[jd]);
            }
        }
    }

    // ---- epilogue ----
    {
        float inv0 = 1.f / l00, inv1 = 1.f / l01;
        float* og  = o + (((size_t)(b * Sq + q0 + lr0) * Hh + h) << 6);
        float* og8 = og + (size_t)8 * 1024;
#pragma unroll
        for (int jd = 0; jd < 8; jd++) {
            int c = jd * 8 + 2 * tig;
            *reinterpret_cast<float2*>(og + c)  = make_float2(oac0[jd][0] * inv0, oac0[jd][1] * inv0);
            *reinterpret_cast<float2*>(og8 + c) = make_float2(oac0[jd][2] * inv1, oac0[jd][3] * inv1);
        }
    }
    {
        float inv0 = 1.f / l10, inv1 = 1.f / l11;
        float* og  = o + (((size_t)(b * Sq + q0 + lr1) * Hh + h) << 6);
        float* og8 = og + (size_t)8 * 1024;
#pragma unroll
        for (int jd = 0; jd < 8; jd++) {
            int c = jd * 8 + 2 * tig;
            *reinterpret_cast<float2*>(og + c)  = make_float2(oac1[jd][0] * inv0, oac1[jd][1] * inv0);
            *reinterpret_cast<float2*>(og8 + c) = make_float2(oac1[jd][2] * inv1, oac1[jd][3] * inv1);
        }
    }
}

// ========= fused LN1 + quantum FFN + LN2 (2-wire fused gates) =========
__global__ __launch_bounds__(256) void ln_quantum(const float* __restrict__ x,
                                                  const float* __restrict__ proj,
                                                  const float* __restrict__ g1,
                                                  const float* __restrict__ b1,
                                                  const float* __restrict__ Win,
                                                  const float* __restrict__ b_in,
                                                  const float* __restrict__ Wout,
                                                  const float* __restrict__ b_out,
                                                  const float* __restrict__ ry,
                                                  const float* __restrict__ g2,
                                                  const float* __restrict__ b2,
                                                  float* __restrict__ out)
{
    const int row = blockIdx.x;
    const int tid = threadIdx.x;
    const int lane = tid & 31, wid = tid >> 5;
    const float* px = x + (size_t)row * Dm;
    const float* pprj = proj + (size_t)row * Dm;

    __shared__ float redw[64];
    __shared__ float angs[8];
    __shared__ float ezs[8];
    __shared__ float2 st[2][DIMq];

    float xv[4];
    {
        float yv[4], sum = 0.f, sq = 0.f;
#pragma unroll
        for (int j = 0; j < 4; j++) {
            int d = tid + (j << 8);
            float t = px[d] + pprj[d];
            yv[j] = t; sum += t; sq = fmaf(t, t, sq);
        }
#pragma unroll
        for (int off = 16; off; off >>= 1) {
            sum += __shfl_xor_sync(0xffffffffu, sum, off);
            sq  += __shfl_xor_sync(0xffffffffu, sq, off);
        }
        if (lane == 0) { redw[wid] = sum; redw[8 + wid] = sq; }
        __syncthreads();
        float tsum = 0.f, tsq = 0.f;
#pragma unroll
        for (int w = 0; w < 8; w++) { tsum += redw[w]; tsq += redw[8 + w]; }
        float mean = tsum * (1.f / 1024.f);
        float var  = tsq * (1.f / 1024.f) - mean * mean;
        float rstd = rsqrtf(var + EPSf);
#pragma unroll
        for (int j = 0; j < 4; j++) {
            int d = tid + (j << 8);
            xv[j] = (yv[j] - mean) * rstd * g1[d] + b1[d];
        }
        __syncthreads();
    }

    float accq[8] = {0, 0, 0, 0, 0, 0, 0, 0};
#pragma unroll
    for (int j = 0; j < 4; j++) {
        int d = tid + (j << 8);
#pragma unroll
        for (int qq = 0; qq < 8; qq++)
            accq[qq] = fmaf(xv[j], Win[qq * Dm + d], accq[qq]);
    }
#pragma unroll
    for (int qq = 0; qq < 8; qq++) {
        float vsum = accq[qq];
#pragma unroll
        for (int off = 16; off; off >>= 1)
            vsum += __shfl_xor_sync(0xffffffffu, vsum, off);
        if (lane == 0) redw[wid * 8 + qq] = vsum;
    }
    __syncthreads();
    if (tid < 8) {
        float s = b_in[tid];
#pragma unroll
        for (int w = 0; w < 8; w++) s += redw[w * 8 + tid];
        angs[tid] = s * 0.5f;
    }
    st[0][tid] = make_float2(tid == 0 ? 1.f : 0.f, 0.f);
    __syncthreads();

    int curb = 0;
    // ---- RX gates, 2 wires per stage (wires 2k, 2k+1) ----
#pragma unroll
    for (int k = 0; k < 4; k++) {
        int m1 = 1 << (7 - 2 * k);
        int m2 = m1 >> 1;
        float s1, c1, s2, c2;
        __sincosf(angs[2 * k], &s1, &c1);
        __sincosf(angs[2 * k + 1], &s2, &c2);
        float cc = c1 * c2, cs = c1 * s2, sc = s1 * c2, ss = s1 * s2;
        float2 x0  = st[curb][tid];
        float2 x1  = st[curb][tid ^ m1];
        float2 x2  = st[curb][tid ^ m2];
        float2 x12 = st[curb][tid ^ (m1 | m2)];
        float nr = cc * x0.x + cs * x2.y + sc * x1.y - ss * x12.x;
        float ni = cc * x0.y - cs * x2.x - sc * x1.x - ss * x12.y;
        st[curb ^ 1][tid] = make_float2(nr, ni);
        curb ^= 1;
        __syncthreads();
    }
    // ---- RY gates, 2 wires per stage ----
#pragma unroll
    for (int k = 0; k < 4; k++) {
        int m1 = 1 << (7 - 2 * k);
        int m2 = m1 >> 1;
        float s1, c1, s2, c2;
        __sincosf(ry[2 * k] * 0.5f, &s1, &c1);
        __sincosf(ry[2 * k + 1] * 0.5f, &s2, &c2);
        float sg1 = (tid & m1) ? s1 : -s1;
        float sg2 = (tid & m2) ? s2 : -s2;
        float cc = c1 * c2, a2 = c1 * sg2, a1 = sg1 * c2, a12 = sg1 * sg2;
        float2 x0  = st[curb][tid];
        float2 x1  = st[curb][tid ^ m1];
        float2 x2  = st[curb][tid ^ m2];
        float2 x12 = st[curb][tid ^ (m1 | m2)];
        float nr = cc * x0.x + a2 * x2.x + a1 * x1.x + a12 * x12.x;
        float ni = cc * x0.y + a2 * x2.y + a1 * x1.y + a12 * x12.y;
        st[curb ^ 1][tid] = make_float2(nr, ni);
        curb ^= 1;
        __syncthreads();
    }
    int src = tid;
#pragma unroll
    for (int c = 6; c >= 0; c--) {
        int cmask = 1 << (7 - c);
        int tmask = cmask >> 1;
        if (src & cmask) src ^= tmask;
    }
    float2 fa = st[curb][src];
    float p = fa.x * fa.x + fa.y * fa.y;

#pragma unroll
    for (int w = 0; w < 8; w++) {
        float vsum = ((tid >> (7 - w)) & 1) ? -p : p;
#pragma unroll
        for (int off = 16; off; off >>= 1)
            vsum += __shfl_xor_sync(0xffffffffu, vsum, off);
        if (lane == 0) redw[wid * 8 + w] = vsum;
    }
    __syncthreads();
    if (tid < 8) {
        float s = 0.f;
#pragma unroll
        for (int w = 0; w < 8; w++) s += redw[w * 8 + tid];
        ezs[tid] = s;
    }
    __syncthreads();
    float e[8];
#pragma unroll
    for (int qq = 0; qq < 8; qq++) e[qq] = ezs[qq];

    float y[4], sum = 0.f, sq = 0.f;
#pragma unroll
    for (int j = 0; j < 4; j++) {
        int d = tid + (j << 8);
        const float4* wrow = reinterpret_cast<const float4*>(Wout + (size_t)d * 8);
        float4 w0 = wrow[0], w1 = wrow[1];
        float acc = b_out[d];
        acc = fmaf(e[0], w0.x, acc); acc = fmaf(e[1], w0.y, acc);
        acc = fmaf(e[2], w0.z, acc); acc = fmaf(e[3], w0.w, acc);
        acc = fmaf(e[4], w1.x, acc); acc = fmaf(e[5], w1.y, acc);
        acc = fmaf(e[6], w1.z, acc); acc = fmaf(e[7], w1.w, acc);
        acc = fmaxf(acc, 0.f);
        float yv = xv[j] + acc;
        y[j] = yv; sum += yv; sq = fmaf(yv, yv, sq);
    }
    __syncthreads();
#pragma unroll
    for (int off = 16; off; off >>= 1) {
        sum += __shfl_xor_sync(0xffffffffu, sum, off);
        sq  += __shfl_xor_sync(0xffffffffu, sq, off);
    }
    if (lane == 0) { redw[wid] = sum; redw[8 + wid] = sq; }
    __syncthreads();
    float tsum = 0.f, tsq = 0.f;
#pragma unroll
    for (int w = 0; w < 8; w++) { tsum += redw[w]; tsq += redw[8 + w]; }
    float mean = tsum * (1.f / 1024.f);
    float var  = tsq * (1.f / 1024.f) - mean * mean;
    float rstd = rsqrtf(var + EPSf);
#pragma unroll
    for (int j = 0; j < 4; j++) {
        int d = tid + (j << 8);
        out[(size_t)row * Dm + d] = (y[j] - mean) * rstd * g2[d] + b2[d];
    }
}

// ---------------- launch ----------------
extern "C" void kernel_launch(void* const* d_in, const int* in_sizes, int n_in,
                              void* d_out, int out_size)
{
    const float* x     = (const float*)d_in[0];
    const float* Wq    = (const float*)d_in[1];
    const float* Wk    = (const float*)d_in[2];
    const float* Wv    = (const float*)d_in[3];
    const float* Wo    = (const float*)d_in[4];
    const float* g1    = (const float*)d_in[5];
    const float* b1    = (const float*)d_in[6];
    const float* g2    = (const float*)d_in[7];
    const float* b2    = (const float*)d_in[8];
    const float* Win   = (const float*)d_in[9];
    const float* b_in  = (const float*)d_in[10];
    const float* Wout  = (const float*)d_in[11];
    const float* b_out = (const float*)d_in[12];
    const float* ry    = (const float*)d_in[13];
    float* out = (float*)d_out;

    uint32_t *qp, *kp;
    float *v, *o, *proj;
    cudaGetSymbolAddress((void**)&qp,   g_qp);
    cudaGetSymbolAddress((void**)&kp,   g_kp);
    cudaGetSymbolAddress((void**)&v,    g_v);
    cudaGetSymbolAddress((void**)&o,    g_o);
    cudaGetSymbolAddress((void**)&proj, g_proj);

    cudaFuncSetAttribute(gemm_mma,  cudaFuncAttributeMaxDynamicSharedMemorySize, GSMEM);
    cudaFuncSetAttribute(gemm_qkv,  cudaFuncAttributeMaxDynamicSharedMemorySize, GSMEM);
    cudaFuncSetAttribute(flash_mma, cudaFuncAttributeMaxDynamicSharedMemorySize, FA_SMEM);

    gemm_qkv<<<dim3(Dm / BN, Mtot / BM, 3), 256, GSMEM>>>(x, Wq, Wk, Wv, qp, kp, v);
    flash_mma<<<dim3(Sq / 256, Hh, Bsz), 256, FA_SMEM>>>(qp, kp, v, o);
    gemm_mma<<<dim3(Dm / BN, Mtot / BM), 256, GSMEM>>>(o, Wo, proj);
    ln_quantum<<<Mtot, 256>>>(x, proj, g1, b1, Win, b_in, Wout, b_out, ry, g2, b2, out);
}

// round 12
// speedup vs baseline: 2.1076x; 1.1692x over previous
#include <cuda_runtime.h>
#include <math.h>
#include <cstdint>

#define Bsz   2
#define Sq    2048
#define Dm    1024
#define Hh    16
#define Mtot  4096
#define DIMq  256
#define EPSf  1e-5f
#define LOG2E 1.44269504088896f

// ---------------- scratch ----------------
__device__ uint32_t g_xp[Mtot * 512];   // packed x
__device__ uint32_t g_qp[Mtot * 512];   // packed Q (pre-scaled)
__device__ uint32_t g_kp[Mtot * 512];   // packed K
__device__ float    g_v [Mtot * Dm];    // V fp32
__device__ uint32_t g_vt[Mtot * 512];   // V transposed+packed: [(b*Hh+h)*64+d]*1024 + kvpair
__device__ uint32_t g_op[Mtot * 512];   // packed attention output
__device__ float    g_proj[Mtot * Dm];

// ======================= helpers =======================
__device__ __forceinline__ uint32_t smem_to_u32(const void* p) {
    uint32_t a;
    asm("{ .reg .u64 t; cvta.to.shared.u64 t, %1; cvt.u32.u64 %0, t; }" : "=r"(a) : "l"(p));
    return a;
}
__device__ __forceinline__ void cp16(uint32_t sm, const void* g) {
    asm volatile("cp.async.cg.shared.global [%0], [%1], 16;" :: "r"(sm), "l"(g));
}
__device__ __forceinline__ void cp_commit() {
    asm volatile("cp.async.commit_group;");
}
template <int N>
__device__ __forceinline__ void cp_wait() {
    asm volatile("cp.async.wait_group %0;" :: "n"(N));
}
__device__ __forceinline__ uint32_t f2bf2(float lo, float hi) {
    uint32_t r;
    asm("cvt.rn.bf16x2.f32 %0, %1, %2;" : "=r"(r) : "f"(hi), "f"(lo));
    return r;
}
__device__ __forceinline__ void mma_bf16(float c[4], const uint32_t a[4], const uint32_t b[2]) {
    asm volatile(
        "mma.sync.aligned.m16n8k16.row.col.f32.bf16.bf16.f32 "
        "{%0,%1,%2,%3}, {%4,%5,%6,%7}, {%8,%9}, {%0,%1,%2,%3};"
        : "+f"(c[0]), "+f"(c[1]), "+f"(c[2]), "+f"(c[3])
        : "r"(a[0]), "r"(a[1]), "r"(a[2]), "r"(a[3]), "r"(b[0]), "r"(b[1]));
}

// ================= pack x -> bf16x2 =================
__global__ __launch_bounds__(256) void pack_x(const float4* __restrict__ x4,
                                              uint4* __restrict__ xp4)
{
    int idx = blockIdx.x * 256 + threadIdx.x;       // 524288 uint4 total
    float4 a = x4[idx * 2];
    float4 b = x4[idx * 2 + 1];
    uint4 w;
    w.x = f2bf2(a.x, a.y); w.y = f2bf2(a.z, a.w);
    w.z = f2bf2(b.x, b.y); w.w = f2bf2(b.z, b.w);
    xp4[idx] = w;
}

// ======= V transpose+pack: g_v[token, h*64+d] -> g_vt[(bh*64+d)*1024 + kp] =======
__global__ __launch_bounds__(256) void vtrans(const float* __restrict__ v,
                                              uint32_t* __restrict__ vt)
{
    __shared__ float sm[64 * 65 + 16];   // sm[d*65 + tok]
    const int tid = threadIdx.x;
    const int kt = blockIdx.x, h = blockIdx.y, b = blockIdx.z;
    const float* vg = v + (size_t)(b * Sq + kt * 64) * 1024 + h * 64;

#pragma unroll
    for (int i = 0; i < 4; i++) {
        int e = tid + (i << 8);
        int r = e >> 4, c4 = (e & 15) << 2;          // token r, d cols c4..c4+3
        float4 vv = *reinterpret_cast<const float4*>(vg + (size_t)r * 1024 + c4);
        sm[(c4 + 0) * 65 + r] = vv.x;
        sm[(c4 + 1) * 65 + r] = vv.y;
        sm[(c4 + 2) * 65 + r] = vv.z;
        sm[(c4 + 3) * 65 + r] = vv.w;
    }
    __syncthreads();

    uint32_t* og = vt + ((size_t)(b * Hh + h) * 64) * 1024 + kt * 32;
#pragma unroll
    for (int i = 0; i < 8; i++) {
        int idx = tid + (i << 8);                    // 2048 outputs
        int d = idx >> 5, kp = idx & 31;
        og[(size_t)d * 1024 + kp] = f2bf2(sm[d * 65 + 2 * kp], sm[d * 65 + 2 * kp + 1]);
    }
}

// ============ bf16 GEMM, packed A: C = Ap[M,512] * W[1024,1024]^T ============
#define BM 128
#define BN 256
#define LDP 36
#define PAW 20
#define PA_STAGE_B (BM * PAW * 4)            // 10240
#define PB_STAGE_B (BN * LDP * 4)            // 36864
#define GPSMEM (3 * (PA_STAGE_B + PB_STAGE_B))  // 141312
#define NKT (Dm / 32)

__device__ __forceinline__ void gemm_pa(const uint32_t* __restrict__ Ap,
                                        const float* __restrict__ W,
                                        float* __restrict__ Cf,
                                        uint32_t* __restrict__ Cp,
                                        int outmode, float scale,
                                        char* gsm)
{
    const uint32_t usm = smem_to_u32(gsm);
    const uint32_t usmA = usm;
    const uint32_t usmB = usm + 3 * PA_STAGE_B;

    const int tid  = threadIdx.x;
    const int wid  = tid >> 5;
    const int lane = tid & 31;
    const int grp  = lane >> 2;
    const int tig  = lane & 3;
    const int wm   = wid >> 2;
    const int wn   = wid & 3;

    const int aRow0 = blockIdx.y * BM;
    const int bRow0 = blockIdx.x * BN;

    int aSm[2], aGm[2], bSm[8], bGm[8];
#pragma unroll
    for (int i = 0; i < 2; i++) {
        int e = tid + (i << 8);
        int r = e >> 2, c4 = (e & 3) << 2;
        aSm[i] = (r * PAW + c4) * 4;
        aGm[i] = r * 512 + c4;
    }
#pragma unroll
    for (int i = 0; i < 8; i++) {
        int e = tid + (i << 8);
        int r = e >> 3, c4 = (e & 7) << 2;
        bSm[i] = (r * LDP + c4) * 4;
        bGm[i] = r * Dm + c4;
    }
    const uint32_t* gA = Ap + (size_t)aRow0 * 512;
    const float*    gB = W + (size_t)bRow0 * Dm;

    float acc[4][8][4];
#pragma unroll
    for (int im = 0; im < 4; im++)
#pragma unroll
        for (int jn = 0; jn < 8; jn++)
#pragma unroll
            for (int t = 0; t < 4; t++) acc[im][jn][t] = 0.f;

#pragma unroll
    for (int p = 0; p < 2; p++) {
        uint32_t sa = usmA + p * PA_STAGE_B;
        uint32_t sb = usmB + p * PB_STAGE_B;
        const uint32_t* ka = gA + p * 16;
        const float*    kb = gB + p * 32;
#pragma unroll
        for (int i = 0; i < 2; i++) cp16(sa + aSm[i], ka + aGm[i]);
#pragma unroll
        for (int i = 0; i < 8; i++) cp16(sb + bSm[i], kb + bGm[i]);
        cp_commit();
    }

    for (int kt = 0; kt < NKT; kt++) {
        cp_wait<1>();
        __syncthreads();

        if (kt + 2 < NKT) {
            int s = (kt + 2) % 3;
            uint32_t sa = usmA + s * PA_STAGE_B;
            uint32_t sb = usmB + s * PB_STAGE_B;
            const uint32_t* ka = gA + (kt + 2) * 16;
            const float*    kb = gB + (kt + 2) * 32;
#pragma unroll
            for (int i = 0; i < 2; i++) cp16(sa + aSm[i], ka + aGm[i]);
#pragma unroll
            for (int i = 0; i < 8; i++) cp16(sb + bSm[i], kb + bGm[i]);
        }
        cp_commit();

        const uint32_t* Asp = (const uint32_t*)(gsm + (kt % 3) * PA_STAGE_B);
        const float*    Bs  = (const float*)(gsm + 3 * PA_STAGE_B + (kt % 3) * PB_STAGE_B);

#pragma unroll
        for (int k16 = 0; k16 < 2; k16++) {
            const int pi = k16 * 8 + tig;
            const int kb = k16 * 16 + 2 * tig;
            uint32_t afr[4][4], bfr[8][2];
#pragma unroll
            for (int im = 0; im < 4; im++) {
                int row = wm * 64 + im * 16 + grp;
                afr[im][0] = Asp[row * PAW + pi];
                afr[im][1] = Asp[(row + 8) * PAW + pi];
                afr[im][2] = Asp[row * PAW + pi + 4];
                afr[im][3] = Asp[(row + 8) * PAW + pi + 4];
            }
#pragma unroll
            for (int jn = 0; jn < 8; jn++) {
                int brow = wn * 64 + jn * 8 + grp;
                float2 b0 = *reinterpret_cast<const float2*>(Bs + brow * LDP + kb);
                float2 b8 = *reinterpret_cast<const float2*>(Bs + brow * LDP + kb + 8);
                bfr[jn][0] = f2bf2(b0.x, b0.y);
                bfr[jn][1] = f2bf2(b8.x, b8.y);
            }
#pragma unroll
            for (int im = 0; im < 4; im++)
#pragma unroll
                for (int jn = 0; jn < 8; jn++)
                    mma_bf16(acc[im][jn], afr[im], bfr[jn]);
        }
    }

    const int rowBase = aRow0 + wm * 64;
    const int colBase = bRow0 + wn * 64;
    if (outmode == 0) {
#pragma unroll
        for (int im = 0; im < 4; im++) {
            int r0 = rowBase + im * 16 + grp;
#pragma unroll
            for (int jn = 0; jn < 8; jn++) {
                int col = colBase + jn * 8 + 2 * tig;
                float2 v01 = make_float2(acc[im][jn][0], acc[im][jn][1]);
                float2 v23 = make_float2(acc[im][jn][2], acc[im][jn][3]);
                *reinterpret_cast<float2*>(Cf + (size_t)r0 * Dm + col) = v01;
                *reinterpret_cast<float2*>(Cf + (size_t)(r0 + 8) * Dm + col) = v23;
            }
        }
    } else {
#pragma unroll
        for (int im = 0; im < 4; im++) {
            int r0 = rowBase + im * 16 + grp;
#pragma unroll
            for (int jn = 0; jn < 8; jn++) {
                int col = colBase + jn * 8 + 2 * tig;
                Cp[(size_t)r0 * 512 + (col >> 1)] =
                    f2bf2(acc[im][jn][0] * scale, acc[im][jn][1] * scale);
                Cp[(size_t)(r0 + 8) * 512 + (col >> 1)] =
                    f2bf2(acc[im][jn][2] * scale, acc[im][jn][3] * scale);
            }
        }
    }
}

__global__ __launch_bounds__(256, 1) void gemm_qkv(const uint32_t* __restrict__ Ap,
                                                   const float* __restrict__ W0,
                                                   const float* __restrict__ W1,
                                                   const float* __restrict__ W2,
                                                   uint32_t* __restrict__ Qp,
                                                   uint32_t* __restrict__ Kp,
                                                   float* __restrict__ Vf)
{
    extern __shared__ __align__(16) char gsm[];
    const int z = blockIdx.z;
    if (z == 0)      gemm_pa(Ap, W0, nullptr, Qp, 1, 0.125f * LOG2E, gsm);
    else if (z == 1) gemm_pa(Ap, W1, nullptr, Kp, 1, 1.f, gsm);
    else             gemm_pa(Ap, W2, Vf, nullptr, 0, 1.f, gsm);
}

__global__ __launch_bounds__(256, 1) void gemm_wo(const uint32_t* __restrict__ Ap,
                                                  const float* __restrict__ W,
                                                  float* __restrict__ C)
{
    extern __shared__ __align__(16) char gsm[];
    gemm_pa(Ap, W, C, nullptr, 0, 1.f, gsm);
}

// ============ Flash attention: all operands packed bf16x2 ================
// smem (u32): Qp 256x36 | Pp 256x36 | Kp 3x64x36 | Vp 3x64x36
#define PPW   36
#define KPW   36
#define QP_OFF 0
#define PP_OFF (256 * PPW)                   // 9216
#define KP_OFF (2 * 256 * PPW)               // 18432
#define KP_STRIDE (64 * KPW)                 // 2304
#define VP_OFF (KP_OFF + 3 * KP_STRIDE)      // 25344
#define FA_SMEM ((VP_OFF + 3 * KP_STRIDE) * 4)  // 129024 B
#define NKV (Sq / 64)

__global__ __launch_bounds__(256, 1) void flash_mma(const uint32_t* __restrict__ qpg,
                                                    const uint32_t* __restrict__ kpg,
                                                    const uint32_t* __restrict__ vtg_all,
                                                    uint32_t* __restrict__ op)
{
    extern __shared__ __align__(16) uint32_t fsu[];
    const uint32_t usm = smem_to_u32(fsu);
    uint32_t* qp = fsu + QP_OFF;
    uint32_t* pp = fsu + PP_OFF;
    const uint32_t* kp = fsu + KP_OFF;
    const uint32_t* vp = fsu + VP_OFF;

    const int tid  = threadIdx.x;
    const int wid  = tid >> 5;
    const int lane = tid & 31;
    const int grp  = lane >> 2;
    const int tig  = lane & 3;

    const int b  = blockIdx.z;
    const int h  = blockIdx.y;
    const int q0 = blockIdx.x << 8;

    const uint32_t* qg  = qpg + (size_t)(b * Sq + q0) * 512 + h * 32;
    const uint32_t* kg  = kpg + (size_t)(b * Sq) * 512 + h * 32;
    const uint32_t* vtg = vtg_all + ((size_t)(b * Hh + h) * 64) * 1024;

    // ---- prologue: {K0,V0,Q} group0; {K1,V1} group1 ----
    {
#pragma unroll
        for (int i = 0; i < 2; i++) {
            int e = tid + (i << 8);
            int r = e >> 3, c4 = (e & 7) << 2;
            cp16(usm + (KP_OFF + r * KPW + c4) * 4, kg + (size_t)r * 512 + c4);
            cp16(usm + (VP_OFF + r * KPW + c4) * 4, vtg + (size_t)r * 1024 + c4);
        }
#pragma unroll
        for (int i = 0; i < 8; i++) {
            int e = tid + (i << 8);
            int r = e >> 3, c4 = (e & 7) << 2;
            cp16(usm + (QP_OFF + r * PPW + c4) * 4, qg + (size_t)r * 512 + c4);
        }
        cp_commit();
#pragma unroll
        for (int i = 0; i < 2; i++) {
            int e = tid + (i << 8);
            int r = e >> 3, c4 = (e & 7) << 2;
            cp16(usm + (KP_OFF + KP_STRIDE + r * KPW + c4) * 4, kg + (size_t)(64 + r) * 512 + c4);
            cp16(usm + (VP_OFF + KP_STRIDE + r * KPW + c4) * 4, vtg + (size_t)r * 1024 + 32 + c4);
        }
        cp_commit();
    }

    const int lr0 = wid * 32 + grp;
    const int lr1 = lr0 + 16;

    float m00 = -1e30f, m01 = -1e30f, m10 = -1e30f, m11 = -1e30f;
    float l00 = 0.f, l01 = 0.f, l10 = 0.f, l11 = 0.f;
    float oac0[8][4], oac1[8][4];
#pragma unroll
    for (int jd = 0; jd < 8; jd++)
#pragma unroll
        for (int t = 0; t < 4; t++) { oac0[jd][t] = 0.f; oac1[jd][t] = 0.f; }

    for (int it = 0; it < NKV; it++) {
        cp_wait<1>();
        __syncthreads();   // stage it ready; buffer (it+2)%3 free

        if (it + 2 < NKV) {
            int s = (it + 2) % 3;
            int kv0 = (it + 2) << 6;
            int kv32 = (it + 2) << 5;
#pragma unroll
            for (int i = 0; i < 2; i++) {
                int e = tid + (i << 8);
                int r = e >> 3, c4 = (e & 7) << 2;
                cp16(usm + (KP_OFF + s * KP_STRIDE + r * KPW + c4) * 4,
                     kg + (size_t)(kv0 + r) * 512 + c4);
                cp16(usm + (VP_OFF + s * KP_STRIDE + r * KPW + c4) * 4,
                     vtg + (size_t)r * 1024 + kv32 + c4);
            }
        }
        cp_commit();

        const uint32_t* Kb = kp + (it % 3) * KP_STRIDE;
        const uint32_t* Vb = vp + (it % 3) * KP_STRIDE;

        // ---- S = Q K^T (all LDS.32, zero cvt) ----
        float sac0[8][4], sac1[8][4];
#pragma unroll
        for (int jn = 0; jn < 8; jn++)
#pragma unroll
            for (int t = 0; t < 4; t++) { sac0[jn][t] = 0.f; sac1[jn][t] = 0.f; }
#pragma unroll
        for (int k16 = 0; k16 < 4; k16++) {
            const int pi = k16 * 8 + tig;
            uint32_t bfr[8][2];
#pragma unroll
            for (int jn = 0; jn < 8; jn++) {
                int krow = jn * 8 + grp;
                bfr[jn][0] = Kb[krow * KPW + pi];
                bfr[jn][1] = Kb[krow * KPW + pi + 4];
            }
            uint32_t af0[4], af1[4];
            af0[0] = qp[lr0 * PPW + pi];       af0[1] = qp[(lr0 + 8) * PPW + pi];
            af0[2] = qp[lr0 * PPW + pi + 4];   af0[3] = qp[(lr0 + 8) * PPW + pi + 4];
            af1[0] = qp[lr1 * PPW + pi];       af1[1] = qp[(lr1 + 8) * PPW + pi];
            af1[2] = qp[lr1 * PPW + pi + 4];   af1[3] = qp[(lr1 + 8) * PPW + pi + 4];
#pragma unroll
            for (int jn = 0; jn < 8; jn++) {
                mma_bf16(sac0[jn], af0, bfr[jn]);
                mma_bf16(sac1[jn], af1, bfr[jn]);
            }
        }

        // ---- online softmax (base-2) ----
        {
            float mx0 = -1e30f, mx1 = -1e30f;
#pragma unroll
            for (int jn = 0; jn < 8; jn++) {
                mx0 = fmaxf(mx0, fmaxf(sac0[jn][0], sac0[jn][1]));
                mx1 = fmaxf(mx1, fmaxf(sac0[jn][2], sac0[jn][3]));
            }
            mx0 = fmaxf(mx0, __shfl_xor_sync(0xffffffffu, mx0, 1));
            mx0 = fmaxf(mx0, __shfl_xor_sync(0xffffffffu, mx0, 2));
            mx1 = fmaxf(mx1, __shfl_xor_sync(0xffffffffu, mx1, 1));
            mx1 = fmaxf(mx1, __shfl_xor_sync(0xffffffffu, mx1, 2));
            float mn0 = fmaxf(m00, mx0), mn1 = fmaxf(m01, mx1);
            float al0 = exp2f(m00 - mn0), al1 = exp2f(m01 - mn1);
            float sum0 = 0.f, sum1 = 0.f;
#pragma unroll
            for (int jn = 0; jn < 8; jn++) {
                float p00 = exp2f(sac0[jn][0] - mn0);
                float p01 = exp2f(sac0[jn][1] - mn0);
                float p10 = exp2f(sac0[jn][2] - mn1);
                float p11 = exp2f(sac0[jn][3] - mn1);
                int ci = jn * 4 + tig;
                pp[lr0 * PPW + ci]       = f2bf2(p00, p01);
                pp[(lr0 + 8) * PPW + ci] = f2bf2(p10, p11);
                sum0 += p00 + p01;  sum1 += p10 + p11;
            }
            sum0 += __shfl_xor_sync(0xffffffffu, sum0, 1);
            sum0 += __shfl_xor_sync(0xffffffffu, sum0, 2);
            sum1 += __shfl_xor_sync(0xffffffffu, sum1, 1);
            sum1 += __shfl_xor_sync(0xffffffffu, sum1, 2);
            l00 = l00 * al0 + sum0;  m00 = mn0;
            l01 = l01 * al1 + sum1;  m01 = mn1;
#pragma unroll
            for (int jd = 0; jd < 8; jd++) {
                oac0[jd][0] *= al0; oac0[jd][1] *= al0;
                oac0[jd][2] *= al1; oac0[jd][3] *= al1;
            }
        }
        {
            float mx0 = -1e30f, mx1 = -1e30f;
#pragma unroll
            for (int jn = 0; jn < 8; jn++) {
                mx0 = fmaxf(mx0, fmaxf(sac1[jn][0], sac1[jn][1]));
                mx1 = fmaxf(mx1, fmaxf(sac1[jn][2], sac1[jn][3]));
            }
            mx0 = fmaxf(mx0, __shfl_xor_sync(0xffffffffu, mx0, 1));
            mx0 = fmaxf(mx0, __shfl_xor_sync(0xffffffffu, mx0, 2));
            mx1 = fmaxf(mx1, __shfl_xor_sync(0xffffffffu, mx1, 1));
            mx1 = fmaxf(mx1, __shfl_xor_sync(0xffffffffu, mx1, 2));
            float mn0 = fmaxf(m10, mx0), mn1 = fmaxf(m11, mx1);
            float al0 = exp2f(m10 - mn0), al1 = exp2f(m11 - mn1);
            float sum0 = 0.f, sum1 = 0.f;
#pragma unroll
            for (int jn = 0; jn < 8; jn++) {
                float p00 = exp2f(sac1[jn][0] - mn0);
                float p01 = exp2f(sac1[jn][1] - mn0);
                float p10 = exp2f(sac1[jn][2] - mn1);
                float p11 = exp2f(sac1[jn][3] - mn1);
                int ci = jn * 4 + tig;
                pp[lr1 * PPW + ci]       = f2bf2(p00, p01);
                pp[(lr1 + 8) * PPW + ci] = f2bf2(p10, p11);
                sum0 += p00 + p01;  sum1 += p10 + p11;
            }
            sum0 += __shfl_xor_sync(0xffffffffu, sum0, 1);
            sum0 += __shfl_xor_sync(0xffffffffu, sum0, 2);
            sum1 += __shfl_xor_sync(0xffffffffu, sum1, 1);
            sum1 += __shfl_xor_sync(0xffffffffu, sum1, 2);
            l10 = l10 * al0 + sum0;  m10 = mn0;
            l11 = l11 * al1 + sum1;  m11 = mn1;
#pragma unroll
            for (int jd = 0; jd < 8; jd++) {
                oac1[jd][0] *= al0; oac1[jd][1] *= al0;
                oac1[jd][2] *= al1; oac1[jd][3] *= al1;
            }
        }
        __syncwarp();

        // ---- O += P V (all LDS.32, zero cvt) ----
#pragma unroll
        for (int k16 = 0; k16 < 4; k16++) {
            const int pi = k16 * 8 + tig;
            uint32_t bfr[8][2];
#pragma unroll
            for (int jd = 0; jd < 8; jd++) {
                int dcol = jd * 8 + grp;
                bfr[jd][0] = Vb[dcol * KPW + pi];
                bfr[jd][1] = Vb[dcol * KPW + pi + 4];
            }
            uint32_t af0[4], af1[4];
            af0[0] = pp[lr0 * PPW + pi];       af0[1] = pp[(lr0 + 8) * PPW + pi];
            af0[2] = pp[lr0 * PPW + pi + 4];   af0[3] = pp[(lr0 + 8) * PPW + pi + 4];
            af1[0] = pp[lr1 * PPW + pi];       af1[1] = pp[(lr1 + 8) * PPW + pi];
            af1[2] = pp[lr1 * PPW + pi + 4];   af1[3] = pp[(lr1 + 8) * PPW + pi + 4];
#pragma unroll
            for (int jd = 0; jd < 8; jd++) {
                mma_bf16(oac0[jd], af0, bfr[jd]);
                mma_bf16(oac1[jd], af1, bfr[jd]);
            }
        }
    }

    // ---- epilogue: packed bf16x2 output ----
    {
        float inv0 = 1.f / l00, inv1 = 1.f / l01;
        uint32_t* og  = op + (size_t)(b * Sq + q0 + lr0) * 512 + h * 32;
        uint32_t* og8 = og + (size_t)8 * 512;
#pragma unroll
        for (int jd = 0; jd < 8; jd++) {
            og[jd * 4 + tig]  = f2bf2(oac0[jd][0] * inv0, oac0[jd][1] * inv0);
            og8[jd * 4 + tig] = f2bf2(oac0[jd][2] * inv1, oac0[jd][3] * inv1);
        }
    }
    {
        float inv0 = 1.f / l10, inv1 = 1.f / l11;
        uint32_t* og  = op + (size_t)(b * Sq + q0 + lr1) * 512 + h * 32;
        uint32_t* og8 = og + (size_t)8 * 512;
#pragma unroll
        for (int jd = 0; jd < 8; jd++) {
            og[jd * 4 + tig]  = f2bf2(oac1[jd][0] * inv0, oac1[jd][1] * inv0);
            og8[jd * 4 + tig] = f2bf2(oac1[jd][2] * inv1, oac1[jd][3] * inv1);
        }
    }
}

// ========= fused LN1 + quantum FFN + LN2 (2-wire fused gates, R11-proven) =========
__global__ __launch_bounds__(256) void ln_quantum(const float* __restrict__ x,
                                                  const float* __restrict__ proj,
                                                  const float* __restrict__ g1,
                                                  const float* __restrict__ b1,
                                                  const float* __restrict__ Win,
                                                  const float* __restrict__ b_in,
                                                  const float* __restrict__ Wout,
                                                  const float* __restrict__ b_out,
                                                  const float* __restrict__ ry,
                                                  const float* __restrict__ g2,
                                                  const float* __restrict__ b2,
                                                  float* __restrict__ out)
{
    const int row = blockIdx.x;
    const int tid = threadIdx.x;
    const int lane = tid & 31, wid = tid >> 5;
    const float* px = x + (size_t)row * Dm;
    const float* pprj = proj + (size_t)row * Dm;

    __shared__ float redw[64];
    __shared__ float angs[8];
    __shared__ float ezs[8];
    __shared__ float2 st[2][DIMq];

    float xv[4];
    {
        float yv[4], sum = 0.f, sq = 0.f;
#pragma unroll
        for (int j = 0; j < 4; j++) {
            int d = tid + (j << 8);
            float t = px[d] + pprj[d];
            yv[j] = t; sum += t; sq = fmaf(t, t, sq);
        }
#pragma unroll
        for (int off = 16; off; off >>= 1) {
            sum += __shfl_xor_sync(0xffffffffu, sum, off);
            sq  += __shfl_xor_sync(0xffffffffu, sq, off);
        }
        if (lane == 0) { redw[wid] = sum; redw[8 + wid] = sq; }
        __syncthreads();
        float tsum = 0.f, tsq = 0.f;
#pragma unroll
        for (int w = 0; w < 8; w++) { tsum += redw[w]; tsq += redw[8 + w]; }
        float mean = tsum * (1.f / 1024.f);
        float var  = tsq * (1.f / 1024.f) - mean * mean;
        float rstd = rsqrtf(var + EPSf);
#pragma unroll
        for (int j = 0; j < 4; j++) {
            int d = tid + (j << 8);
            xv[j] = (yv[j] - mean) * rstd * g1[d] + b1[d];
        }
        __syncthreads();
    }

    float accq[8] = {0, 0, 0, 0, 0, 0, 0, 0};
#pragma unroll
    for (int j = 0; j < 4; j++) {
        int d = tid + (j << 8);
#pragma unroll
        for (int qq = 0; qq < 8; qq++)
            accq[qq] = fmaf(xv[j], Win[qq * Dm + d], accq[qq]);
    }
#pragma unroll
    for (int qq = 0; qq < 8; qq++) {
        float vsum = accq[qq];
#pragma unroll
        for (int off = 16; off; off >>= 1)
            vsum += __shfl_xor_sync(0xffffffffu, vsum, off);
        if (lane == 0) redw[wid * 8 + qq] = vsum;
    }
    __syncthreads();
    if (tid < 8) {
        float s = b_in[tid];
#pragma unroll
        for (int w = 0; w < 8; w++) s += redw[w * 8 + tid];
        angs[tid] = s * 0.5f;
    }
    st[0][tid] = make_float2(tid == 0 ? 1.f : 0.f, 0.f);
    __syncthreads();

    int curb = 0;
#pragma unroll
    for (int k = 0; k < 4; k++) {
        int m1 = 1 << (7 - 2 * k);
        int m2 = m1 >> 1;
        float s1, c1, s2, c2;
        __sincosf(angs[2 * k], &s1, &c1);
        __sincosf(angs[2 * k + 1], &s2, &c2);
        float cc = c1 * c2, cs = c1 * s2, sc = s1 * c2, ss = s1 * s2;
        float2 x0  = st[curb][tid];
        float2 x1  = st[curb][tid ^ m1];
        float2 x2  = st[curb][tid ^ m2];
        float2 x12 = st[curb][tid ^ (m1 | m2)];
        float nr = cc * x0.x + cs * x2.y + sc * x1.y - ss * x12.x;
        float ni = cc * x0.y - cs * x2.x - sc * x1.x - ss * x12.y;
        st[curb ^ 1][tid] = make_float2(nr, ni);
        curb ^= 1;
        __syncthreads();
    }
#pragma unroll
    for (int k = 0; k < 4; k++) {
        int m1 = 1 << (7 - 2 * k);
        int m2 = m1 >> 1;
        float s1, c1, s2, c2;
        __sincosf(ry[2 * k] * 0.5f, &s1, &c1);
        __sincosf(ry[2 * k + 1] * 0.5f, &s2, &c2);
        float sg1 = (tid & m1) ? s1 : -s1;
        float sg2 = (tid & m2) ? s2 : -s2;
        float cc = c1 * c2, a2 = c1 * sg2, a1 = sg1 * c2, a12 = sg1 * sg2;
        float2 x0  = st[curb][tid];
        float2 x1  = st[curb][tid ^ m1];
        float2 x2  = st[curb][tid ^ m2];
        float2 x12 = st[curb][tid ^ (m1 | m2)];
        float nr = cc * x0.x + a2 * x2.x + a1 * x1.x + a12 * x12.x;
        float ni = cc * x0.y + a2 * x2.y + a1 * x1.y + a12 * x12.y;
        st[curb ^ 1][tid] = make_float2(nr, ni);
        curb ^= 1;
        __syncthreads();
    }
    int src = tid;
#pragma unroll
    for (int c = 6; c >= 0; c--) {
        int cmask = 1 << (7 - c);
        int tmask = cmask >> 1;
        if (src & cmask) src ^= tmask;
    }
    float2 fa = st[curb][src];
    float p = fa.x * fa.x + fa.y * fa.y;

#pragma unroll
    for (int w = 0; w < 8; w++) {
        float vsum = ((tid >> (7 - w)) & 1) ? -p : p;
#pragma unroll
        for (int off = 16; off; off >>= 1)
            vsum += __shfl_xor_sync(0xffffffffu, vsum, off);
        if (lane == 0) redw[wid * 8 + w] = vsum;
    }
    __syncthreads();
    if (tid < 8) {
        float s = 0.f;
#pragma unroll
        for (int w = 0; w < 8; w++) s += redw[w * 8 + tid];
        ezs[tid] = s;
    }
    __syncthreads();
    float e[8];
#pragma unroll
    for (int qq = 0; qq < 8; qq++) e[qq] = ezs[qq];

    float y[4], sum = 0.f, sq = 0.f;
#pragma unroll
    for (int j = 0; j < 4; j++) {
        int d = tid + (j << 8);
        const float4* wrow = reinterpret_cast<const float4*>(Wout + (size_t)d * 8);
        float4 w0 = wrow[0], w1 = wrow[1];
        float acc = b_out[d];
        acc = fmaf(e[0], w0.x, acc); acc = fmaf(e[1], w0.y, acc);
        acc = fmaf(e[2], w0.z, acc); acc = fmaf(e[3], w0.w, acc);
        acc = fmaf(e[4], w1.x, acc); acc = fmaf(e[5], w1.y, acc);
        acc = fmaf(e[6], w1.z, acc); acc = fmaf(e[7], w1.w, acc);
        acc = fmaxf(acc, 0.f);
        float yv = xv[j] + acc;
        y[j] = yv; sum += yv; sq = fmaf(yv, yv, sq);
    }
    __syncthreads();
#pragma unroll
    for (int off = 16; off; off >>= 1) {
        sum += __shfl_xor_sync(0xffffffffu, sum, off);
        sq  += __shfl_xor_sync(0xffffffffu, sq, off);
    }
    if (lane == 0) { redw[wid] = sum; redw[8 + wid] = sq; }
    __syncthreads();
    float tsum = 0.f, tsq = 0.f;
#pragma unroll
    for (int w = 0; w < 8; w++) { tsum += redw[w]; tsq += redw[8 + w]; }
    float mean = tsum * (1.f / 1024.f);
    float var  = tsq * (1.f / 1024.f) - mean * mean;
    float rstd = rsqrtf(var + EPSf);
#pragma unroll
    for (int j = 0; j < 4; j++) {
        int d = tid + (j << 8);
        out[(size_t)row * Dm + d] = (y[j] - mean) * rstd * g2[d] + b2[d];
    }
}

// ---------------- launch ----------------
extern "C" void kernel_launch(void* const* d_in, const int* in_sizes, int n_in,
                              void* d_out, int out_size)
{
    const float* x     = (const float*)d_in[0];
    const float* Wq    = (const float*)d_in[1];
    const float* Wk    = (const float*)d_in[2];
    const float* Wv    = (const float*)d_in[3];
    const float* Wo    = (const float*)d_in[4];
    const float* g1    = (const float*)d_in[5];
    const float* b1    = (const float*)d_in[6];
    const float* g2    = (const float*)d_in[7];
    const float* b2    = (const float*)d_in[8];
    const float* Win   = (const float*)d_in[9];
    const float* b_in  = (const float*)d_in[10];
    const float* Wout  = (const float*)d_in[11];
    const float* b_out = (const float*)d_in[12];
    const float* ry    = (const float*)d_in[13];
    float* out = (float*)d_out;

    uint32_t *xp, *qp, *kp, *vt, *op;
    float *v, *proj;
    cudaGetSymbolAddress((void**)&xp,   g_xp);
    cudaGetSymbolAddress((void**)&qp,   g_qp);
    cudaGetSymbolAddress((void**)&kp,   g_kp);
    cudaGetSymbolAddress((void**)&v,    g_v);
    cudaGetSymbolAddress((void**)&vt,   g_vt);
    cudaGetSymbolAddress((void**)&op,   g_op);
    cudaGetSymbolAddress((void**)&proj, g_proj);

    cudaFuncSetAttribute(gemm_qkv,  cudaFuncAttributeMaxDynamicSharedMemorySize, GPSMEM);
    cudaFuncSetAttribute(gemm_wo,   cudaFuncAttributeMaxDynamicSharedMemorySize, GPSMEM);
    cudaFuncSetAttribute(flash_mma, cudaFuncAttributeMaxDynamicSharedMemorySize, FA_SMEM);

    pack_x<<<2048, 256>>>((const float4*)x, (uint4*)xp);
    gemm_qkv<<<dim3(Dm / BN, Mtot / BM, 3), 256, GPSMEM>>>(xp, Wq, Wk, Wv, qp, kp, v);
    vtrans<<<dim3(Sq / 64, Hh, Bsz), 256>>>(v, vt);
    flash_mma<<<dim3(Sq / 256, Hh, Bsz), 256, FA_SMEM>>>(qp, kp, vt, op);
    gemm_wo<<<dim3(Dm / BN, Mtot / BM), 256, GPSMEM>>>(op, Wo, proj);
    ln_quantum<<<Mtot, 256>>>(x, proj, g1, b1, Win, b_in, Wout, b_out, ry, g2, b2, out);
}

// round 13
// speedup vs baseline: 2.3073x; 1.0947x over previous
#include <cuda_runtime.h>
#include <math.h>
#include <cstdint>

#define Bsz   2
#define Sq    2048
#define Dm    1024
#define Hh    16
#define Mtot  4096
#define DIMq  256
#define EPSf  1e-5f
#define LOG2E 1.44269504088896f

// ---------------- scratch ----------------
__device__ uint32_t g_xp[Mtot * 512];   // packed x
__device__ uint32_t g_wp[4 * 1024 * 512]; // packed Wq|Wk|Wv|Wo
__device__ uint32_t g_qp[Mtot * 512];   // packed Q (pre-scaled)
__device__ uint32_t g_kp[Mtot * 512];   // packed K
__device__ float    g_v [Mtot * Dm];    // V fp32
__device__ uint32_t g_vt[Mtot * 512];   // V transposed+packed
__device__ uint32_t g_op[Mtot * 512];   // packed attention output
__device__ float    g_proj[Mtot * Dm];

// ======================= helpers =======================
__device__ __forceinline__ uint32_t smem_to_u32(const void* p) {
    uint32_t a;
    asm("{ .reg .u64 t; cvta.to.shared.u64 t, %1; cvt.u32.u64 %0, t; }" : "=r"(a) : "l"(p));
    return a;
}
__device__ __forceinline__ void cp16(uint32_t sm, const void* g) {
    asm volatile("cp.async.cg.shared.global [%0], [%1], 16;" :: "r"(sm), "l"(g));
}
__device__ __forceinline__ void cp_commit() {
    asm volatile("cp.async.commit_group;");
}
template <int N>
__device__ __forceinline__ void cp_wait() {
    asm volatile("cp.async.wait_group %0;" :: "n"(N));
}
__device__ __forceinline__ uint32_t f2bf2(float lo, float hi) {
    uint32_t r;
    asm("cvt.rn.bf16x2.f32 %0, %1, %2;" : "=r"(r) : "f"(hi), "f"(lo));
    return r;
}
__device__ __forceinline__ void mma_bf16(float c[4], const uint32_t a[4], const uint32_t b[2]) {
    asm volatile(
        "mma.sync.aligned.m16n8k16.row.col.f32.bf16.bf16.f32 "
        "{%0,%1,%2,%3}, {%4,%5,%6,%7}, {%8,%9}, {%0,%1,%2,%3};"
        : "+f"(c[0]), "+f"(c[1]), "+f"(c[2]), "+f"(c[3])
        : "r"(a[0]), "r"(a[1]), "r"(a[2]), "r"(a[3]), "r"(b[0]), "r"(b[1]));
}

// ================= pack x -> bf16x2 =================
__global__ __launch_bounds__(256) void pack_x(const float4* __restrict__ x4,
                                              uint4* __restrict__ xp4)
{
    int idx = blockIdx.x * 256 + threadIdx.x;
    float4 a = x4[idx * 2];
    float4 b = x4[idx * 2 + 1];
    uint4 w;
    w.x = f2bf2(a.x, a.y); w.y = f2bf2(a.z, a.w);
    w.z = f2bf2(b.x, b.y); w.w = f2bf2(b.z, b.w);
    xp4[idx] = w;
}

// ================= pack 4 weights -> bf16x2 =================
__global__ __launch_bounds__(256) void pack_w(const float* __restrict__ W0,
                                              const float* __restrict__ W1,
                                              const float* __restrict__ W2,
                                              const float* __restrict__ W3,
                                              uint32_t* __restrict__ wp)
{
    const int z = blockIdx.y;
    const float* W = (z == 0) ? W0 : (z == 1) ? W1 : (z == 2) ? W2 : W3;
    const float4* w4 = reinterpret_cast<const float4*>(W);
    uint4* o4 = reinterpret_cast<uint4*>(wp + (size_t)z * 1024 * 512);
    int idx = blockIdx.x * 256 + threadIdx.x;    // 131072 uint4 per weight
    float4 a = w4[idx * 2];
    float4 b = w4[idx * 2 + 1];
    uint4 w;
    w.x = f2bf2(a.x, a.y); w.y = f2bf2(a.z, a.w);
    w.z = f2bf2(b.x, b.y); w.w = f2bf2(b.z, b.w);
    o4[idx] = w;
}

// ======= V transpose+pack =======
__global__ __launch_bounds__(256) void vtrans(const float* __restrict__ v,
                                              uint32_t* __restrict__ vt)
{
    __shared__ float sm[64 * 65 + 16];
    const int tid = threadIdx.x;
    const int kt = blockIdx.x, h = blockIdx.y, b = blockIdx.z;
    const float* vg = v + (size_t)(b * Sq + kt * 64) * 1024 + h * 64;

#pragma unroll
    for (int i = 0; i < 4; i++) {
        int e = tid + (i << 8);
        int r = e >> 4, c4 = (e & 15) << 2;
        float4 vv = *reinterpret_cast<const float4*>(vg + (size_t)r * 1024 + c4);
        sm[(c4 + 0) * 65 + r] = vv.x;
        sm[(c4 + 1) * 65 + r] = vv.y;
        sm[(c4 + 2) * 65 + r] = vv.z;
        sm[(c4 + 3) * 65 + r] = vv.w;
    }
    __syncthreads();

    uint32_t* og = vt + ((size_t)(b * Hh + h) * 64) * 1024 + kt * 32;
#pragma unroll
    for (int i = 0; i < 8; i++) {
        int idx = tid + (i << 8);
        int d = idx >> 5, kp = idx & 31;
        og[(size_t)d * 1024 + kp] = f2bf2(sm[d * 65 + 2 * kp], sm[d * 65 + 2 * kp + 1]);
    }
}

// ============ bf16 GEMM, BOTH operands packed ============
#define BM 128
#define BN 256
#define PAW 20
#define PBW 20
#define PA_STAGE_B (BM * PAW * 4)            // 10240
#define PB_STAGE_B (BN * PBW * 4)            // 20480
#define GPSMEM (3 * (PA_STAGE_B + PB_STAGE_B))  // 92160
#define NKT (Dm / 32)

__device__ __forceinline__ void gemm_pp(const uint32_t* __restrict__ Ap,
                                        const uint32_t* __restrict__ Wp,
                                        float* __restrict__ Cf,
                                        uint32_t* __restrict__ Cp,
                                        int outmode, float scale,
                                        char* gsm)
{
    const uint32_t usm = smem_to_u32(gsm);
    const uint32_t usmA = usm;
    const uint32_t usmB = usm + 3 * PA_STAGE_B;

    const int tid  = threadIdx.x;
    const int wid  = tid >> 5;
    const int lane = tid & 31;
    const int grp  = lane >> 2;
    const int tig  = lane & 3;
    const int wm   = wid >> 2;
    const int wn   = wid & 3;

    const int aRow0 = blockIdx.y * BM;
    const int bRow0 = blockIdx.x * BN;

    int aSm[2], aGm[2], bSm[4], bGm[4];
#pragma unroll
    for (int i = 0; i < 2; i++) {
        int e = tid + (i << 8);
        int r = e >> 2, c4 = (e & 3) << 2;
        aSm[i] = (r * PAW + c4) * 4;
        aGm[i] = r * 512 + c4;
    }
#pragma unroll
    for (int i = 0; i < 4; i++) {
        int e = tid + (i << 8);
        int r = e >> 2, c4 = (e & 3) << 2;
        bSm[i] = (r * PBW + c4) * 4;
        bGm[i] = r * 512 + c4;
    }
    const uint32_t* gA = Ap + (size_t)aRow0 * 512;
    const uint32_t* gB = Wp + (size_t)bRow0 * 512;

    float acc[4][8][4];
#pragma unroll
    for (int im = 0; im < 4; im++)
#pragma unroll
        for (int jn = 0; jn < 8; jn++)
#pragma unroll
            for (int t = 0; t < 4; t++) acc[im][jn][t] = 0.f;

#pragma unroll
    for (int p = 0; p < 2; p++) {
        uint32_t sa = usmA + p * PA_STAGE_B;
        uint32_t sb = usmB + p * PB_STAGE_B;
        const uint32_t* ka = gA + p * 16;
        const uint32_t* kb = gB + p * 16;
#pragma unroll
        for (int i = 0; i < 2; i++) cp16(sa + aSm[i], ka + aGm[i]);
#pragma unroll
        for (int i = 0; i < 4; i++) cp16(sb + bSm[i], kb + bGm[i]);
        cp_commit();
    }

    for (int kt = 0; kt < NKT; kt++) {
        cp_wait<1>();
        __syncthreads();

        if (kt + 2 < NKT) {
            int s = (kt + 2) % 3;
            uint32_t sa = usmA + s * PA_STAGE_B;
            uint32_t sb = usmB + s * PB_STAGE_B;
            const uint32_t* ka = gA + (kt + 2) * 16;
            const uint32_t* kb = gB + (kt + 2) * 16;
#pragma unroll
            for (int i = 0; i < 2; i++) cp16(sa + aSm[i], ka + aGm[i]);
#pragma unroll
            for (int i = 0; i < 4; i++) cp16(sb + bSm[i], kb + bGm[i]);
        }
        cp_commit();

        const uint32_t* Asp = (const uint32_t*)(gsm + (kt % 3) * PA_STAGE_B);
        const uint32_t* Bsp = (const uint32_t*)(gsm + 3 * PA_STAGE_B + (kt % 3) * PB_STAGE_B);

#pragma unroll
        for (int k16 = 0; k16 < 2; k16++) {
            const int pi = k16 * 8 + tig;
            uint32_t afr[4][4], bfr[8][2];
#pragma unroll
            for (int im = 0; im < 4; im++) {
                int row = wm * 64 + im * 16 + grp;
                afr[im][0] = Asp[row * PAW + pi];
                afr[im][1] = Asp[(row + 8) * PAW + pi];
                afr[im][2] = Asp[row * PAW + pi + 4];
                afr[im][3] = Asp[(row + 8) * PAW + pi + 4];
            }
#pragma unroll
            for (int jn = 0; jn < 8; jn++) {
                int brow = wn * 64 + jn * 8 + grp;
                bfr[jn][0] = Bsp[brow * PBW + pi];
                bfr[jn][1] = Bsp[brow * PBW + pi + 4];
            }
#pragma unroll
            for (int im = 0; im < 4; im++)
#pragma unroll
                for (int jn = 0; jn < 8; jn++)
                    mma_bf16(acc[im][jn], afr[im], bfr[jn]);
        }
    }

    const int rowBase = aRow0 + wm * 64;
    const int colBase = bRow0 + wn * 64;
    if (outmode == 0) {
#pragma unroll
        for (int im = 0; im < 4; im++) {
            int r0 = rowBase + im * 16 + grp;
#pragma unroll
            for (int jn = 0; jn < 8; jn++) {
                int col = colBase + jn * 8 + 2 * tig;
                float2 v01 = make_float2(acc[im][jn][0], acc[im][jn][1]);
                float2 v23 = make_float2(acc[im][jn][2], acc[im][jn][3]);
                *reinterpret_cast<float2*>(Cf + (size_t)r0 * Dm + col) = v01;
                *reinterpret_cast<float2*>(Cf + (size_t)(r0 + 8) * Dm + col) = v23;
            }
        }
    } else {
#pragma unroll
        for (int im = 0; im < 4; im++) {
            int r0 = rowBase + im * 16 + grp;
#pragma unroll
            for (int jn = 0; jn < 8; jn++) {
                int col = colBase + jn * 8 + 2 * tig;
                Cp[(size_t)r0 * 512 + (col >> 1)] =
                    f2bf2(acc[im][jn][0] * scale, acc[im][jn][1] * scale);
                Cp[(size_t)(r0 + 8) * 512 + (col >> 1)] =
                    f2bf2(acc[im][jn][2] * scale, acc[im][jn][3] * scale);
            }
        }
    }
}

__global__ __launch_bounds__(256, 1) void gemm_qkv(const uint32_t* __restrict__ Ap,
                                                   const uint32_t* __restrict__ Wp,
                                                   uint32_t* __restrict__ Qp,
                                                   uint32_t* __restrict__ Kp,
                                                   float* __restrict__ Vf)
{
    extern __shared__ __align__(16) char gsm[];
    const int z = blockIdx.z;
    if (z == 0)      gemm_pp(Ap, Wp,               nullptr, Qp, 1, 0.125f * LOG2E, gsm);
    else if (z == 1) gemm_pp(Ap, Wp + 1024 * 512,  nullptr, Kp, 1, 1.f, gsm);
    else             gemm_pp(Ap, Wp + 2 * 1024 * 512, Vf, nullptr, 0, 1.f, gsm);
}

__global__ __launch_bounds__(256, 1) void gemm_wo(const uint32_t* __restrict__ Ap,
                                                  const uint32_t* __restrict__ Wp,
                                                  float* __restrict__ C)
{
    extern __shared__ __align__(16) char gsm[];
    gemm_pp(Ap, Wp + 3 * 1024 * 512, C, nullptr, 0, 1.f, gsm);
}

// ============ Flash attention (R12-proven, all packed) ================
#define PPW   36
#define KPW   36
#define QP_OFF 0
#define PP_OFF (256 * PPW)
#define KP_OFF (2 * 256 * PPW)
#define KP_STRIDE (64 * KPW)
#define VP_OFF (KP_OFF + 3 * KP_STRIDE)
#define FA_SMEM ((VP_OFF + 3 * KP_STRIDE) * 4)
#define NKV (Sq / 64)

__global__ __launch_bounds__(256, 1) void flash_mma(const uint32_t* __restrict__ qpg,
                                                    const uint32_t* __restrict__ kpg,
                                                    const uint32_t* __restrict__ vtg_all,
                                                    uint32_t* __restrict__ op)
{
    extern __shared__ __align__(16) uint32_t fsu[];
    const uint32_t usm = smem_to_u32(fsu);
    uint32_t* qp = fsu + QP_OFF;
    uint32_t* pp = fsu + PP_OFF;
    const uint32_t* kp = fsu + KP_OFF;
    const uint32_t* vp = fsu + VP_OFF;

    const int tid  = threadIdx.x;
    const int wid  = tid >> 5;
    const int lane = tid & 31;
    const int grp  = lane >> 2;
    const int tig  = lane & 3;

    const int b  = blockIdx.z;
    const int h  = blockIdx.y;
    const int q0 = blockIdx.x << 8;

    const uint32_t* qg  = qpg + (size_t)(b * Sq + q0) * 512 + h * 32;
    const uint32_t* kg  = kpg + (size_t)(b * Sq) * 512 + h * 32;
    const uint32_t* vtg = vtg_all + ((size_t)(b * Hh + h) * 64) * 1024;

    {
#pragma unroll
        for (int i = 0; i < 2; i++) {
            int e = tid + (i << 8);
            int r = e >> 3, c4 = (e & 7) << 2;
            cp16(usm + (KP_OFF + r * KPW + c4) * 4, kg + (size_t)r * 512 + c4);
            cp16(usm + (VP_OFF + r * KPW + c4) * 4, vtg + (size_t)r * 1024 + c4);
        }
#pragma unroll
        for (int i = 0; i < 8; i++) {
            int e = tid + (i << 8);
            int r = e >> 3, c4 = (e & 7) << 2;
            cp16(usm + (QP_OFF + r * PPW + c4) * 4, qg + (size_t)r * 512 + c4);
        }
        cp_commit();
#pragma unroll
        for (int i = 0; i < 2; i++) {
            int e = tid + (i << 8);
            int r = e >> 3, c4 = (e & 7) << 2;
            cp16(usm + (KP_OFF + KP_STRIDE + r * KPW + c4) * 4, kg + (size_t)(64 + r) * 512 + c4);
            cp16(usm + (VP_OFF + KP_STRIDE + r * KPW + c4) * 4, vtg + (size_t)r * 1024 + 32 + c4);
        }
        cp_commit();
    }

    const int lr0 = wid * 32 + grp;
    const int lr1 = lr0 + 16;

    float m00 = -1e30f, m01 = -1e30f, m10 = -1e30f, m11 = -1e30f;
    float l00 = 0.f, l01 = 0.f, l10 = 0.f, l11 = 0.f;
    float oac0[8][4], oac1[8][4];
#pragma unroll
    for (int jd = 0; jd < 8; jd++)
#pragma unroll
        for (int t = 0; t < 4; t++) { oac0[jd][t] = 0.f; oac1[jd][t] = 0.f; }

    for (int it = 0; it < NKV; it++) {
        cp_wait<1>();
        __syncthreads();

        if (it + 2 < NKV) {
            int s = (it + 2) % 3;
            int kv0 = (it + 2) << 6;
            int kv32 = (it + 2) << 5;
#pragma unroll
            for (int i = 0; i < 2; i++) {
                int e = tid + (i << 8);
                int r = e >> 3, c4 = (e & 7) << 2;
                cp16(usm + (KP_OFF + s * KP_STRIDE + r * KPW + c4) * 4,
                     kg + (size_t)(kv0 + r) * 512 + c4);
                cp16(usm + (VP_OFF + s * KP_STRIDE + r * KPW + c4) * 4,
                     vtg + (size_t)r * 1024 + kv32 + c4);
            }
        }
        cp_commit();

        const uint32_t* Kb = kp + (it % 3) * KP_STRIDE;
        const uint32_t* Vb = vp + (it % 3) * KP_STRIDE;

        float sac0[8][4], sac1[8][4];
#pragma unroll
        for (int jn = 0; jn < 8; jn++)
#pragma unroll
            for (int t = 0; t < 4; t++) { sac0[jn][t] = 0.f; sac1[jn][t] = 0.f; }
#pragma unroll
        for (int k16 = 0; k16 < 4; k16++) {
            const int pi = k16 * 8 + tig;
            uint32_t bfr[8][2];
#pragma unroll
            for (int jn = 0; jn < 8; jn++) {
                int krow = jn * 8 + grp;
                bfr[jn][0] = Kb[krow * KPW + pi];
                bfr[jn][1] = Kb[krow * KPW + pi + 4];
            }
            uint32_t af0[4], af1[4];
            af0[0] = qp[lr0 * PPW + pi];       af0[1] = qp[(lr0 + 8) * PPW + pi];
            af0[2] = qp[lr0 * PPW + pi + 4];   af0[3] = qp[(lr0 + 8) * PPW + pi + 4];
            af1[0] = qp[lr1 * PPW + pi];       af1[1] = qp[(lr1 + 8) * PPW + pi];
            af1[2] = qp[lr1 * PPW + pi + 4];   af1[3] = qp[(lr1 + 8) * PPW + pi + 4];
#pragma unroll
            for (int jn = 0; jn < 8; jn++) {
                mma_bf16(sac0[jn], af0, bfr[jn]);
                mma_bf16(sac1[jn], af1, bfr[jn]);
            }
        }

        {
            float mx0 = -1e30f, mx1 = -1e30f;
#pragma unroll
            for (int jn = 0; jn < 8; jn++) {
                mx0 = fmaxf(mx0, fmaxf(sac0[jn][0], sac0[jn][1]));
                mx1 = fmaxf(mx1, fmaxf(sac0[jn][2], sac0[jn][3]));
            }
            mx0 = fmaxf(mx0, __shfl_xor_sync(0xffffffffu, mx0, 1));
            mx0 = fmaxf(mx0, __shfl_xor_sync(0xffffffffu, mx0, 2));
            mx1 = fmaxf(mx1, __shfl_xor_sync(0xffffffffu, mx1, 1));
            mx1 = fmaxf(mx1, __shfl_xor_sync(0xffffffffu, mx1, 2));
            float mn0 = fmaxf(m00, mx0), mn1 = fmaxf(m01, mx1);
            float al0 = exp2f(m00 - mn0), al1 = exp2f(m01 - mn1);
            float sum0 = 0.f, sum1 = 0.f;
#pragma unroll
            for (int jn = 0; jn < 8; jn++) {
                float p00 = exp2f(sac0[jn][0] - mn0);
                float p01 = exp2f(sac0[jn][1] - mn0);
                float p10 = exp2f(sac0[jn][2] - mn1);
                float p11 = exp2f(sac0[jn][3] - mn1);
                int ci = jn * 4 + tig;
                pp[lr0 * PPW + ci]       = f2bf2(p00, p01);
                pp[(lr0 + 8) * PPW + ci] = f2bf2(p10, p11);
                sum0 += p00 + p01;  sum1 += p10 + p11;
            }
            sum0 += __shfl_xor_sync(0xffffffffu, sum0, 1);
            sum0 += __shfl_xor_sync(0xffffffffu, sum0, 2);
            sum1 += __shfl_xor_sync(0xffffffffu, sum1, 1);
            sum1 += __shfl_xor_sync(0xffffffffu, sum1, 2);
            l00 = l00 * al0 + sum0;  m00 = mn0;
            l01 = l01 * al1 + sum1;  m01 = mn1;
#pragma unroll
            for (int jd = 0; jd < 8; jd++) {
                oac0[jd][0] *= al0; oac0[jd][1] *= al0;
                oac0[jd][2] *= al1; oac0[jd][3] *= al1;
            }
        }
        {
            float mx0 = -1e30f, mx1 = -1e30f;
#pragma unroll
            for (int jn = 0; jn < 8; jn++) {
                mx0 = fmaxf(mx0, fmaxf(sac1[jn][0], sac1[jn][1]));
                mx1 = fmaxf(mx1, fmaxf(sac1[jn][2], sac1[jn][3]));
            }
            mx0 = fmaxf(mx0, __shfl_xor_sync(0xffffffffu, mx0, 1));
            mx0 = fmaxf(mx0, __shfl_xor_sync(0xffffffffu, mx0, 2));
            mx1 = fmaxf(mx1, __shfl_xor_sync(0xffffffffu, mx1, 1));
            mx1 = fmaxf(mx1, __shfl_xor_sync(0xffffffffu, mx1, 2));
            float mn0 = fmaxf(m10, mx0), mn1 = fmaxf(m11, mx1);
            float al0 = exp2f(m10 - mn0), al1 = exp2f(m11 - mn1);
            float sum0 = 0.f, sum1 = 0.f;
#pragma unroll
            for (int jn = 0; jn < 8; jn++) {
                float p00 = exp2f(sac1[jn][0] - mn0);
                float p01 = exp2f(sac1[jn][1] - mn0);
                float p10 = exp2f(sac1[jn][2] - mn1);
                float p11 = exp2f(sac1[jn][3] - mn1);
                int ci = jn * 4 + tig;
                pp[lr1 * PPW + ci]       = f2bf2(p00, p01);
                pp[(lr1 + 8) * PPW + ci] = f2bf2(p10, p11);
                sum0 += p00 + p01;  sum1 += p10 + p11;
            }
            sum0 += __shfl_xor_sync(0xffffffffu, sum0, 1);
            sum0 += __shfl_xor_sync(0xffffffffu, sum0, 2);
            sum1 += __shfl_xor_sync(0xffffffffu, sum1, 1);
            sum1 += __shfl_xor_sync(0xffffffffu, sum1, 2);
            l10 = l10 * al0 + sum0;  m10 = mn0;
            l11 = l11 * al1 + sum1;  m11 = mn1;
#pragma unroll
            for (int jd = 0; jd < 8; jd++) {
                oac1[jd][0] *= al0; oac1[jd][1] *= al0;
                oac1[jd][2] *= al1; oac1[jd][3] *= al1;
            }
        }
        __syncwarp();

#pragma unroll
        for (int k16 = 0; k16 < 4; k16++) {
            const int pi = k16 * 8 + tig;
            uint32_t bfr[8][2];
#pragma unroll
            for (int jd = 0; jd < 8; jd++) {
                int dcol = jd * 8 + grp;
                bfr[jd][0] = Vb[dcol * KPW + pi];
                bfr[jd][1] = Vb[dcol * KPW + pi + 4];
            }
            uint32_t af0[4], af1[4];
            af0[0] = pp[lr0 * PPW + pi];       af0[1] = pp[(lr0 + 8) * PPW + pi];
            af0[2] = pp[lr0 * PPW + pi + 4];   af0[3] = pp[(lr0 + 8) * PPW + pi + 4];
            af1[0] = pp[lr1 * PPW + pi];       af1[1] = pp[(lr1 + 8) * PPW + pi];
            af1[2] = pp[lr1 * PPW + pi + 4];   af1[3] = pp[(lr1 + 8) * PPW + pi + 4];
#pragma unroll
            for (int jd = 0; jd < 8; jd++) {
                mma_bf16(oac0[jd], af0, bfr[jd]);
                mma_bf16(oac1[jd], af1, bfr[jd]);
            }
        }
    }

    {
        float inv0 = 1.f / l00, inv1 = 1.f / l01;
        uint32_t* og  = op + (size_t)(b * Sq + q0 + lr0) * 512 + h * 32;
        uint32_t* og8 = og + (size_t)8 * 512;
#pragma unroll
        for (int jd = 0; jd < 8; jd++) {
            og[jd * 4 + tig]  = f2bf2(oac0[jd][0] * inv0, oac0[jd][1] * inv0);
            og8[jd * 4 + tig] = f2bf2(oac0[jd][2] * inv1, oac0[jd][3] * inv1);
        }
    }
    {
        float inv0 = 1.f / l10, inv1 = 1.f / l11;
        uint32_t* og  = op + (size_t)(b * Sq + q0 + lr1) * 512 + h * 32;
        uint32_t* og8 = og + (size_t)8 * 512;
#pragma unroll
        for (int jd = 0; jd < 8; jd++) {
            og[jd * 4 + tig]  = f2bf2(oac1[jd][0] * inv0, oac1[jd][1] * inv0);
            og8[jd * 4 + tig] = f2bf2(oac1[jd][2] * inv1, oac1[jd][3] * inv1);
        }
    }
}

// ========= fused LN1 + quantum FFN + LN2 (R11-proven) =========
__global__ __launch_bounds__(256) void ln_quantum(const float* __restrict__ x,
                                                  const float* __restrict__ proj,
                                                  const float* __restrict__ g1,
                                                  const float* __restrict__ b1,
                                                  const float* __restrict__ Win,
                                                  const float* __restrict__ b_in,
                                                  const float* __restrict__ Wout,
                                                  const float* __restrict__ b_out,
                                                  const float* __restrict__ ry,
                                                  const float* __restrict__ g2,
                                                  const float* __restrict__ b2,
                                                  float* __restrict__ out)
{
    const int row = blockIdx.x;
    const int tid = threadIdx.x;
    const int lane = tid & 31, wid = tid >> 5;
    const float* px = x + (size_t)row * Dm;
    const float* pprj = proj + (size_t)row * Dm;

    __shared__ float redw[64];
    __shared__ float angs[8];
    __shared__ float ezs[8];
    __shared__ float2 st[2][DIMq];

    float xv[4];
    {
        float yv[4], sum = 0.f, sq = 0.f;
#pragma unroll
        for (int j = 0; j < 4; j++) {
            int d = tid + (j << 8);
            float t = px[d] + pprj[d];
            yv[j] = t; sum += t; sq = fmaf(t, t, sq);
        }
#pragma unroll
        for (int off = 16; off; off >>= 1) {
            sum += __shfl_xor_sync(0xffffffffu, sum, off);
            sq  += __shfl_xor_sync(0xffffffffu, sq, off);
        }
        if (lane == 0) { redw[wid] = sum; redw[8 + wid] = sq; }
        __syncthreads();
        float tsum = 0.f, tsq = 0.f;
#pragma unroll
        for (int w = 0; w < 8; w++) { tsum += redw[w]; tsq += redw[8 + w]; }
        float mean = tsum * (1.f / 1024.f);
        float var  = tsq * (1.f / 1024.f) - mean * mean;
        float rstd = rsqrtf(var + EPSf);
#pragma unroll
        for (int j = 0; j < 4; j++) {
            int d = tid + (j << 8);
            xv[j] = (yv[j] - mean) * rstd * g1[d] + b1[d];
        }
        __syncthreads();
    }

    float accq[8] = {0, 0, 0, 0, 0, 0, 0, 0};
#pragma unroll
    for (int j = 0; j < 4; j++) {
        int d = tid + (j << 8);
#pragma unroll
        for (int qq = 0; qq < 8; qq++)
            accq[qq] = fmaf(xv[j], Win[qq * Dm + d], accq[qq]);
    }
#pragma unroll
    for (int qq = 0; qq < 8; qq++) {
        float vsum = accq[qq];
#pragma unroll
        for (int off = 16; off; off >>= 1)
            vsum += __shfl_xor_sync(0xffffffffu, vsum, off);
        if (lane == 0) redw[wid * 8 + qq] = vsum;
    }
    __syncthreads();
    if (tid < 8) {
        float s = b_in[tid];
#pragma unroll
        for (int w = 0; w < 8; w++) s += redw[w * 8 + tid];
        angs[tid] = s * 0.5f;
    }
    st[0][tid] = make_float2(tid == 0 ? 1.f : 0.f, 0.f);
    __syncthreads();

    int curb = 0;
#pragma unroll
    for (int k = 0; k < 4; k++) {
        int m1 = 1 << (7 - 2 * k);
        int m2 = m1 >> 1;
        float s1, c1, s2, c2;
        __sincosf(angs[2 * k], &s1, &c1);
        __sincosf(angs[2 * k + 1], &s2, &c2);
        float cc = c1 * c2, cs = c1 * s2, sc = s1 * c2, ss = s1 * s2;
        float2 x0  = st[curb][tid];
        float2 x1  = st[curb][tid ^ m1];
        float2 x2  = st[curb][tid ^ m2];
        float2 x12 = st[curb][tid ^ (m1 | m2)];
        float nr = cc * x0.x + cs * x2.y + sc * x1.y - ss * x12.x;
        float ni = cc * x0.y - cs * x2.x - sc * x1.x - ss * x12.y;
        st[curb ^ 1][tid] = make_float2(nr, ni);
        curb ^= 1;
        __syncthreads();
    }
#pragma unroll
    for (int k = 0; k < 4; k++) {
        int m1 = 1 << (7 - 2 * k);
        int m2 = m1 >> 1;
        float s1, c1, s2, c2;
        __sincosf(ry[2 * k] * 0.5f, &s1, &c1);
        __sincosf(ry[2 * k + 1] * 0.5f, &s2, &c2);
        float sg1 = (tid & m1) ? s1 : -s1;
        float sg2 = (tid & m2) ? s2 : -s2;
        float cc = c1 * c2, a2 = c1 * sg2, a1 = sg1 * c2, a12 = sg1 * sg2;
        float2 x0  = st[curb][tid];
        float2 x1  = st[curb][tid ^ m1];
        float2 x2  = st[curb][tid ^ m2];
        float2 x12 = st[curb][tid ^ (m1 | m2)];
        float nr = cc * x0.x + a2 * x2.x + a1 * x1.x + a12 * x12.x;
        float ni = cc * x0.y + a2 * x2.y + a1 * x1.y + a12 * x12.y;
        st[curb ^ 1][tid] = make_float2(nr, ni);
        curb ^= 1;
        __syncthreads();
    }
    int src = tid;
#pragma unroll
    for (int c = 6; c >= 0; c--) {
        int cmask = 1 << (7 - c);
        int tmask = cmask >> 1;
        if (src & cmask) src ^= tmask;
    }
    float2 fa = st[curb][src];
    float p = fa.x * fa.x + fa.y * fa.y;

#pragma unroll
    for (int w = 0; w < 8; w++) {
        float vsum = ((tid >> (7 - w)) & 1) ? -p : p;
#pragma unroll
        for (int off = 16; off; off >>= 1)
            vsum += __shfl_xor_sync(0xffffffffu, vsum, off);
        if (lane == 0) redw[wid * 8 + w] = vsum;
    }
    __syncthreads();
    if (tid < 8) {
        float s = 0.f;
#pragma unroll
        for (int w = 0; w < 8; w++) s += redw[w * 8 + tid];
        ezs[tid] = s;
    }
    __syncthreads();
    float e[8];
#pragma unroll
    for (int qq = 0; qq < 8; qq++) e[qq] = ezs[qq];

    float y[4], sum = 0.f, sq = 0.f;
#pragma unroll
    for (int j = 0; j < 4; j++) {
        int d = tid + (j << 8);
        const float4* wrow = reinterpret_cast<const float4*>(Wout + (size_t)d * 8);
        float4 w0 = wrow[0], w1 = wrow[1];
        float acc = b_out[d];
        acc = fmaf(e[0], w0.x, acc); acc = fmaf(e[1], w0.y, acc);
        acc = fmaf(e[2], w0.z, acc); acc = fmaf(e[3], w0.w, acc);
        acc = fmaf(e[4], w1.x, acc); acc = fmaf(e[5], w1.y, acc);
        acc = fmaf(e[6], w1.z, acc); acc = fmaf(e[7], w1.w, acc);
        acc = fmaxf(acc, 0.f);
        float yv = xv[j] + acc;
        y[j] = yv; sum += yv; sq = fmaf(yv, yv, sq);
    }
    __syncthreads();
#pragma unroll
    for (int off = 16; off; off >>= 1) {
        sum += __shfl_xor_sync(0xffffffffu, sum, off);
        sq  += __shfl_xor_sync(0xffffffffu, sq, off);
    }
    if (lane == 0) { redw[wid] = sum; redw[8 + wid] = sq; }
    __syncthreads();
    float tsum = 0.f, tsq = 0.f;
#pragma unroll
    for (int w = 0; w < 8; w++) { tsum += redw[w]; tsq += redw[8 + w]; }
    float mean = tsum * (1.f / 1024.f);
    float var  = tsq * (1.f / 1024.f) - mean * mean;
    float rstd = rsqrtf(var + EPSf);
#pragma unroll
    for (int j = 0; j < 4; j++) {
        int d = tid + (j << 8);
        out[(size_t)row * Dm + d] = (y[j] - mean) * rstd * g2[d] + b2[d];
    }
}

// ---------------- launch ----------------
extern "C" void kernel_launch(void* const* d_in, const int* in_sizes, int n_in,
                              void* d_out, int out_size)
{
    const float* x     = (const float*)d_in[0];
    const float* Wq    = (const float*)d_in[1];
    const float* Wk    = (const float*)d_in[2];
    const float* Wv    = (const float*)d_in[3];
    const float* Wo    = (const float*)d_in[4];
    const float* g1    = (const float*)d_in[5];
    const float* b1    = (const float*)d_in[6];
    const float* g2    = (const float*)d_in[7];
    const float* b2    = (const float*)d_in[8];
    const float* Win   = (const float*)d_in[9];
    const float* b_in  = (const float*)d_in[10];
    const float* Wout  = (const float*)d_in[11];
    const float* b_out = (const float*)d_in[12];
    const float* ry    = (const float*)d_in[13];
    float* out = (float*)d_out;

    uint32_t *xp, *wp, *qp, *kp, *vt, *op;
    float *v, *proj;
    cudaGetSymbolAddress((void**)&xp,   g_xp);
    cudaGetSymbolAddress((void**)&wp,   g_wp);
    cudaGetSymbolAddress((void**)&qp,   g_qp);
    cudaGetSymbolAddress((void**)&kp,   g_kp);
    cudaGetSymbolAddress((void**)&v,    g_v);
    cudaGetSymbolAddress((void**)&vt,   g_vt);
    cudaGetSymbolAddress((void**)&op,   g_op);
    cudaGetSymbolAddress((void**)&proj, g_proj);

    cudaFuncSetAttribute(gemm_qkv,  cudaFuncAttributeMaxDynamicSharedMemorySize, GPSMEM);
    cudaFuncSetAttribute(gemm_wo,   cudaFuncAttributeMaxDynamicSharedMemorySize, GPSMEM);
    cudaFuncSetAttribute(flash_mma, cudaFuncAttributeMaxDynamicSharedMemorySize, FA_SMEM);

    pack_x<<<2048, 256>>>((const float4*)x, (uint4*)xp);
    pack_w<<<dim3(512, 4), 256>>>(Wq, Wk, Wv, Wo, wp);
    gemm_qkv<<<dim3(Dm / BN, Mtot / BM, 3), 256, GPSMEM>>>(xp, wp, qp, kp, v);
    vtrans<<<dim3(Sq / 64, Hh, Bsz), 256>>>(v, vt);
    flash_mma<<<dim3(Sq / 256, Hh, Bsz), 256, FA_SMEM>>>(qp, kp, vt, op);
    gemm_wo<<<dim3(Dm / BN, Mtot / BM), 256, GPSMEM>>>(op, wp, proj);
    ln_quantum<<<Mtot, 256>>>(x, proj, g1, b1, Win, b_in, Wout, b_out, ry, g2, b2, out);
}